// round 3
// baseline (speedup 1.0000x reference)
#include <cuda_runtime.h>

#define NND 50000
#define NED 300000
#define HD 128
#define NL 6
#define KP 132
#define TIL 16

__device__ float g_h[NND*HD];
__device__ float g_hn[NND*HD];
__device__ float g_A[NND*HD];
__device__ float g_B[NND*HD];
__device__ float g_agg[NND*HD];
__device__ float g_u1[NND*HD];
__device__ float g_deg[NND];
__device__ float g_bias_emb[HD];
__device__ float g_bias_msg[NL*HD];
__device__ float g_bias_upd[NL*HD];
__device__ float g_stats[2*HD];
__device__ float g_hsum[HD];

typedef unsigned long long u64;

__device__ __forceinline__ void ffma2(u64 &d, u64 a, u64 b){
    asm("fma.rn.f32x2 %0, %1, %2, %0;" : "+l"(d) : "l"(a), "l"(b));
}
__device__ __forceinline__ float hadd2(u64 a){
    return __uint_as_float((unsigned)a) + __uint_as_float((unsigned)(a>>32));
}

__global__ void k_prep(const float* __restrict__ dom, const float* __restrict__ t,
                       const float* __restrict__ xg, const float* __restrict__ domn,
                       const float* __restrict__ tn,
                       const float* __restrict__ embW1, const float* __restrict__ embb1,
                       const float* __restrict__ msgW1, const float* __restrict__ msgb1,
                       const float* __restrict__ updW1, const float* __restrict__ updb1)
{
    __shared__ float gf[12];
    int j = threadIdx.x;
    if (j < 12){
        float val;
        if (j < 3) val = dom[j];
        else if (j == 3) val = t[0];
        else if (j < 8) val = xg[j-4];
        else if (j < 11) val = domn[j-8];
        else val = tn[0];
        gf[j] = val;
    }
    __syncthreads();
    float acc = embb1[j];
    #pragma unroll
    for (int g = 0; g < 12; g++) acc += gf[g]*embW1[(7+g)*HD + j];
    g_bias_emb[j] = acc;
    for (int l = 0; l < NL; l++){
        const float* W = msgW1 + (size_t)l*279*HD;
        float a = msgb1[l*HD + j];
        #pragma unroll
        for (int g = 0; g < 12; g++) a += gf[g]*W[(267+g)*HD + j];
        g_bias_msg[l*HD + j] = a;
        const float* U = updW1 + (size_t)l*268*HD;
        float b = updb1[l*HD + j];
        #pragma unroll
        for (int g = 0; g < 12; g++) b += gf[g]*U[(256+g)*HD + j];
        g_bias_upd[l*HD + j] = b;
    }
}

__global__ void k_zero0(){
    int i = blockIdx.x*blockDim.x + threadIdx.x;
    for (int idx = i; idx < NND; idx += gridDim.x*blockDim.x) g_deg[idx] = 0.f;
    if (i < HD) g_hsum[i] = 0.f;
}

__global__ void k_zeroagg(){
    int i = blockIdx.x*blockDim.x + threadIdx.x;
    for (int idx = i; idx < NND*HD; idx += gridDim.x*blockDim.x) g_agg[idx] = 0.f;
    if (i < 2*HD) g_stats[i] = 0.f;
}

__global__ void k_count(const int* __restrict__ ei){
    for (int e = blockIdx.x*blockDim.x + threadIdx.x; e < NED; e += gridDim.x*blockDim.x)
        atomicAdd(&g_deg[ei[NED + e]], 1.0f);
}

__global__ void __launch_bounds__(128) k_embed(const float* __restrict__ embW1,
                                               const float* __restrict__ embW2,
                                               const float* __restrict__ embb2,
                                               const float* __restrict__ v,
                                               const float* __restrict__ rr)
{
    extern __shared__ float sm[];
    float* w2t = sm;                 // 128*KP
    float* w1  = w2t + 128*KP;       // 7*128
    float* be  = w1 + 7*128;
    float* b2e = be + 128;
    float* hid = b2e + 128;          // 16*128
    float* rv  = hid + TIL*128;      // 16*8
    for (int idx = threadIdx.x; idx < 128*128; idx += 128){
        int k = idx >> 7, jj = idx & 127;
        w2t[jj*KP + k] = embW2[idx];
    }
    for (int idx = threadIdx.x; idx < 7*128; idx += 128) w1[idx] = embW1[idx];
    be[threadIdx.x]  = g_bias_emb[threadIdx.x];
    b2e[threadIdx.x] = embb2[threadIdx.x];
    __syncthreads();
    int j = threadIdx.x;
    for (int tile = blockIdx.x; tile < NND/TIL; tile += gridDim.x){
        int base = tile*TIL;
        if (j < TIL*7){ int i = j/7, c = j%7;
            rv[i*8+c] = (c==0) ? rr[base+i] : v[(base+i)*6 + c-1]; }
        __syncthreads();
        #pragma unroll
        for (int i = 0; i < TIL; i++){
            float acc = be[j] + rv[i*8]*w1[j];
            #pragma unroll
            for (int c = 0; c < 6; c++) acc += rv[i*8+1+c]*w1[(1+c)*128 + j];
            hid[i*128 + j] = fmaxf(acc, 0.f);
        }
        __syncthreads();
        u64 acc[TIL];
        #pragma unroll
        for (int i = 0; i < TIL; i++) acc[i] = 0ull;
        const float* wr = &w2t[j*KP];
        #pragma unroll 4
        for (int k = 0; k < 128; k += 4){
            ulonglong2 w = *(const ulonglong2*)(wr + k);
            #pragma unroll
            for (int i = 0; i < TIL; i++){
                ulonglong2 x = *(const ulonglong2*)(&hid[i*128 + k]);
                ffma2(acc[i], x.x, w.x);
                ffma2(acc[i], x.y, w.y);
            }
        }
        #pragma unroll
        for (int i = 0; i < TIL; i++)
            g_h[(base+i)*HD + j] = fmaxf(hadd2(acc[i]) + b2e[j], 0.f);
        __syncthreads();
    }
}

__global__ void __launch_bounds__(128) k_AB(const float* __restrict__ msgW1,
                                            const float* __restrict__ v,
                                            const float* __restrict__ rr, int l)
{
    extern __shared__ float sm[];
    float* wdT = sm;
    float* wsT = wdT + 128*KP;
    float* wv  = wsT + 128*KP;       // 6*128
    float* wrd = wv + 6*128;
    float* wrs = wrd + 128;
    float* hsm = wrs + 128;          // 16*128
    float* rv  = hsm + TIL*128;      // 16*8
    const float* W = msgW1 + (size_t)l*279*HD;
    for (int idx = threadIdx.x; idx < 128*128; idx += 128){
        int k = idx >> 7, jj = idx & 127;
        wdT[jj*KP + k] = W[idx];
        wsT[jj*KP + k] = W[128*128 + idx];
    }
    for (int idx = threadIdx.x; idx < 6*128; idx += 128) wv[idx] = W[259*128 + idx];
    wrd[threadIdx.x] = W[265*128 + threadIdx.x];
    wrs[threadIdx.x] = W[266*128 + threadIdx.x];
    __syncthreads();
    int j = threadIdx.x;
    for (int tile = blockIdx.x; tile < NND/TIL; tile += gridDim.x){
        int base = tile*TIL;
        for (int idx = j; idx < TIL*128; idx += 128) hsm[idx] = g_h[base*HD + idx];
        if (j < TIL*7){ int i = j/7, c = j%7;
            rv[i*8+c] = (c==0) ? rr[base+i] : v[(base+i)*6 + c-1]; }
        __syncthreads();
        u64 accA[TIL], accB[TIL];
        #pragma unroll
        for (int i = 0; i < TIL; i++){ accA[i] = 0ull; accB[i] = 0ull; }
        const float* wd = &wdT[j*KP];
        const float* ws = &wsT[j*KP];
        #pragma unroll 2
        for (int k = 0; k < 128; k += 4){
            ulonglong2 wa = *(const ulonglong2*)(wd + k);
            ulonglong2 wb = *(const ulonglong2*)(ws + k);
            #pragma unroll
            for (int i = 0; i < TIL; i++){
                ulonglong2 x = *(const ulonglong2*)(&hsm[i*128 + k]);
                ffma2(accA[i], x.x, wa.x); ffma2(accA[i], x.y, wa.y);
                ffma2(accB[i], x.x, wb.x); ffma2(accB[i], x.y, wb.y);
            }
        }
        #pragma unroll
        for (int i = 0; i < TIL; i++){
            float vd = 0.f;
            #pragma unroll
            for (int c = 0; c < 6; c++) vd += rv[i*8+1+c]*wv[c*128 + j];
            float ri = rv[i*8];
            g_A[(base+i)*HD + j] = hadd2(accA[i]) + vd + ri*wrd[j];
            g_B[(base+i)*HD + j] = hadd2(accB[i]) - vd + ri*wrs[j];
        }
        __syncthreads();
    }
}

__global__ void __launch_bounds__(128) k_edge(const float* __restrict__ msgW1,
                                              const float* __restrict__ msgW2,
                                              const float* __restrict__ msgb2,
                                              const int* __restrict__ ei,
                                              const float* __restrict__ pos,
                                              const float* __restrict__ dom, int l)
{
    extern __shared__ float sm[];
    float* w2t  = sm;                 // 128*KP
    float* wp   = w2t + 128*KP;       // 3*128
    float* bias = wp + 3*128;
    float* b2   = bias + 128;
    float* m1   = b2 + 128;           // 16*128
    float* dsm  = m1 + TIL*128;       // 4
    float* dp   = dsm + 4;            // 16*4
    int*   es   = (int*)(dp + TIL*4); // 16
    int*   ed   = es + TIL;           // 16
    const float* W1 = msgW1 + (size_t)l*279*HD;
    const float* W2 = msgW2 + (size_t)l*HD*HD;
    for (int idx = threadIdx.x; idx < 128*128; idx += 128){
        int k = idx >> 7, jj = idx & 127;
        w2t[jj*KP + k] = W2[idx];
    }
    for (int idx = threadIdx.x; idx < 3*128; idx += 128) wp[idx] = W1[256*128 + idx];
    bias[threadIdx.x] = g_bias_msg[l*HD + threadIdx.x];
    b2[threadIdx.x]   = msgb2[l*HD + threadIdx.x];
    if (threadIdx.x < 3) dsm[threadIdx.x] = dom[threadIdx.x];
    __syncthreads();
    int j = threadIdx.x;
    for (int tile = blockIdx.x; tile < NED/TIL; tile += gridDim.x){
        int base = tile*TIL;
        if (j < TIL) es[j] = ei[base + j];
        else if (j < 2*TIL) ed[j-TIL] = ei[NED + base + (j-TIL)];
        __syncthreads();
        if (j < TIL*3){
            int e = j/3, c = j%3;
            float d = pos[ed[e]*3 + c] - pos[es[e]*3 + c];
            float dm = dsm[c];
            d -= dm * rintf(d/dm);
            dp[e*4 + c] = d;
        }
        __syncthreads();
        #pragma unroll
        for (int e = 0; e < TIL; e++){
            float pre = g_A[ed[e]*HD + j] + g_B[es[e]*HD + j] + bias[j];
            pre += dp[e*4+0]*wp[j] + dp[e*4+1]*wp[128+j] + dp[e*4+2]*wp[256+j];
            m1[e*128 + j] = fmaxf(pre, 0.f);
        }
        __syncthreads();
        u64 acc[TIL];
        #pragma unroll
        for (int e = 0; e < TIL; e++) acc[e] = 0ull;
        const float* wr = &w2t[j*KP];
        #pragma unroll 2
        for (int k = 0; k < 128; k += 4){
            ulonglong2 w = *(const ulonglong2*)(wr + k);
            #pragma unroll
            for (int e = 0; e < TIL; e++){
                ulonglong2 x = *(const ulonglong2*)(&m1[e*128 + k]);
                ffma2(acc[e], x.x, w.x);
                ffma2(acc[e], x.y, w.y);
            }
        }
        #pragma unroll
        for (int e = 0; e < TIL; e++){
            float m = fmaxf(hadd2(acc[e]) + b2[j], 0.f);
            atomicAdd(&g_agg[ed[e]*HD + j], m);
        }
        __syncthreads();
    }
}

__global__ void __launch_bounds__(128) k_upd1(const float* __restrict__ updW1, int l)
{
    extern __shared__ float sm[];
    float* whT  = sm;
    float* waT  = whT + 128*KP;
    float* bias = waT + 128*KP;
    float* hsm  = bias + 128;         // 16*128
    float* agm  = hsm + TIL*128;      // 16*128
    float* dinv = agm + TIL*128;      // 16
    const float* W = updW1 + (size_t)l*268*HD;
    for (int idx = threadIdx.x; idx < 128*128; idx += 128){
        int k = idx >> 7, jj = idx & 127;
        whT[jj*KP + k] = W[idx];
        waT[jj*KP + k] = W[128*128 + idx];
    }
    bias[threadIdx.x] = g_bias_upd[l*HD + threadIdx.x];
    __syncthreads();
    int j = threadIdx.x;
    for (int tile = blockIdx.x; tile < NND/TIL; tile += gridDim.x){
        int base = tile*TIL;
        if (j < TIL) dinv[j] = 1.f / fmaxf(g_deg[base + j], 1.f);
        for (int idx = j; idx < TIL*128; idx += 128) hsm[idx] = g_h[base*HD + idx];
        __syncthreads();
        for (int idx = j; idx < TIL*128; idx += 128)
            agm[idx] = g_agg[base*HD + idx] * dinv[idx >> 7];
        __syncthreads();
        u64 acc[TIL];
        #pragma unroll
        for (int i = 0; i < TIL; i++) acc[i] = 0ull;
        const float* wh = &whT[j*KP];
        const float* wa = &waT[j*KP];
        #pragma unroll 2
        for (int k = 0; k < 128; k += 4){
            ulonglong2 w1v = *(const ulonglong2*)(wh + k);
            ulonglong2 w2v = *(const ulonglong2*)(wa + k);
            #pragma unroll
            for (int i = 0; i < TIL; i++){
                ulonglong2 x = *(const ulonglong2*)(&hsm[i*128 + k]);
                ulonglong2 a = *(const ulonglong2*)(&agm[i*128 + k]);
                ffma2(acc[i], x.x, w1v.x); ffma2(acc[i], x.y, w1v.y);
                ffma2(acc[i], a.x, w2v.x); ffma2(acc[i], a.y, w2v.y);
            }
        }
        #pragma unroll
        for (int i = 0; i < TIL; i++)
            g_u1[(base+i)*HD + j] = fmaxf(hadd2(acc[i]) + bias[j], 0.f);
        __syncthreads();
    }
}

__global__ void __launch_bounds__(128) k_upd2(const float* __restrict__ updW2,
                                              const float* __restrict__ updb2, int l)
{
    extern __shared__ float sm[];
    float* w2t = sm;
    float* b2  = w2t + 128*KP;
    float* usm = b2 + 128;            // 16*128
    const float* W = updW2 + (size_t)l*HD*HD;
    for (int idx = threadIdx.x; idx < 128*128; idx += 128){
        int k = idx >> 7, jj = idx & 127;
        w2t[jj*KP + k] = W[idx];
    }
    b2[threadIdx.x] = updb2[l*HD + threadIdx.x];
    __syncthreads();
    int j = threadIdx.x;
    float s1 = 0.f, s2 = 0.f;
    for (int tile = blockIdx.x; tile < NND/TIL; tile += gridDim.x){
        int base = tile*TIL;
        for (int idx = j; idx < TIL*128; idx += 128) usm[idx] = g_u1[base*HD + idx];
        __syncthreads();
        u64 acc[TIL];
        #pragma unroll
        for (int i = 0; i < TIL; i++) acc[i] = 0ull;
        const float* wr = &w2t[j*KP];
        #pragma unroll 4
        for (int k = 0; k < 128; k += 4){
            ulonglong2 w = *(const ulonglong2*)(wr + k);
            #pragma unroll
            for (int i = 0; i < TIL; i++){
                ulonglong2 x = *(const ulonglong2*)(&usm[i*128 + k]);
                ffma2(acc[i], x.x, w.x);
                ffma2(acc[i], x.y, w.y);
            }
        }
        #pragma unroll
        for (int i = 0; i < TIL; i++){
            float hn = g_h[(base+i)*HD + j] + hadd2(acc[i]) + b2[j];
            g_hn[(base+i)*HD + j] = hn;
            s1 += hn; s2 += hn*hn;
        }
        __syncthreads();
    }
    atomicAdd(&g_stats[j], s1);
    atomicAdd(&g_stats[HD + j], s2);
}

__global__ void k_norm(){
    const float inv_n = 1.0f / (float)NND;
    int total = NND*HD;
    for (int idx = blockIdx.x*blockDim.x + threadIdx.x; idx < total; idx += gridDim.x*blockDim.x){
        int j = idx & 127;
        float mean = g_stats[j]*inv_n;
        float var  = fmaxf(g_stats[HD + j]*inv_n - mean*mean, 0.f);
        g_h[idx] = (g_hn[idx] - mean) * rsqrtf(var + 1e-5f);
    }
}

__global__ void k_hsum(){
    int j = threadIdx.x;
    float s = 0.f;
    for (int node = blockIdx.x; node < NND; node += gridDim.x)
        s += g_h[node*HD + j];
    atomicAdd(&g_hsum[j], s);
}

__global__ void __launch_bounds__(128) k_out(const float* __restrict__ outW1,
                                             const float* __restrict__ outb1,
                                             const float* __restrict__ outW2,
                                             const float* __restrict__ outb2,
                                             const float* __restrict__ pos,
                                             const float* __restrict__ v,
                                             const float* __restrict__ domn,
                                             float* __restrict__ out)
{
    extern __shared__ float sm[];
    float* w1T = sm;                  // 128*KP
    float* b1  = w1T + 128*KP;
    float* w2o = b1 + 128;            // 128*12
    float* b2o = w2o + 128*12;        // 16
    float* dnx = b2o + 16;            // 4
    float* hsm = dnx + 4;             // 16*128
    float* o1  = hsm + TIL*128;       // 16*128
    float* rv9 = o1 + TIL*128;        // 16*12
    for (int idx = threadIdx.x; idx < 128*128; idx += 128){
        int k = idx >> 7, jj = idx & 127;
        w1T[jj*KP + k] = outW1[idx];
    }
    for (int idx = threadIdx.x; idx < HD*9; idx += 128){
        int k = idx/9, c = idx%9;
        w2o[k*12 + c] = outW2[idx];
    }
    b1[threadIdx.x] = outb1[threadIdx.x];
    if (threadIdx.x < 9) b2o[threadIdx.x] = outb2[threadIdx.x];
    if (threadIdx.x < 3) dnx[threadIdx.x] = domn[threadIdx.x];
    __syncthreads();
    int j = threadIdx.x;
    for (int tile = blockIdx.x; tile < NND/TIL; tile += gridDim.x){
        int base = tile*TIL;
        for (int idx = j; idx < TIL*128; idx += 128) hsm[idx] = g_h[base*HD + idx];
        for (int tt = j; tt < TIL*9; tt += 128){
            int i = tt/9, c = tt%9;
            rv9[i*12 + c] = (c < 3) ? pos[(base+i)*3 + c] : v[(base+i)*6 + c-3];
        }
        __syncthreads();
        u64 acc[TIL];
        #pragma unroll
        for (int i = 0; i < TIL; i++) acc[i] = 0ull;
        const float* wr = &w1T[j*KP];
        #pragma unroll 4
        for (int k = 0; k < 128; k += 4){
            ulonglong2 w = *(const ulonglong2*)(wr + k);
            #pragma unroll
            for (int i = 0; i < TIL; i++){
                ulonglong2 x = *(const ulonglong2*)(&hsm[i*128 + k]);
                ffma2(acc[i], x.x, w.x);
                ffma2(acc[i], x.y, w.y);
            }
        }
        #pragma unroll
        for (int i = 0; i < TIL; i++)
            o1[i*128 + j] = fmaxf(hadd2(acc[i]) + b1[j], 0.f);
        __syncthreads();
        for (int tt = j; tt < TIL*9; tt += 128){
            int i = tt/9, c = tt%9;
            float s = b2o[c];
            for (int k = 0; k < HD; k++) s += o1[i*128 + k]*w2o[k*12 + c];
            if (c < 3){
                float p = 0.001f*s + rv9[i*12 + c];
                float d = dnx[c];
                out[(base+i)*3 + c] = p - floorf(p/d)*d;
            } else {
                float sc = (c < 6) ? 0.001f : 0.01f;
                out[NND*3 + (base+i)*6 + (c-3)] = sc*s + rv9[i*12 + c];
            }
        }
        __syncthreads();
    }
}

__global__ void k_macro(const float* __restrict__ W1, const float* __restrict__ b1,
                        const float* __restrict__ W2, const float* __restrict__ b2,
                        float* __restrict__ out)
{
    __shared__ float hm[HD];
    __shared__ float hid[HD];
    int j = threadIdx.x;
    hm[j] = g_hsum[j] * (1.0f / (float)NND);
    __syncthreads();
    float acc = b1[j];
    for (int k = 0; k < HD; k++) acc += hm[k]*W1[k*HD + j];
    hid[j] = fmaxf(acc, 0.f);
    __syncthreads();
    if (j < 3){
        float s = b2[j];
        for (int k = 0; k < HD; k++) s += hid[k]*W2[k*3 + j];
        out[NND*9 + j] = s;
    }
}

extern "C" void kernel_launch(void* const* d_in, const int* in_sizes, int n_in,
                              void* d_out, int out_size)
{
    const float* v    = (const float*)d_in[0];
    const float* pos  = (const float*)d_in[1];
    const float* r    = (const float*)d_in[2];
    const float* dom  = (const float*)d_in[3];
    const float* t    = (const float*)d_in[4];
    const float* xg   = (const float*)d_in[5];
    const float* domn = (const float*)d_in[6];
    const float* tn   = (const float*)d_in[7];
    const int*   ei   = (const int*)d_in[8];
    const float* embW1=(const float*)d_in[10];
    const float* embb1=(const float*)d_in[11];
    const float* embW2=(const float*)d_in[12];
    const float* embb2=(const float*)d_in[13];
    const float* msgW1=(const float*)d_in[14];
    const float* msgb1=(const float*)d_in[15];
    const float* msgW2=(const float*)d_in[16];
    const float* msgb2=(const float*)d_in[17];
    const float* updW1=(const float*)d_in[18];
    const float* updb1=(const float*)d_in[19];
    const float* updW2=(const float*)d_in[20];
    const float* updb2=(const float*)d_in[21];
    const float* outW1=(const float*)d_in[22];
    const float* outb1=(const float*)d_in[23];
    const float* outW2=(const float*)d_in[24];
    const float* outb2=(const float*)d_in[25];
    const float* macW1=(const float*)d_in[26];
    const float* macb1=(const float*)d_in[27];
    const float* macW2=(const float*)d_in[28];
    const float* macb2=(const float*)d_in[29];
    float* out = (float*)d_out;

    size_t smEmbed = (size_t)(128*KP + 7*128 + 128 + 128 + TIL*128 + TIL*8)*4;
    size_t smAB    = (size_t)(2*128*KP + 6*128 + 256 + TIL*128 + TIL*8)*4;
    size_t smEdge  = (size_t)(128*KP + 3*128 + 256 + TIL*128 + 4 + TIL*4 + 2*TIL)*4;
    size_t smU1    = (size_t)(2*128*KP + 128 + 2*TIL*128 + TIL)*4;
    size_t smU2    = (size_t)(128*KP + 128 + TIL*128)*4;
    size_t smOut   = (size_t)(128*KP + 128 + 128*12 + 16 + 4 + 2*TIL*128 + TIL*12)*4;
    cudaFuncSetAttribute(k_embed, cudaFuncAttributeMaxDynamicSharedMemorySize, (int)smEmbed);
    cudaFuncSetAttribute(k_AB,    cudaFuncAttributeMaxDynamicSharedMemorySize, (int)smAB);
    cudaFuncSetAttribute(k_edge,  cudaFuncAttributeMaxDynamicSharedMemorySize, (int)smEdge);
    cudaFuncSetAttribute(k_upd1,  cudaFuncAttributeMaxDynamicSharedMemorySize, (int)smU1);
    cudaFuncSetAttribute(k_upd2,  cudaFuncAttributeMaxDynamicSharedMemorySize, (int)smU2);
    cudaFuncSetAttribute(k_out,   cudaFuncAttributeMaxDynamicSharedMemorySize, (int)smOut);

    k_prep<<<1,128>>>(dom, t, xg, domn, tn, embW1, embb1, msgW1, msgb1, updW1, updb1);
    k_zero0<<<64,256>>>();
    k_count<<<256,256>>>(ei);
    k_embed<<<296,128,smEmbed>>>(embW1, embW2, embb2, v, r);
    for (int l = 0; l < NL; l++){
        k_zeroagg<<<512,256>>>();
        k_AB<<<148,128,smAB>>>(msgW1, v, r, l);
        k_edge<<<296,128,smEdge>>>(msgW1, msgW2, msgb2, ei, pos, dom, l);
        k_upd1<<<148,128,smU1>>>(updW1, l);
        k_upd2<<<296,128,smU2>>>(updW2, updb2, l);
        k_norm<<<512,256>>>();
    }
    k_hsum<<<148,128>>>();
    k_out<<<296,128,smOut>>>(outW1, outb1, outW2, outb2, pos, v, domn, out);
    k_macro<<<1,128>>>(macW1, macb1, macW2, macb2, out);
}

// round 5
// speedup vs baseline: 1.2819x; 1.2819x over previous
#include <cuda_runtime.h>

#define NND 50000
#define NED 300000
#define HD 128
#define NL 6
#define KP 132
#define TIL 16
#define NTILE (NND/TIL)
#define ETILE (NED/TIL)

__device__ float g_h[NND*HD];      // pre-norm activations z
__device__ float g_A[NND*HD];
__device__ float g_B[NND*HD];
__device__ float g_agg[NND*HD];
__device__ float g_u1[NND*HD];
__device__ float g_deg[NND];
__device__ float g_bias_emb[HD];
__device__ float g_bias_msg[NL*HD];
__device__ float g_bias_upd[NL*HD];
__device__ float g_stats[2*HD];
__device__ float g_mu[HD];
__device__ float g_is[HD];
__device__ float g_hsum[HD];

typedef unsigned long long u64;

__device__ __forceinline__ void ffma2(u64 &d, u64 a, u64 b){
    asm("fma.rn.f32x2 %0, %1, %2, %0;" : "+l"(d) : "l"(a), "l"(b));
}
__device__ __forceinline__ float hadd2(u64 a){
    return __uint_as_float((unsigned)a) + __uint_as_float((unsigned)(a>>32));
}
__device__ __forceinline__ void red4(float* p, float4 v){
    asm volatile("red.global.add.v4.f32 [%0], {%1,%2,%3,%4};"
                 :: "l"(p), "f"(v.x), "f"(v.y), "f"(v.z), "f"(v.w) : "memory");
}

__global__ void k_prep(const float* __restrict__ dom, const float* __restrict__ t,
                       const float* __restrict__ xg, const float* __restrict__ domn,
                       const float* __restrict__ tn,
                       const float* __restrict__ embW1, const float* __restrict__ embb1,
                       const float* __restrict__ msgW1, const float* __restrict__ msgb1,
                       const float* __restrict__ updW1, const float* __restrict__ updb1)
{
    __shared__ float gf[12];
    int j = threadIdx.x;
    if (j < 12){
        float val;
        if (j < 3) val = dom[j];
        else if (j == 3) val = t[0];
        else if (j < 8) val = xg[j-4];
        else if (j < 11) val = domn[j-8];
        else val = tn[0];
        gf[j] = val;
    }
    __syncthreads();
    float acc = embb1[j];
    #pragma unroll
    for (int g = 0; g < 12; g++) acc += gf[g]*embW1[(7+g)*HD + j];
    g_bias_emb[j] = acc;
    for (int l = 0; l < NL; l++){
        const float* W = msgW1 + (size_t)l*279*HD;
        float a = msgb1[l*HD + j];
        #pragma unroll
        for (int g = 0; g < 12; g++) a += gf[g]*W[(267+g)*HD + j];
        g_bias_msg[l*HD + j] = a;
        const float* U = updW1 + (size_t)l*268*HD;
        float b = updb1[l*HD + j];
        #pragma unroll
        for (int g = 0; g < 12; g++) b += gf[g]*U[(256+g)*HD + j];
        g_bias_upd[l*HD + j] = b;
    }
}

__global__ void k_zero0(){
    int i = blockIdx.x*blockDim.x + threadIdx.x;
    for (int idx = i; idx < NND; idx += gridDim.x*blockDim.x) g_deg[idx] = 0.f;
    if (i < HD){ g_hsum[i] = 0.f; g_mu[i] = 0.f; g_is[i] = 1.f; }
}

__global__ void k_zeroagg(){
    int i = blockIdx.x*blockDim.x + threadIdx.x;
    float4 z = {0.f,0.f,0.f,0.f};
    for (int idx = i; idx < NND*HD/4; idx += gridDim.x*blockDim.x)
        ((float4*)g_agg)[idx] = z;
    if (i < 2*HD) g_stats[i] = 0.f;
}

__global__ void k_count(const int* __restrict__ ei){
    for (int e = blockIdx.x*blockDim.x + threadIdx.x; e < NED; e += gridDim.x*blockDim.x)
        atomicAdd(&g_deg[ei[NED + e]], 1.0f);
}

__global__ void k_stats(){
    int j = threadIdx.x;
    const float inv_n = 1.0f/(float)NND;
    float mu = g_stats[j]*inv_n;
    float var = fmaxf(g_stats[HD+j]*inv_n - mu*mu, 0.f);
    g_mu[j] = mu;
    g_is[j] = rsqrtf(var + 1e-5f);
}

// ---------------- embedding ----------------
__global__ void __launch_bounds__(256) k_embed(const float* __restrict__ embW1,
                                               const float* __restrict__ embW2,
                                               const float* __restrict__ embb2,
                                               const float* __restrict__ v,
                                               const float* __restrict__ rr)
{
    extern __shared__ float sm[];
    float* w2t = sm;                 // 128*KP
    float* w1  = w2t + 128*KP;       // 7*128
    float* be  = w1 + 7*128;         // 128
    float* b2e = be + 128;           // 128
    float* hid = b2e + 128;          // 16*128
    float* rv  = hid + TIL*128;      // 16*8
    int tid = threadIdx.x;
    for (int idx = tid; idx < 128*128; idx += 256){
        int k = idx >> 7, jj = idx & 127;
        w2t[jj*KP + k] = embW2[idx];
    }
    for (int idx = tid; idx < 7*128; idx += 256) w1[idx] = embW1[idx];
    if (tid < 128){ be[tid] = g_bias_emb[tid]; b2e[tid] = embb2[tid]; }
    __syncthreads();
    int j = tid & 127, r0 = (tid >> 7)*8;
    for (int tile = blockIdx.x; tile < NTILE; tile += gridDim.x){
        int base = tile*TIL;
        if (tid < TIL*7){ int i = tid/7, c = tid%7;
            rv[i*8+c] = (c==0) ? rr[base+i] : v[(base+i)*6 + c-1]; }
        __syncthreads();
        #pragma unroll
        for (int i = r0; i < r0+8; i++){
            float acc = be[j] + rv[i*8]*w1[j];
            #pragma unroll
            for (int c = 0; c < 6; c++) acc += rv[i*8+1+c]*w1[(1+c)*128 + j];
            hid[i*128 + j] = fmaxf(acc, 0.f);
        }
        __syncthreads();
        u64 acc[8];
        #pragma unroll
        for (int i = 0; i < 8; i++) acc[i] = 0ull;
        const float* wr = &w2t[j*KP];
        const float* hb = &hid[r0*128];
        #pragma unroll 2
        for (int k = 0; k < 128; k += 4){
            ulonglong2 w = *(const ulonglong2*)(wr + k);
            #pragma unroll
            for (int i = 0; i < 8; i++){
                ulonglong2 x = *(const ulonglong2*)(hb + i*128 + k);
                ffma2(acc[i], x.x, w.x);
                ffma2(acc[i], x.y, w.y);
            }
        }
        #pragma unroll
        for (int i = 0; i < 8; i++)
            g_h[(base+r0+i)*HD + j] = fmaxf(hadd2(acc[i]) + b2e[j], 0.f);
        __syncthreads();
    }
}

// ---------------- node precompute A or B ----------------
__global__ void __launch_bounds__(256) k_node(const float* __restrict__ msgW1,
                                              const float* __restrict__ v,
                                              const float* __restrict__ rr,
                                              int l, int which)
{
    extern __shared__ float sm[];
    float* wT  = sm;                 // 128*KP
    float* wv  = wT + 128*KP;        // 6*128
    float* wrc = wv + 6*128;         // 128
    float* mu  = wrc + 128;          // 128
    float* is  = mu + 128;           // 128
    float* hsm = is + 128;           // 16*128
    float* rv  = hsm + TIL*128;      // 16*8
    const float* W = msgW1 + (size_t)l*279*HD;
    const float* Wm = W + (which ? 128*128 : 0);
    float sgn = which ? -1.f : 1.f;
    float* ob = which ? g_B : g_A;
    int tid = threadIdx.x;
    for (int idx = tid; idx < 128*128; idx += 256){
        int k = idx >> 7, jj = idx & 127;
        wT[jj*KP + k] = Wm[idx];
    }
    for (int idx = tid; idx < 6*128; idx += 256) wv[idx] = W[259*128 + idx];
    if (tid < 128){
        wrc[tid] = W[(265+which)*128 + tid];
        mu[tid] = g_mu[tid]; is[tid] = g_is[tid];
    }
    __syncthreads();
    int j = tid & 127, r0 = (tid >> 7)*8;
    for (int tile = blockIdx.x; tile < NTILE; tile += gridDim.x){
        int base = tile*TIL;
        for (int idx = tid; idx < TIL*128; idx += 256)
            hsm[idx] = (g_h[base*HD + idx] - mu[idx & 127])*is[idx & 127];
        if (tid < TIL*7){ int i = tid/7, c = tid%7;
            rv[i*8+c] = (c==0) ? rr[base+i] : v[(base+i)*6 + c-1]; }
        __syncthreads();
        u64 acc[8];
        #pragma unroll
        for (int i = 0; i < 8; i++) acc[i] = 0ull;
        const float* wr = &wT[j*KP];
        const float* hb = &hsm[r0*128];
        #pragma unroll 2
        for (int k = 0; k < 128; k += 4){
            ulonglong2 w = *(const ulonglong2*)(wr + k);
            #pragma unroll
            for (int i = 0; i < 8; i++){
                ulonglong2 x = *(const ulonglong2*)(hb + i*128 + k);
                ffma2(acc[i], x.x, w.x);
                ffma2(acc[i], x.y, w.y);
            }
        }
        #pragma unroll
        for (int i = 0; i < 8; i++){
            int row = r0 + i;
            float vd = 0.f;
            #pragma unroll
            for (int c = 0; c < 6; c++) vd += rv[row*8+1+c]*wv[c*128 + j];
            ob[(base+row)*HD + j] = hadd2(acc[i]) + sgn*vd + rv[row*8]*wrc[j];
        }
        __syncthreads();
    }
}

// ---------------- edge kernel ----------------
__global__ void __launch_bounds__(256) k_edge(const float* __restrict__ msgW1,
                                              const float* __restrict__ msgW2,
                                              const float* __restrict__ msgb2,
                                              const int* __restrict__ ei,
                                              const float* __restrict__ pos,
                                              const float* __restrict__ dom, int l)
{
    extern __shared__ float sm[];
    float* w2t  = sm;                 // 128*KP
    float* wp   = w2t + 128*KP;       // 3*128
    float* bias = wp + 3*128;         // 128
    float* b2   = bias + 128;         // 128
    float* m1   = b2 + 128;           // 16*128
    float* dsm  = m1 + TIL*128;       // 4
    float* dp   = dsm + 4;            // 16*4
    int*   es   = (int*)(dp + TIL*4); // 16
    int*   ed   = es + TIL;           // 16
    const float* W1 = msgW1 + (size_t)l*279*HD;
    const float* W2 = msgW2 + (size_t)l*HD*HD;
    int tid = threadIdx.x;
    for (int idx = tid; idx < 128*128; idx += 256){
        int k = idx >> 7, jj = idx & 127;
        w2t[jj*KP + k] = W2[idx];
    }
    for (int idx = tid; idx < 3*128; idx += 256) wp[idx] = W1[256*128 + idx];
    if (tid < 128){
        bias[tid] = g_bias_msg[l*HD + tid];
        b2[tid]   = msgb2[l*HD + tid];
    }
    if (tid < 3) dsm[tid] = dom[tid];
    __syncthreads();
    int j = tid & 127, r0 = (tid >> 7)*8;
    for (int tile = blockIdx.x; tile < ETILE; tile += gridDim.x){
        int base = tile*TIL;
        if (tid < TIL) es[tid] = ei[base + tid];
        else if (tid < 2*TIL) ed[tid-TIL] = ei[NED + base + (tid-TIL)];
        __syncthreads();
        if (tid < TIL*3){
            int e = tid/3, c = tid%3;
            float d = pos[ed[e]*3 + c] - pos[es[e]*3 + c];
            float dm = dsm[c];
            d -= dm * rintf(d/dm);
            dp[e*4 + c] = d;
        }
        __syncthreads();
        #pragma unroll
        for (int e = r0; e < r0+8; e++){
            float pre = g_A[ed[e]*HD + j] + g_B[es[e]*HD + j] + bias[j];
            pre += dp[e*4+0]*wp[j] + dp[e*4+1]*wp[128+j] + dp[e*4+2]*wp[256+j];
            m1[e*128 + j] = fmaxf(pre, 0.f);
        }
        __syncthreads();
        u64 acc[8];
        #pragma unroll
        for (int e = 0; e < 8; e++) acc[e] = 0ull;
        const float* wr = &w2t[j*KP];
        const float* mb = &m1[r0*128];
        #pragma unroll 2
        for (int k = 0; k < 128; k += 4){
            ulonglong2 w = *(const ulonglong2*)(wr + k);
            #pragma unroll
            for (int e = 0; e < 8; e++){
                ulonglong2 x = *(const ulonglong2*)(mb + e*128 + k);
                ffma2(acc[e], x.x, w.x);
                ffma2(acc[e], x.y, w.y);
            }
        }
        __syncthreads();
        #pragma unroll
        for (int e = 0; e < 8; e++)
            m1[(r0+e)*128 + j] = fmaxf(hadd2(acc[e]) + b2[j], 0.f);
        __syncthreads();
        #pragma unroll
        for (int q = 0; q < 2; q++){
            int idx = tid + q*256;
            int e = idx >> 5, c = idx & 31;
            float4 val = ((const float4*)m1)[e*32 + c];
            red4(&g_agg[ed[e]*HD + c*4], val);
        }
        __syncthreads();
    }
}

// ---------------- update first linear (K=256) ----------------
__global__ void __launch_bounds__(256) k_upd1(const float* __restrict__ updW1, int l)
{
    extern __shared__ float sm[];
    float* whT  = sm;
    float* waT  = whT + 128*KP;
    float* bias = waT + 128*KP;       // 128
    float* mu   = bias + 128;         // 128
    float* is   = mu + 128;           // 128
    float* hsm  = is + 128;           // 16*128
    float* agm  = hsm + TIL*128;      // 16*128
    float* dinv = agm + TIL*128;      // 16
    const float* W = updW1 + (size_t)l*268*HD;
    int tid = threadIdx.x;
    for (int idx = tid; idx < 128*128; idx += 256){
        int k = idx >> 7, jj = idx & 127;
        whT[jj*KP + k] = W[idx];
        waT[jj*KP + k] = W[128*128 + idx];
    }
    if (tid < 128){
        bias[tid] = g_bias_upd[l*HD + tid];
        mu[tid] = g_mu[tid]; is[tid] = g_is[tid];
    }
    __syncthreads();
    int j = tid & 127, r0 = (tid >> 7)*8;
    for (int tile = blockIdx.x; tile < NTILE; tile += gridDim.x){
        int base = tile*TIL;
        if (tid < TIL) dinv[tid] = 1.f / fmaxf(g_deg[base + tid], 1.f);
        for (int idx = tid; idx < TIL*128; idx += 256)
            hsm[idx] = (g_h[base*HD + idx] - mu[idx & 127])*is[idx & 127];
        __syncthreads();
        for (int idx = tid; idx < TIL*128; idx += 256)
            agm[idx] = g_agg[base*HD + idx] * dinv[idx >> 7];
        __syncthreads();
        u64 acc[8];
        #pragma unroll
        for (int i = 0; i < 8; i++) acc[i] = 0ull;
        const float* wh = &whT[j*KP];
        const float* wa = &waT[j*KP];
        const float* hb = &hsm[r0*128];
        const float* ab = &agm[r0*128];
        #pragma unroll 2
        for (int k = 0; k < 128; k += 4){
            ulonglong2 w1v = *(const ulonglong2*)(wh + k);
            ulonglong2 w2v = *(const ulonglong2*)(wa + k);
            #pragma unroll
            for (int i = 0; i < 8; i++){
                ulonglong2 x = *(const ulonglong2*)(hb + i*128 + k);
                ulonglong2 a = *(const ulonglong2*)(ab + i*128 + k);
                ffma2(acc[i], x.x, w1v.x); ffma2(acc[i], x.y, w1v.y);
                ffma2(acc[i], a.x, w2v.x); ffma2(acc[i], a.y, w2v.y);
            }
        }
        #pragma unroll
        for (int i = 0; i < 8; i++)
            g_u1[(base+r0+i)*HD + j] = fmaxf(hadd2(acc[i]) + bias[j], 0.f);
        __syncthreads();
    }
}

// ---------------- update second linear + residual + stats ----------------
__global__ void __launch_bounds__(256) k_upd2(const float* __restrict__ updW2,
                                              const float* __restrict__ updb2, int l)
{
    extern __shared__ float sm[];
    float* w2t = sm;
    float* b2  = w2t + 128*KP;        // 128
    float* mu  = b2 + 128;            // 128
    float* is  = mu + 128;            // 128
    float* usm = is + 128;            // 16*128
    const float* W = updW2 + (size_t)l*HD*HD;
    int tid = threadIdx.x;
    for (int idx = tid; idx < 128*128; idx += 256){
        int k = idx >> 7, jj = idx & 127;
        w2t[jj*KP + k] = W[idx];
    }
    if (tid < 128){
        b2[tid] = updb2[l*HD + tid];
        mu[tid] = g_mu[tid]; is[tid] = g_is[tid];
    }
    __syncthreads();
    int j = tid & 127, r0 = (tid >> 7)*8;
    float s1 = 0.f, s2 = 0.f;
    for (int tile = blockIdx.x; tile < NTILE; tile += gridDim.x){
        int base = tile*TIL;
        for (int idx = tid; idx < TIL*128; idx += 256) usm[idx] = g_u1[base*HD + idx];
        __syncthreads();
        u64 acc[8];
        #pragma unroll
        for (int i = 0; i < 8; i++) acc[i] = 0ull;
        const float* wr = &w2t[j*KP];
        const float* ub = &usm[r0*128];
        #pragma unroll 2
        for (int k = 0; k < 128; k += 4){
            ulonglong2 w = *(const ulonglong2*)(wr + k);
            #pragma unroll
            for (int i = 0; i < 8; i++){
                ulonglong2 x = *(const ulonglong2*)(ub + i*128 + k);
                ffma2(acc[i], x.x, w.x);
                ffma2(acc[i], x.y, w.y);
            }
        }
        #pragma unroll
        for (int i = 0; i < 8; i++){
            int idx = (base+r0+i)*HD + j;
            float hprev = (g_h[idx] - mu[j])*is[j];
            float z = hprev + hadd2(acc[i]) + b2[j];
            g_h[idx] = z;
            s1 += z; s2 += z*z;
        }
        __syncthreads();
    }
    atomicAdd(&g_stats[j], s1);
    atomicAdd(&g_stats[HD + j], s2);
}

__global__ void k_hsum(){
    int j = threadIdx.x;
    float s = 0.f;
    for (int node = blockIdx.x; node < NND; node += gridDim.x)
        s += g_h[node*HD + j];
    atomicAdd(&g_hsum[j], s);
}

// ---------------- output head ----------------
__global__ void __launch_bounds__(256) k_out(const float* __restrict__ outW1,
                                             const float* __restrict__ outb1,
                                             const float* __restrict__ outW2,
                                             const float* __restrict__ outb2,
                                             const float* __restrict__ pos,
                                             const float* __restrict__ v,
                                             const float* __restrict__ domn,
                                             float* __restrict__ out)
{
    extern __shared__ float sm[];
    float* w1T = sm;                  // 128*KP
    float* b1  = w1T + 128*KP;        // 128
    float* mu  = b1 + 128;            // 128
    float* is  = mu + 128;            // 128
    float* w2o = is + 128;            // 128*12
    float* b2o = w2o + 128*12;        // 16
    float* dnx = b2o + 16;            // 4
    float* hsm = dnx + 4;             // 16*128
    float* o1  = hsm + TIL*128;       // 16*128
    float* rv9 = o1 + TIL*128;        // 16*12
    int tid = threadIdx.x;
    for (int idx = tid; idx < 128*128; idx += 256){
        int k = idx >> 7, jj = idx & 127;
        w1T[jj*KP + k] = outW1[idx];
    }
    for (int idx = tid; idx < HD*9; idx += 256){
        int k = idx/9, c = idx%9;
        w2o[k*12 + c] = outW2[idx];
    }
    if (tid < 128){
        b1[tid] = outb1[tid];
        mu[tid] = g_mu[tid]; is[tid] = g_is[tid];
    }
    if (tid < 9) b2o[tid] = outb2[tid];
    if (tid < 3) dnx[tid] = domn[tid];
    __syncthreads();
    int j = tid & 127, r0 = (tid >> 7)*8;
    for (int tile = blockIdx.x; tile < NTILE; tile += gridDim.x){
        int base = tile*TIL;
        for (int idx = tid; idx < TIL*128; idx += 256)
            hsm[idx] = (g_h[base*HD + idx] - mu[idx & 127])*is[idx & 127];
        for (int tt = tid; tt < TIL*9; tt += 256){
            int i = tt/9, c = tt%9;
            rv9[i*12 + c] = (c < 3) ? pos[(base+i)*3 + c] : v[(base+i)*6 + c-3];
        }
        __syncthreads();
        u64 acc[8];
        #pragma unroll
        for (int i = 0; i < 8; i++) acc[i] = 0ull;
        const float* wr = &w1T[j*KP];
        const float* hb = &hsm[r0*128];
        #pragma unroll 2
        for (int k = 0; k < 128; k += 4){
            ulonglong2 w = *(const ulonglong2*)(wr + k);
            #pragma unroll
            for (int i = 0; i < 8; i++){
                ulonglong2 x = *(const ulonglong2*)(hb + i*128 + k);
                ffma2(acc[i], x.x, w.x);
                ffma2(acc[i], x.y, w.y);
            }
        }
        #pragma unroll
        for (int i = 0; i < 8; i++)
            o1[(r0+i)*128 + j] = fmaxf(hadd2(acc[i]) + b1[j], 0.f);
        __syncthreads();
        for (int tt = tid; tt < TIL*9; tt += 256){
            int i = tt/9, c = tt%9;
            float s = b2o[c];
            for (int k = 0; k < HD; k++) s += o1[i*128 + k]*w2o[k*12 + c];
            if (c < 3){
                float p = 0.001f*s + rv9[i*12 + c];
                float d = dnx[c];
                out[(base+i)*3 + c] = p - floorf(p/d)*d;
            } else {
                float sc = (c < 6) ? 0.001f : 0.01f;
                out[NND*3 + (base+i)*6 + (c-3)] = sc*s + rv9[i*12 + c];
            }
        }
        __syncthreads();
    }
}

__global__ void k_macro(const float* __restrict__ W1, const float* __restrict__ b1,
                        const float* __restrict__ W2, const float* __restrict__ b2,
                        float* __restrict__ out)
{
    __shared__ float hm[HD];
    __shared__ float hid[HD];
    int j = threadIdx.x;
    hm[j] = (g_hsum[j]*(1.0f/(float)NND) - g_mu[j])*g_is[j];
    __syncthreads();
    float acc = b1[j];
    for (int k = 0; k < HD; k++) acc += hm[k]*W1[k*HD + j];
    hid[j] = fmaxf(acc, 0.f);
    __syncthreads();
    if (j < 3){
        float s = b2[j];
        for (int k = 0; k < HD; k++) s += hid[k]*W2[k*3 + j];
        out[NND*9 + j] = s;
    }
}

extern "C" void kernel_launch(void* const* d_in, const int* in_sizes, int n_in,
                              void* d_out, int out_size)
{
    const float* v    = (const float*)d_in[0];
    const float* pos  = (const float*)d_in[1];
    const float* r    = (const float*)d_in[2];
    const float* dom  = (const float*)d_in[3];
    const float* t    = (const float*)d_in[4];
    const float* xg   = (const float*)d_in[5];
    const float* domn = (const float*)d_in[6];
    const float* tn   = (const float*)d_in[7];
    const int*   ei   = (const int*)d_in[8];
    const float* embW1=(const float*)d_in[10];
    const float* embb1=(const float*)d_in[11];
    const float* embW2=(const float*)d_in[12];
    const float* embb2=(const float*)d_in[13];
    const float* msgW1=(const float*)d_in[14];
    const float* msgb1=(const float*)d_in[15];
    const float* msgW2=(const float*)d_in[16];
    const float* msgb2=(const float*)d_in[17];
    const float* updW1=(const float*)d_in[18];
    const float* updb1=(const float*)d_in[19];
    const float* updW2=(const float*)d_in[20];
    const float* updb2=(const float*)d_in[21];
    const float* outW1=(const float*)d_in[22];
    const float* outb1=(const float*)d_in[23];
    const float* outW2=(const float*)d_in[24];
    const float* outb2=(const float*)d_in[25];
    const float* macW1=(const float*)d_in[26];
    const float* macb1=(const float*)d_in[27];
    const float* macW2=(const float*)d_in[28];
    const float* macb2=(const float*)d_in[29];
    float* out = (float*)d_out;

    size_t smEmbed = (size_t)(128*KP + 7*128 + 256 + TIL*128 + TIL*8)*4;
    size_t smNode  = (size_t)(128*KP + 6*128 + 3*128 + TIL*128 + TIL*8)*4;
    size_t smEdge  = (size_t)(128*KP + 3*128 + 256 + TIL*128 + 4 + TIL*4 + 2*TIL)*4;
    size_t smU1    = (size_t)(2*128*KP + 3*128 + 2*TIL*128 + TIL)*4;
    size_t smU2    = (size_t)(128*KP + 3*128 + TIL*128)*4;
    size_t smOut   = (size_t)(128*KP + 3*128 + 128*12 + 16 + 4 + 2*TIL*128 + TIL*12)*4;
    cudaFuncSetAttribute(k_embed, cudaFuncAttributeMaxDynamicSharedMemorySize, (int)smEmbed);
    cudaFuncSetAttribute(k_node,  cudaFuncAttributeMaxDynamicSharedMemorySize, (int)smNode);
    cudaFuncSetAttribute(k_edge,  cudaFuncAttributeMaxDynamicSharedMemorySize, (int)smEdge);
    cudaFuncSetAttribute(k_upd1,  cudaFuncAttributeMaxDynamicSharedMemorySize, (int)smU1);
    cudaFuncSetAttribute(k_upd2,  cudaFuncAttributeMaxDynamicSharedMemorySize, (int)smU2);
    cudaFuncSetAttribute(k_out,   cudaFuncAttributeMaxDynamicSharedMemorySize, (int)smOut);

    k_prep<<<1,128>>>(dom, t, xg, domn, tn, embW1, embb1, msgW1, msgb1, updW1, updb1);
    k_zero0<<<64,256>>>();
    k_count<<<256,256>>>(ei);
    k_embed<<<296,256,smEmbed>>>(embW1, embW2, embb2, v, r);
    for (int l = 0; l < NL; l++){
        k_zeroagg<<<512,256>>>();
        k_node<<<296,256,smNode>>>(msgW1, v, r, l, 0);
        k_node<<<296,256,smNode>>>(msgW1, v, r, l, 1);
        k_edge<<<296,256,smEdge>>>(msgW1, msgW2, msgb2, ei, pos, dom, l);
        k_upd1<<<148,256,smU1>>>(updW1, l);
        k_upd2<<<296,256,smU2>>>(updW2, updb2, l);
        k_stats<<<1,128>>>();
    }
    k_hsum<<<296,128>>>();
    k_out<<<296,256,smOut>>>(outW1, outb1, outW2, outb2, pos, v, domn, out);
    k_macro<<<1,128>>>(macW1, macb1, macW2, macb2, out);
}

// round 6
// speedup vs baseline: 1.5364x; 1.1986x over previous
#include <cuda_runtime.h>

#define NND 50000
#define NP  50048
#define NED 300000
#define NEP 300032
#define HD 128
#define NL 6
#define KP 132
#define TIL 64
#define NT  (NP/TIL)
#define ET  (NEP/TIL)
#define OTIL 32
#define ONT (NP/OTIL)

__device__ float g_h[NP*HD];
__device__ float g_A[NP*HD];
__device__ float g_B[NP*HD];
__device__ float g_agg[NP*HD];
__device__ float g_u1[NP*HD];
__device__ float g_deg[NP];
__device__ float g_bias_emb[HD];
__device__ float g_bias_msg[NL*HD];
__device__ float g_bias_upd[NL*HD];
__device__ float g_stats[2*HD];
__device__ float g_mu[HD];
__device__ float g_is[HD];
__device__ float g_hsum[HD];

typedef unsigned long long u64;

__device__ __forceinline__ void ffma2(u64 &d, u64 a, u64 b){
    asm("fma.rn.f32x2 %0, %1, %2, %0;" : "+l"(d) : "l"(a), "l"(b));
}
__device__ __forceinline__ float hadd2(u64 a){
    return __uint_as_float((unsigned)a) + __uint_as_float((unsigned)(a>>32));
}
__device__ __forceinline__ void red4(float* p, float4 v){
    asm volatile("red.global.add.v4.f32 [%0], {%1,%2,%3,%4};"
                 :: "l"(p), "f"(v.x), "f"(v.y), "f"(v.z), "f"(v.w) : "memory");
}

// 16-row x 2-channel GEMM core over K=128
#define GEMM16(ACC0, ACC1, ACTB, WR0, WR1) \
  _Pragma("unroll 2") \
  for (int kk = 0; kk < 128; kk += 4){ \
    ulonglong2 w0v = *(const ulonglong2*)((WR0) + kk); \
    ulonglong2 w1v = *(const ulonglong2*)((WR1) + kk); \
    _Pragma("unroll") \
    for (int ii = 0; ii < 16; ii++){ \
      ulonglong2 xv = *(const ulonglong2*)((ACTB) + ii*128 + kk); \
      ffma2(ACC0[ii], xv.x, w0v.x); ffma2(ACC0[ii], xv.y, w0v.y); \
      ffma2(ACC1[ii], xv.x, w1v.x); ffma2(ACC1[ii], xv.y, w1v.y); \
    } \
  }

#define GEMM8(ACC0, ACC1, ACTB, WR0, WR1) \
  _Pragma("unroll 2") \
  for (int kk = 0; kk < 128; kk += 4){ \
    ulonglong2 w0v = *(const ulonglong2*)((WR0) + kk); \
    ulonglong2 w1v = *(const ulonglong2*)((WR1) + kk); \
    _Pragma("unroll") \
    for (int ii = 0; ii < 8; ii++){ \
      ulonglong2 xv = *(const ulonglong2*)((ACTB) + ii*128 + kk); \
      ffma2(ACC0[ii], xv.x, w0v.x); ffma2(ACC0[ii], xv.y, w0v.y); \
      ffma2(ACC1[ii], xv.x, w1v.x); ffma2(ACC1[ii], xv.y, w1v.y); \
    } \
  }

__global__ void k_prep(const float* __restrict__ dom, const float* __restrict__ t,
                       const float* __restrict__ xg, const float* __restrict__ domn,
                       const float* __restrict__ tn,
                       const float* __restrict__ embW1, const float* __restrict__ embb1,
                       const float* __restrict__ msgW1, const float* __restrict__ msgb1,
                       const float* __restrict__ updW1, const float* __restrict__ updb1)
{
    __shared__ float gf[12];
    int j = threadIdx.x;
    if (j < 12){
        float val;
        if (j < 3) val = dom[j];
        else if (j == 3) val = t[0];
        else if (j < 8) val = xg[j-4];
        else if (j < 11) val = domn[j-8];
        else val = tn[0];
        gf[j] = val;
    }
    __syncthreads();
    float acc = embb1[j];
    #pragma unroll
    for (int g = 0; g < 12; g++) acc += gf[g]*embW1[(7+g)*HD + j];
    g_bias_emb[j] = acc;
    for (int l = 0; l < NL; l++){
        const float* W = msgW1 + (size_t)l*279*HD;
        float a = msgb1[l*HD + j];
        #pragma unroll
        for (int g = 0; g < 12; g++) a += gf[g]*W[(267+g)*HD + j];
        g_bias_msg[l*HD + j] = a;
        const float* U = updW1 + (size_t)l*268*HD;
        float b = updb1[l*HD + j];
        #pragma unroll
        for (int g = 0; g < 12; g++) b += gf[g]*U[(256+g)*HD + j];
        g_bias_upd[l*HD + j] = b;
    }
}

__global__ void k_zero0(){
    int i = blockIdx.x*blockDim.x + threadIdx.x;
    for (int idx = i; idx < NP; idx += gridDim.x*blockDim.x) g_deg[idx] = 0.f;
    if (i < HD){ g_hsum[i] = 0.f; g_mu[i] = 0.f; g_is[i] = 1.f; }
}

__global__ void k_zeroagg(){
    int i = blockIdx.x*blockDim.x + threadIdx.x;
    float4 z = {0.f,0.f,0.f,0.f};
    for (int idx = i; idx < NP*HD/4; idx += gridDim.x*blockDim.x)
        ((float4*)g_agg)[idx] = z;
    if (i < 2*HD) g_stats[i] = 0.f;
}

__global__ void k_count(const int* __restrict__ ei){
    for (int e = blockIdx.x*blockDim.x + threadIdx.x; e < NED; e += gridDim.x*blockDim.x)
        atomicAdd(&g_deg[ei[NED + e]], 1.0f);
}

__global__ void k_stats(){
    int j = threadIdx.x;
    const float inv_n = 1.0f/(float)NND;
    float mu = g_stats[j]*inv_n;
    float var = fmaxf(g_stats[HD+j]*inv_n - mu*mu, 0.f);
    g_mu[j] = mu;
    g_is[j] = rsqrtf(var + 1e-5f);
}

// ---------------- embedding ----------------
__global__ void __launch_bounds__(256,2) k_embed(const float* __restrict__ embW1,
                                                 const float* __restrict__ embW2,
                                                 const float* __restrict__ embb2,
                                                 const float* __restrict__ v,
                                                 const float* __restrict__ rr)
{
    extern __shared__ float sm[];
    float* w2t = sm;                 // 128*KP
    float* w1  = w2t + 128*KP;       // 7*128
    float* be  = w1 + 7*128;         // 128
    float* b2e = be + 128;           // 128
    float* hid = b2e + 128;          // 64*128
    float* rv  = hid + TIL*128;      // 64*8
    int tid = threadIdx.x;
    for (int idx = tid; idx < 128*128; idx += 256){
        int k = idx >> 7, jj = idx & 127;
        w2t[jj*KP + k] = embW2[idx];
    }
    for (int idx = tid; idx < 7*128; idx += 256) w1[idx] = embW1[idx];
    if (tid < 128){ be[tid] = g_bias_emb[tid]; b2e[tid] = embb2[tid]; }
    __syncthreads();
    int c0 = tid & 63, c1 = c0 + 64, r0 = (tid >> 6)*16;
    for (int tile = blockIdx.x; tile < NT; tile += gridDim.x){
        int base = tile*TIL;
        for (int idx = tid; idx < TIL*7; idx += 256){
            int i = idx/7, c = idx%7; int row = base + i;
            rv[i*8+c] = (row < NND) ? ((c==0) ? rr[row] : v[row*6 + c-1]) : 0.f;
        }
        __syncthreads();
        #pragma unroll
        for (int i = 0; i < 16; i++){
            int rr8 = (r0+i)*8;
            float a0 = be[c0] + rv[rr8]*w1[c0];
            float a1 = be[c1] + rv[rr8]*w1[c1];
            #pragma unroll
            for (int c = 0; c < 6; c++){
                float x = rv[rr8+1+c];
                a0 += x*w1[(1+c)*128 + c0];
                a1 += x*w1[(1+c)*128 + c1];
            }
            hid[(r0+i)*128 + c0] = fmaxf(a0, 0.f);
            hid[(r0+i)*128 + c1] = fmaxf(a1, 0.f);
        }
        __syncthreads();
        u64 acc0[16], acc1[16];
        #pragma unroll
        for (int i = 0; i < 16; i++){ acc0[i]=0ull; acc1[i]=0ull; }
        const float* wr0 = &w2t[c0*KP];
        const float* wr1 = &w2t[c1*KP];
        const float* ab  = &hid[r0*128];
        GEMM16(acc0, acc1, ab, wr0, wr1);
        #pragma unroll
        for (int i = 0; i < 16; i++){
            int row = base + r0 + i;
            g_h[row*HD + c0] = fmaxf(hadd2(acc0[i]) + b2e[c0], 0.f);
            g_h[row*HD + c1] = fmaxf(hadd2(acc1[i]) + b2e[c1], 0.f);
        }
        __syncthreads();
    }
}

// ---------------- generic node GEMM: mode 0=A, 1=B, 2=upd-h (raw to g_u1) ----------------
__global__ void __launch_bounds__(256,2) k_node(const float* __restrict__ Wblk,
                                                const float* __restrict__ Waux,
                                                const float* __restrict__ v,
                                                const float* __restrict__ rr,
                                                int mode)
{
    extern __shared__ float sm[];
    float* wT  = sm;                 // 128*KP
    float* wv  = wT + 128*KP;        // 6*128
    float* wrc = wv + 6*128;         // 128
    float* mu  = wrc + 128;          // 128
    float* is  = mu + 128;           // 128
    float* hsm = is + 128;           // 64*128
    float* rv  = hsm + TIL*128;      // 64*8
    int tid = threadIdx.x;
    for (int idx = tid; idx < 128*128; idx += 256){
        int k = idx >> 7, jj = idx & 127;
        wT[jj*KP + k] = Wblk[idx];
    }
    if (mode < 2){
        for (int idx = tid; idx < 6*128; idx += 256) wv[idx] = Waux[259*128 + idx];
        if (tid < 128) wrc[tid] = Waux[(265+mode)*128 + tid];
    }
    if (tid < 128){ mu[tid] = g_mu[tid]; is[tid] = g_is[tid]; }
    __syncthreads();
    float sgn = (mode==1) ? -1.f : 1.f;
    float* ob = (mode==0) ? g_A : (mode==1) ? g_B : g_u1;
    int c0 = tid & 63, c1 = c0 + 64, r0 = (tid >> 6)*16;
    for (int tile = blockIdx.x; tile < NT; tile += gridDim.x){
        int base = tile*TIL;
        for (int idx = tid; idx < TIL*128; idx += 256){
            int j = idx & 127;
            hsm[idx] = (g_h[base*HD + idx] - mu[j])*is[j];
        }
        if (mode < 2){
            for (int idx = tid; idx < TIL*7; idx += 256){
                int i = idx/7, c = idx%7; int row = base + i;
                rv[i*8+c] = (row < NND) ? ((c==0) ? rr[row] : v[row*6 + c-1]) : 0.f;
            }
        }
        __syncthreads();
        u64 acc0[16], acc1[16];
        #pragma unroll
        for (int i = 0; i < 16; i++){ acc0[i]=0ull; acc1[i]=0ull; }
        const float* wr0 = &wT[c0*KP];
        const float* wr1 = &wT[c1*KP];
        const float* ab  = &hsm[r0*128];
        GEMM16(acc0, acc1, ab, wr0, wr1);
        if (mode < 2){
            #pragma unroll
            for (int i = 0; i < 16; i++){
                int row = base + r0 + i;
                int rr8 = (r0+i)*8;
                float v0 = 0.f, v1 = 0.f;
                #pragma unroll
                for (int c = 0; c < 6; c++){
                    float x = rv[rr8+1+c];
                    v0 += x*wv[c*128 + c0];
                    v1 += x*wv[c*128 + c1];
                }
                float ri = rv[rr8];
                ob[row*HD + c0] = hadd2(acc0[i]) + sgn*v0 + ri*wrc[c0];
                ob[row*HD + c1] = hadd2(acc1[i]) + sgn*v1 + ri*wrc[c1];
            }
        } else {
            #pragma unroll
            for (int i = 0; i < 16; i++){
                int row = base + r0 + i;
                ob[row*HD + c0] = hadd2(acc0[i]);
                ob[row*HD + c1] = hadd2(acc1[i]);
            }
        }
        __syncthreads();
    }
}

// ---------------- edge kernel ----------------
__global__ void __launch_bounds__(256,2) k_edge(const float* __restrict__ msgW1,
                                                const float* __restrict__ msgW2,
                                                const float* __restrict__ msgb2,
                                                const int* __restrict__ ei,
                                                const float* __restrict__ pos,
                                                const float* __restrict__ dom, int l)
{
    extern __shared__ float sm[];
    float* w2t  = sm;                 // 128*KP
    float* wp   = w2t + 128*KP;       // 3*128
    float* bias = wp + 3*128;         // 128
    float* b2   = bias + 128;         // 128
    float* m1   = b2 + 128;           // 64*128
    float* dp   = m1 + TIL*128;       // 64*4
    float* dsm  = dp + TIL*4;         // 4
    int*   es   = (int*)(dsm + 4);    // 64
    int*   ed   = es + TIL;           // 64
    const float* W1 = msgW1 + (size_t)l*279*HD;
    const float* W2 = msgW2 + (size_t)l*HD*HD;
    int tid = threadIdx.x;
    for (int idx = tid; idx < 128*128; idx += 256){
        int k = idx >> 7, jj = idx & 127;
        w2t[jj*KP + k] = W2[idx];
    }
    for (int idx = tid; idx < 3*128; idx += 256) wp[idx] = W1[256*128 + idx];
    if (tid < 128){
        bias[tid] = g_bias_msg[l*HD + tid];
        b2[tid]   = msgb2[l*HD + tid];
    }
    if (tid < 3) dsm[tid] = dom[tid];
    __syncthreads();
    int c0 = tid & 63, c1 = c0 + 64, r0 = (tid >> 6)*16;
    for (int tile = blockIdx.x; tile < ET; tile += gridDim.x){
        int base = tile*TIL;
        int nval = NED - base; if (nval > TIL) nval = TIL;
        if (tid < TIL) es[tid] = (tid < nval) ? ei[base + tid] : 0;
        else if (tid < 2*TIL){
            int e = tid - TIL;
            ed[e] = (e < nval) ? ei[NED + base + e] : 0;
        }
        __syncthreads();
        for (int idx = tid; idx < TIL*3; idx += 256){
            int e = idx/3, c = idx%3;
            float d = pos[ed[e]*3 + c] - pos[es[e]*3 + c];
            float dm = dsm[c];
            d -= dm * rintf(d/dm);
            dp[e*4 + c] = d;
        }
        __syncthreads();
        for (int idx = tid; idx < TIL*128; idx += 256){
            int e = idx >> 7, j = idx & 127;
            float pre = g_A[ed[e]*HD + j] + g_B[es[e]*HD + j] + bias[j];
            pre += dp[e*4+0]*wp[j] + dp[e*4+1]*wp[128+j] + dp[e*4+2]*wp[256+j];
            m1[idx] = fmaxf(pre, 0.f);
        }
        __syncthreads();
        u64 acc0[16], acc1[16];
        #pragma unroll
        for (int i = 0; i < 16; i++){ acc0[i]=0ull; acc1[i]=0ull; }
        const float* wr0 = &w2t[c0*KP];
        const float* wr1 = &w2t[c1*KP];
        const float* mb  = &m1[r0*128];
        GEMM16(acc0, acc1, mb, wr0, wr1);
        __syncthreads();
        #pragma unroll
        for (int i = 0; i < 16; i++){
            m1[(r0+i)*128 + c0] = fmaxf(hadd2(acc0[i]) + b2[c0], 0.f);
            m1[(r0+i)*128 + c1] = fmaxf(hadd2(acc1[i]) + b2[c1], 0.f);
        }
        __syncthreads();
        #pragma unroll
        for (int q = 0; q < 8; q++){
            int idx = tid + q*256;
            int e = idx >> 5, c = idx & 31;
            if (e < nval){
                float4 val = ((const float4*)m1)[idx];
                red4(&g_agg[ed[e]*HD + c*4], val);
            }
        }
        __syncthreads();
    }
}

// ---------------- upd pass b: u1 = relu(g_u1 + (agg*dinv)@Wa + bias) ----------------
__global__ void __launch_bounds__(256,2) k_upd1b(const float* __restrict__ updW1, int l)
{
    extern __shared__ float sm[];
    float* wT   = sm;                 // 128*KP
    float* bias = wT + 128*KP;        // 128
    float* act  = bias + 128;         // 64*128
    float* dinv = act + TIL*128;      // 64
    const float* W = updW1 + (size_t)l*268*HD + 128*128;
    int tid = threadIdx.x;
    for (int idx = tid; idx < 128*128; idx += 256){
        int k = idx >> 7, jj = idx & 127;
        wT[jj*KP + k] = W[idx];
    }
    if (tid < 128) bias[tid] = g_bias_upd[l*HD + tid];
    __syncthreads();
    int c0 = tid & 63, c1 = c0 + 64, r0 = (tid >> 6)*16;
    for (int tile = blockIdx.x; tile < NT; tile += gridDim.x){
        int base = tile*TIL;
        if (tid < TIL) dinv[tid] = 1.f / fmaxf(g_deg[base + tid], 1.f);
        __syncthreads();
        for (int idx = tid; idx < TIL*128; idx += 256)
            act[idx] = g_agg[base*HD + idx] * dinv[idx >> 7];
        __syncthreads();
        u64 acc0[16], acc1[16];
        #pragma unroll
        for (int i = 0; i < 16; i++){ acc0[i]=0ull; acc1[i]=0ull; }
        const float* wr0 = &wT[c0*KP];
        const float* wr1 = &wT[c1*KP];
        const float* ab  = &act[r0*128];
        GEMM16(acc0, acc1, ab, wr0, wr1);
        #pragma unroll
        for (int i = 0; i < 16; i++){
            int row = base + r0 + i;
            g_u1[row*HD + c0] = fmaxf(g_u1[row*HD + c0] + hadd2(acc0[i]) + bias[c0], 0.f);
            g_u1[row*HD + c1] = fmaxf(g_u1[row*HD + c1] + hadd2(acc1[i]) + bias[c1], 0.f);
        }
        __syncthreads();
    }
}

// ---------------- upd2: z = hn + u1@W2 + b2, write g_h, stats ----------------
__global__ void __launch_bounds__(256,2) k_upd2(const float* __restrict__ updW2,
                                                const float* __restrict__ updb2, int l)
{
    extern __shared__ float sm[];
    float* wT  = sm;                 // 128*KP
    float* b2  = wT + 128*KP;        // 128
    float* mu  = b2 + 128;           // 128
    float* is  = mu + 128;           // 128
    float* act = is + 128;           // 64*128
    const float* W = updW2 + (size_t)l*HD*HD;
    int tid = threadIdx.x;
    for (int idx = tid; idx < 128*128; idx += 256){
        int k = idx >> 7, jj = idx & 127;
        wT[jj*KP + k] = W[idx];
    }
    if (tid < 128){
        b2[tid] = updb2[l*HD + tid];
        mu[tid] = g_mu[tid]; is[tid] = g_is[tid];
    }
    __syncthreads();
    int c0 = tid & 63, c1 = c0 + 64, r0 = (tid >> 6)*16;
    float s1a = 0.f, s2a = 0.f, s1b = 0.f, s2b = 0.f;
    for (int tile = blockIdx.x; tile < NT; tile += gridDim.x){
        int base = tile*TIL;
        for (int idx = tid; idx < TIL*128; idx += 256) act[idx] = g_u1[base*HD + idx];
        __syncthreads();
        u64 acc0[16], acc1[16];
        #pragma unroll
        for (int i = 0; i < 16; i++){ acc0[i]=0ull; acc1[i]=0ull; }
        const float* wr0 = &wT[c0*KP];
        const float* wr1 = &wT[c1*KP];
        const float* ab  = &act[r0*128];
        GEMM16(acc0, acc1, ab, wr0, wr1);
        #pragma unroll
        for (int i = 0; i < 16; i++){
            int row = base + r0 + i;
            float h0 = (g_h[row*HD + c0] - mu[c0])*is[c0];
            float h1 = (g_h[row*HD + c1] - mu[c1])*is[c1];
            float z0 = h0 + hadd2(acc0[i]) + b2[c0];
            float z1 = h1 + hadd2(acc1[i]) + b2[c1];
            g_h[row*HD + c0] = z0;
            g_h[row*HD + c1] = z1;
            if (row < NND){ s1a += z0; s2a += z0*z0; s1b += z1; s2b += z1*z1; }
        }
        __syncthreads();
    }
    atomicAdd(&g_stats[c0], s1a);
    atomicAdd(&g_stats[HD + c0], s2a);
    atomicAdd(&g_stats[c1], s1b);
    atomicAdd(&g_stats[HD + c1], s2b);
}

__global__ void k_hsum(){
    int j = threadIdx.x;
    float s = 0.f;
    for (int node = blockIdx.x; node < NND; node += gridDim.x)
        s += g_h[node*HD + j];
    atomicAdd(&g_hsum[j], s);
}

// ---------------- output head (tile=32, 8 rows x 2 ch per thread) ----------------
__global__ void __launch_bounds__(256,2) k_out(const float* __restrict__ outW1,
                                               const float* __restrict__ outb1,
                                               const float* __restrict__ outW2,
                                               const float* __restrict__ outb2,
                                               const float* __restrict__ pos,
                                               const float* __restrict__ v,
                                               const float* __restrict__ domn,
                                               float* __restrict__ out)
{
    extern __shared__ float sm[];
    float* w1T = sm;                  // 128*KP
    float* b1  = w1T + 128*KP;        // 128
    float* mu  = b1 + 128;            // 128
    float* is  = mu + 128;            // 128
    float* w2o = is + 128;            // 128*12
    float* b2o = w2o + 128*12;        // 16
    float* dnx = b2o + 16;            // 4
    float* hsm = dnx + 4;             // 32*128
    float* o1  = hsm + OTIL*128;      // 32*128
    float* rv9 = o1 + OTIL*128;       // 32*12
    int tid = threadIdx.x;
    for (int idx = tid; idx < 128*128; idx += 256){
        int k = idx >> 7, jj = idx & 127;
        w1T[jj*KP + k] = outW1[idx];
    }
    for (int idx = tid; idx < HD*9; idx += 256){
        int k = idx/9, c = idx%9;
        w2o[k*12 + c] = outW2[idx];
    }
    if (tid < 128){
        b1[tid] = outb1[tid];
        mu[tid] = g_mu[tid]; is[tid] = g_is[tid];
    }
    if (tid < 9) b2o[tid] = outb2[tid];
    if (tid < 3) dnx[tid] = domn[tid];
    __syncthreads();
    int c0 = tid & 63, c1 = c0 + 64, r0 = (tid >> 6)*8;
    for (int tile = blockIdx.x; tile < ONT; tile += gridDim.x){
        int base = tile*OTIL;
        for (int idx = tid; idx < OTIL*128; idx += 256){
            int j = idx & 127;
            hsm[idx] = (g_h[base*HD + idx] - mu[j])*is[j];
        }
        for (int tt = tid; tt < OTIL*9; tt += 256){
            int i = tt/9, c = tt%9; int row = base + i;
            rv9[i*12 + c] = (row < NND) ? ((c < 3) ? pos[row*3 + c] : v[row*6 + c-3]) : 0.f;
        }
        __syncthreads();
        u64 acc0[8], acc1[8];
        #pragma unroll
        for (int i = 0; i < 8; i++){ acc0[i]=0ull; acc1[i]=0ull; }
        const float* wr0 = &w1T[c0*KP];
        const float* wr1 = &w1T[c1*KP];
        const float* ab  = &hsm[r0*128];
        GEMM8(acc0, acc1, ab, wr0, wr1);
        #pragma unroll
        for (int i = 0; i < 8; i++){
            o1[(r0+i)*128 + c0] = fmaxf(hadd2(acc0[i]) + b1[c0], 0.f);
            o1[(r0+i)*128 + c1] = fmaxf(hadd2(acc1[i]) + b1[c1], 0.f);
        }
        __syncthreads();
        for (int tt = tid; tt < OTIL*9; tt += 256){
            int i = tt/9, c = tt%9; int row = base + i;
            if (row < NND){
                float s = b2o[c];
                for (int k = 0; k < HD; k++) s += o1[i*128 + k]*w2o[k*12 + c];
                if (c < 3){
                    float p = 0.001f*s + rv9[i*12 + c];
                    float d = dnx[c];
                    out[row*3 + c] = p - floorf(p/d)*d;
                } else {
                    float sc = (c < 6) ? 0.001f : 0.01f;
                    out[NND*3 + row*6 + (c-3)] = sc*s + rv9[i*12 + c];
                }
            }
        }
        __syncthreads();
    }
}

__global__ void k_macro(const float* __restrict__ W1, const float* __restrict__ b1,
                        const float* __restrict__ W2, const float* __restrict__ b2,
                        float* __restrict__ out)
{
    __shared__ float hm[HD];
    __shared__ float hid[HD];
    int j = threadIdx.x;
    hm[j] = (g_hsum[j]*(1.0f/(float)NND) - g_mu[j])*g_is[j];
    __syncthreads();
    float acc = b1[j];
    for (int k = 0; k < HD; k++) acc += hm[k]*W1[k*HD + j];
    hid[j] = fmaxf(acc, 0.f);
    __syncthreads();
    if (j < 3){
        float s = b2[j];
        for (int k = 0; k < HD; k++) s += hid[k]*W2[k*3 + j];
        out[NND*9 + j] = s;
    }
}

extern "C" void kernel_launch(void* const* d_in, const int* in_sizes, int n_in,
                              void* d_out, int out_size)
{
    const float* v    = (const float*)d_in[0];
    const float* pos  = (const float*)d_in[1];
    const float* r    = (const float*)d_in[2];
    const float* dom  = (const float*)d_in[3];
    const float* t    = (const float*)d_in[4];
    const float* xg   = (const float*)d_in[5];
    const float* domn = (const float*)d_in[6];
    const float* tn   = (const float*)d_in[7];
    const int*   ei   = (const int*)d_in[8];
    const float* embW1=(const float*)d_in[10];
    const float* embb1=(const float*)d_in[11];
    const float* embW2=(const float*)d_in[12];
    const float* embb2=(const float*)d_in[13];
    const float* msgW1=(const float*)d_in[14];
    const float* msgb1=(const float*)d_in[15];
    const float* msgW2=(const float*)d_in[16];
    const float* msgb2=(const float*)d_in[17];
    const float* updW1=(const float*)d_in[18];
    const float* updb1=(const float*)d_in[19];
    const float* updW2=(const float*)d_in[20];
    const float* updb2=(const float*)d_in[21];
    const float* outW1=(const float*)d_in[22];
    const float* outb1=(const float*)d_in[23];
    const float* outW2=(const float*)d_in[24];
    const float* outb2=(const float*)d_in[25];
    const float* macW1=(const float*)d_in[26];
    const float* macb1=(const float*)d_in[27];
    const float* macW2=(const float*)d_in[28];
    const float* macb2=(const float*)d_in[29];
    float* out = (float*)d_out;

    size_t smEmbed = (size_t)(128*KP + 7*128 + 256 + TIL*128 + TIL*8)*4;
    size_t smNode  = (size_t)(128*KP + 6*128 + 3*128 + TIL*128 + TIL*8)*4;
    size_t smEdge  = (size_t)(128*KP + 3*128 + 256 + TIL*128 + TIL*4 + 4 + 2*TIL)*4;
    size_t smU1b   = (size_t)(128*KP + 128 + TIL*128 + TIL)*4;
    size_t smU2    = (size_t)(128*KP + 3*128 + TIL*128)*4;
    size_t smOut   = (size_t)(128*KP + 3*128 + 128*12 + 16 + 4 + 2*OTIL*128 + OTIL*12)*4;
    cudaFuncSetAttribute(k_embed, cudaFuncAttributeMaxDynamicSharedMemorySize, (int)smEmbed);
    cudaFuncSetAttribute(k_node,  cudaFuncAttributeMaxDynamicSharedMemorySize, (int)smNode);
    cudaFuncSetAttribute(k_edge,  cudaFuncAttributeMaxDynamicSharedMemorySize, (int)smEdge);
    cudaFuncSetAttribute(k_upd1b, cudaFuncAttributeMaxDynamicSharedMemorySize, (int)smU1b);
    cudaFuncSetAttribute(k_upd2,  cudaFuncAttributeMaxDynamicSharedMemorySize, (int)smU2);
    cudaFuncSetAttribute(k_out,   cudaFuncAttributeMaxDynamicSharedMemorySize, (int)smOut);

    k_prep<<<1,128>>>(dom, t, xg, domn, tn, embW1, embb1, msgW1, msgb1, updW1, updb1);
    k_zero0<<<64,256>>>();
    k_count<<<256,256>>>(ei);
    k_embed<<<296,256,smEmbed>>>(embW1, embW2, embb2, v, r);
    for (int l = 0; l < NL; l++){
        const float* W1 = msgW1 + (size_t)l*279*HD;
        const float* WU = updW1 + (size_t)l*268*HD;
        k_zeroagg<<<512,256>>>();
        k_node<<<296,256,smNode>>>(W1,            W1, v, r, 0);
        k_node<<<296,256,smNode>>>(W1 + 128*128,  W1, v, r, 1);
        k_edge<<<296,256,smEdge>>>(msgW1, msgW2, msgb2, ei, pos, dom, l);
        k_node<<<296,256,smNode>>>(WU, (const float*)0, v, r, 2);
        k_upd1b<<<296,256,smU1b>>>(updW1, l);
        k_upd2<<<296,256,smU2>>>(updW2, updb2, l);
        k_stats<<<1,128>>>();
    }
    k_hsum<<<296,128>>>();
    k_out<<<296,256,smOut>>>(outW1, outb1, outW2, outb2, pos, v, domn, out);
    k_macro<<<1,128>>>(macW1, macb1, macW2, macb2, out);
}

// round 11
// speedup vs baseline: 1.7896x; 1.1648x over previous
#include <cuda_runtime.h>
#include <cuda_bf16.h>
#include <cstdint>

#define NND 50000
#define NP  50048
#define NED 300000
#define NEP 300032
#define HD 128
#define NL 6
#define KP 132
#define TIL 64
#define NT  (NP/TIL)
#define OTIL 32
#define ONT (NP/OTIL)
#define EMT 128
#define ET2 (NEP/EMT)

__device__ float g_h[NP*HD];
__device__ float g_A[NP*HD];
__device__ float g_B[NP*HD];
__device__ float g_agg[NP*HD];
__device__ float g_u1[NP*HD];
__device__ float g_deg[NP];
__device__ float g_bias_emb[HD];
__device__ float g_bias_msg[NL*HD];
__device__ float g_bias_upd[NL*HD];
__device__ float g_stats[2*HD];
__device__ float g_mu[HD];
__device__ float g_is[HD];
__device__ float g_hsum[HD];

typedef unsigned long long u64;

__device__ __forceinline__ void ffma2(u64 &d, u64 a, u64 b){
    asm("fma.rn.f32x2 %0, %1, %2, %0;" : "+l"(d) : "l"(a), "l"(b));
}
__device__ __forceinline__ float hadd2(u64 a){
    return __uint_as_float((unsigned)a) + __uint_as_float((unsigned)(a>>32));
}
__device__ __forceinline__ void red4(float* p, float4 v){
    asm volatile("red.global.add.v4.f32 [%0], {%1,%2,%3,%4};"
                 :: "l"(p), "f"(v.x), "f"(v.y), "f"(v.z), "f"(v.w) : "memory");
}
__device__ __forceinline__ uint32_t smem_u32(const void* p){
    uint32_t a;
    asm("{ .reg .u64 t; cvta.to.shared.u64 t, %1; cvt.u32.u64 %0, t; }" : "=r"(a) : "l"(p));
    return a;
}
// ---- legacy tensor core ops (PTX ISA sm_80 baseline, valid on sm_103) ----
__device__ __forceinline__ void ldsm4(uint32_t* r, uint32_t addr){
    asm volatile("ldmatrix.sync.aligned.m8n8.x4.shared.b16 {%0,%1,%2,%3}, [%4];"
        : "=r"(r[0]),"=r"(r[1]),"=r"(r[2]),"=r"(r[3]) : "r"(addr));
}
__device__ __forceinline__ void ldsm2(uint32_t* r, uint32_t addr){
    asm volatile("ldmatrix.sync.aligned.m8n8.x2.shared.b16 {%0,%1}, [%2];"
        : "=r"(r[0]),"=r"(r[1]) : "r"(addr));
}
__device__ __forceinline__ void mma16816(float* d, const uint32_t* a, const uint32_t* b){
    asm volatile("mma.sync.aligned.m16n8k16.row.col.f32.bf16.bf16.f32 "
        "{%0,%1,%2,%3}, {%4,%5,%6,%7}, {%8,%9}, {%0,%1,%2,%3};"
        : "+f"(d[0]),"+f"(d[1]),"+f"(d[2]),"+f"(d[3])
        : "r"(a[0]),"r"(a[1]),"r"(a[2]),"r"(a[3]), "r"(b[0]),"r"(b[1]));
}

#define GEMM16(ACC0, ACC1, ACTB, WR0, WR1) \
  _Pragma("unroll 2") \
  for (int kk = 0; kk < 128; kk += 4){ \
    ulonglong2 w0v = *(const ulonglong2*)((WR0) + kk); \
    ulonglong2 w1v = *(const ulonglong2*)((WR1) + kk); \
    _Pragma("unroll") \
    for (int ii = 0; ii < 16; ii++){ \
      ulonglong2 xv = *(const ulonglong2*)((ACTB) + ii*128 + kk); \
      ffma2(ACC0[ii], xv.x, w0v.x); ffma2(ACC0[ii], xv.y, w0v.y); \
      ffma2(ACC1[ii], xv.x, w1v.x); ffma2(ACC1[ii], xv.y, w1v.y); \
    } \
  }
#define GEMM8(ACC0, ACC1, ACTB, WR0, WR1) \
  _Pragma("unroll 2") \
  for (int kk = 0; kk < 128; kk += 4){ \
    ulonglong2 w0v = *(const ulonglong2*)((WR0) + kk); \
    ulonglong2 w1v = *(const ulonglong2*)((WR1) + kk); \
    _Pragma("unroll") \
    for (int ii = 0; ii < 8; ii++){ \
      ulonglong2 xv = *(const ulonglong2*)((ACTB) + ii*128 + kk); \
      ffma2(ACC0[ii], xv.x, w0v.x); ffma2(ACC0[ii], xv.y, w0v.y); \
      ffma2(ACC1[ii], xv.x, w1v.x); ffma2(ACC1[ii], xv.y, w1v.y); \
    } \
  }

__global__ void k_prep(const float* __restrict__ dom, const float* __restrict__ t,
                       const float* __restrict__ xg, const float* __restrict__ domn,
                       const float* __restrict__ tn,
                       const float* __restrict__ embW1, const float* __restrict__ embb1,
                       const float* __restrict__ msgW1, const float* __restrict__ msgb1,
                       const float* __restrict__ updW1, const float* __restrict__ updb1)
{
    __shared__ float gf[12];
    int j = threadIdx.x;
    if (j < 12){
        float val;
        if (j < 3) val = dom[j];
        else if (j == 3) val = t[0];
        else if (j < 8) val = xg[j-4];
        else if (j < 11) val = domn[j-8];
        else val = tn[0];
        gf[j] = val;
    }
    __syncthreads();
    float acc = embb1[j];
    #pragma unroll
    for (int g = 0; g < 12; g++) acc += gf[g]*embW1[(7+g)*HD + j];
    g_bias_emb[j] = acc;
    for (int l = 0; l < NL; l++){
        const float* W = msgW1 + (size_t)l*279*HD;
        float a = msgb1[l*HD + j];
        #pragma unroll
        for (int g = 0; g < 12; g++) a += gf[g]*W[(267+g)*HD + j];
        g_bias_msg[l*HD + j] = a;
        const float* U = updW1 + (size_t)l*268*HD;
        float b = updb1[l*HD + j];
        #pragma unroll
        for (int g = 0; g < 12; g++) b += gf[g]*U[(256+g)*HD + j];
        g_bias_upd[l*HD + j] = b;
    }
}

__global__ void k_zero0(){
    int i = blockIdx.x*blockDim.x + threadIdx.x;
    for (int idx = i; idx < NP; idx += gridDim.x*blockDim.x) g_deg[idx] = 0.f;
    if (i < HD){ g_hsum[i] = 0.f; g_mu[i] = 0.f; g_is[i] = 1.f; }
}

__global__ void k_zeroagg(){
    int i = blockIdx.x*blockDim.x + threadIdx.x;
    float4 z = {0.f,0.f,0.f,0.f};
    for (int idx = i; idx < NP*HD/4; idx += gridDim.x*blockDim.x)
        ((float4*)g_agg)[idx] = z;
    if (i < 2*HD) g_stats[i] = 0.f;
}

__global__ void k_count(const int* __restrict__ ei){
    for (int e = blockIdx.x*blockDim.x + threadIdx.x; e < NED; e += gridDim.x*blockDim.x)
        atomicAdd(&g_deg[ei[NED + e]], 1.0f);
}

__global__ void k_stats(){
    int j = threadIdx.x;
    const float inv_n = 1.0f/(float)NND;
    float mu = g_stats[j]*inv_n;
    float var = fmaxf(g_stats[HD+j]*inv_n - mu*mu, 0.f);
    g_mu[j] = mu;
    g_is[j] = rsqrtf(var + 1e-5f);
}

// ---------------- embedding ----------------
__global__ void __launch_bounds__(256,2) k_embed(const float* __restrict__ embW1,
                                                 const float* __restrict__ embW2,
                                                 const float* __restrict__ embb2,
                                                 const float* __restrict__ v,
                                                 const float* __restrict__ rr)
{
    extern __shared__ float sm[];
    float* w2t = sm;
    float* w1  = w2t + 128*KP;
    float* be  = w1 + 7*128;
    float* b2e = be + 128;
    float* hid = b2e + 128;
    float* rv  = hid + TIL*128;
    int tid = threadIdx.x;
    for (int idx = tid; idx < 128*128; idx += 256){
        int k = idx >> 7, jj = idx & 127;
        w2t[jj*KP + k] = embW2[idx];
    }
    for (int idx = tid; idx < 7*128; idx += 256) w1[idx] = embW1[idx];
    if (tid < 128){ be[tid] = g_bias_emb[tid]; b2e[tid] = embb2[tid]; }
    __syncthreads();
    int c0 = tid & 63, c1 = c0 + 64, r0 = (tid >> 6)*16;
    for (int tile = blockIdx.x; tile < NT; tile += gridDim.x){
        int base = tile*TIL;
        for (int idx = tid; idx < TIL*7; idx += 256){
            int i = idx/7, c = idx%7; int row = base + i;
            rv[i*8+c] = (row < NND) ? ((c==0) ? rr[row] : v[row*6 + c-1]) : 0.f;
        }
        __syncthreads();
        #pragma unroll
        for (int i = 0; i < 16; i++){
            int rr8 = (r0+i)*8;
            float a0 = be[c0] + rv[rr8]*w1[c0];
            float a1 = be[c1] + rv[rr8]*w1[c1];
            #pragma unroll
            for (int c = 0; c < 6; c++){
                float x = rv[rr8+1+c];
                a0 += x*w1[(1+c)*128 + c0];
                a1 += x*w1[(1+c)*128 + c1];
            }
            hid[(r0+i)*128 + c0] = fmaxf(a0, 0.f);
            hid[(r0+i)*128 + c1] = fmaxf(a1, 0.f);
        }
        __syncthreads();
        u64 acc0[16], acc1[16];
        #pragma unroll
        for (int i = 0; i < 16; i++){ acc0[i]=0ull; acc1[i]=0ull; }
        const float* wr0 = &w2t[c0*KP];
        const float* wr1 = &w2t[c1*KP];
        const float* ab  = &hid[r0*128];
        GEMM16(acc0, acc1, ab, wr0, wr1);
        #pragma unroll
        for (int i = 0; i < 16; i++){
            int row = base + r0 + i;
            g_h[row*HD + c0] = fmaxf(hadd2(acc0[i]) + b2e[c0], 0.f);
            g_h[row*HD + c1] = fmaxf(hadd2(acc1[i]) + b2e[c1], 0.f);
        }
        __syncthreads();
    }
}

// ---------------- generic node GEMM: mode 0=A, 1=B, 2=upd-h ----------------
__global__ void __launch_bounds__(256,2) k_node(const float* __restrict__ Wblk,
                                                const float* __restrict__ Waux,
                                                const float* __restrict__ v,
                                                const float* __restrict__ rr,
                                                int mode)
{
    extern __shared__ float sm[];
    float* wT  = sm;
    float* wv  = wT + 128*KP;
    float* wrc = wv + 6*128;
    float* mu  = wrc + 128;
    float* is  = mu + 128;
    float* hsm = is + 128;
    float* rv  = hsm + TIL*128;
    int tid = threadIdx.x;
    for (int idx = tid; idx < 128*128; idx += 256){
        int k = idx >> 7, jj = idx & 127;
        wT[jj*KP + k] = Wblk[idx];
    }
    if (mode < 2){
        for (int idx = tid; idx < 6*128; idx += 256) wv[idx] = Waux[259*128 + idx];
        if (tid < 128) wrc[tid] = Waux[(265+mode)*128 + tid];
    }
    if (tid < 128){ mu[tid] = g_mu[tid]; is[tid] = g_is[tid]; }
    __syncthreads();
    float sgn = (mode==1) ? -1.f : 1.f;
    float* ob = (mode==0) ? g_A : (mode==1) ? g_B : g_u1;
    int c0 = tid & 63, c1 = c0 + 64, r0 = (tid >> 6)*16;
    for (int tile = blockIdx.x; tile < NT; tile += gridDim.x){
        int base = tile*TIL;
        for (int idx = tid; idx < TIL*128; idx += 256){
            int j = idx & 127;
            hsm[idx] = (g_h[base*HD + idx] - mu[j])*is[j];
        }
        if (mode < 2){
            for (int idx = tid; idx < TIL*7; idx += 256){
                int i = idx/7, c = idx%7; int row = base + i;
                rv[i*8+c] = (row < NND) ? ((c==0) ? rr[row] : v[row*6 + c-1]) : 0.f;
            }
        }
        __syncthreads();
        u64 acc0[16], acc1[16];
        #pragma unroll
        for (int i = 0; i < 16; i++){ acc0[i]=0ull; acc1[i]=0ull; }
        const float* wr0 = &wT[c0*KP];
        const float* wr1 = &wT[c1*KP];
        const float* ab  = &hsm[r0*128];
        GEMM16(acc0, acc1, ab, wr0, wr1);
        if (mode < 2){
            #pragma unroll
            for (int i = 0; i < 16; i++){
                int row = base + r0 + i;
                int rr8 = (r0+i)*8;
                float v0 = 0.f, v1 = 0.f;
                #pragma unroll
                for (int c = 0; c < 6; c++){
                    float x = rv[rr8+1+c];
                    v0 += x*wv[c*128 + c0];
                    v1 += x*wv[c*128 + c1];
                }
                float ri = rv[rr8];
                ob[row*HD + c0] = hadd2(acc0[i]) + sgn*v0 + ri*wrc[c0];
                ob[row*HD + c1] = hadd2(acc1[i]) + sgn*v1 + ri*wrc[c1];
            }
        } else {
            #pragma unroll
            for (int i = 0; i < 16; i++){
                int row = base + r0 + i;
                ob[row*HD + c0] = hadd2(acc0[i]);
                ob[row*HD + c1] = hadd2(acc1[i]);
            }
        }
        __syncthreads();
    }
}

// ---------------- edge kernel: mma.sync bf16 hi/lo (4-term exact) ----------------
__global__ void __launch_bounds__(256) k_edge_tc(const float* __restrict__ msgW1,
                                                 const float* __restrict__ msgW2,
                                                 const float* __restrict__ msgb2,
                                                 const int* __restrict__ ei,
                                                 const float* __restrict__ pos,
                                                 const float* __restrict__ dom, int l)
{
    extern __shared__ char smc[];
    char* Bhi = smc;                    // 32768  weights hi [n][k] swizzled
    char* Blo = smc + 32768;            // 32768
    char* Ahi = smc + 65536;            // 32768  activations hi [m][k] swizzled
    char* Alo = smc + 98304;            // 32768
    float* outb = (float*)(smc + 65536);// reuse A region post-MMA (64KB = 128x128 f32)
    float* wp   = (float*)(smc + 131072); // 3*128
    float* bias = wp + 384;             // 128
    float* b2   = bias + 128;           // 128
    float* dsm  = b2 + 128;             // 4
    float* dp   = dsm + 4;              // 128*4
    int* es     = (int*)(dp + 512);     // 128
    int* ed     = es + 128;             // 128

    const float* W1 = msgW1 + (size_t)l*279*HD;
    const float* W2 = msgW2 + (size_t)l*HD*HD;
    int tid = threadIdx.x;
    int wid = tid >> 5, lane = tid & 31;
    uint32_t AhiB = smem_u32(Ahi), AloB = smem_u32(Alo);
    uint32_t BhiB = smem_u32(Bhi), BloB = smem_u32(Blo);

    // stage W2^T -> Bhi/Blo: Bs[n][k] = W2[k][n], 256B rows, 16B-block XOR swizzle
    for (int idx = tid; idx < 128*64; idx += 256){
        int n = idx >> 6, kp = idx & 63;
        float w0 = W2[(2*kp)*128 + n];
        float w1 = W2[(2*kp+1)*128 + n];
        __nv_bfloat16 h0 = __float2bfloat16(w0);
        __nv_bfloat16 h1 = __float2bfloat16(w1);
        __nv_bfloat16 l0 = __float2bfloat16(w0 - __bfloat162float(h0));
        __nv_bfloat16 l1 = __float2bfloat16(w1 - __bfloat162float(h1));
        uint32_t o = (uint32_t)n*256 + ((((kp>>2) ^ (n&7)))<<4) + (kp&3)*4;
        *(unsigned*)(Bhi + o) = (unsigned)__bfloat16_as_ushort(h0) | ((unsigned)__bfloat16_as_ushort(h1) << 16);
        *(unsigned*)(Blo + o) = (unsigned)__bfloat16_as_ushort(l0) | ((unsigned)__bfloat16_as_ushort(l1) << 16);
    }
    for (int idx = tid; idx < 3*128; idx += 256) wp[idx] = W1[256*128 + idx];
    if (tid < 128){
        bias[tid] = g_bias_msg[l*HD + tid];
        b2[tid]   = msgb2[l*HD + tid];
    }
    if (tid < 3) dsm[tid] = dom[tid];
    __syncthreads();

    int m0 = (wid & 3)*32;          // this warp: m-blocks m0, m0+16
    int nh = (wid >> 2)*64;         // n range [nh, nh+64)
    int quad = lane >> 2, tq = lane & 3;

    for (int tile = blockIdx.x; tile < ET2; tile += gridDim.x){
        int base = tile*EMT;
        int nval = NED - base; if (nval > EMT) nval = EMT;
        if (tid < EMT) es[tid] = (tid < nval) ? ei[base + tid] : 0;
        else { int e = tid - EMT; ed[e] = (e < nval) ? ei[NED + base + e] : 0; }
        __syncthreads();
        for (int idx = tid; idx < EMT*3; idx += 256){
            int e = idx/3, c = idx%3;
            float d = pos[ed[e]*3 + c] - pos[es[e]*3 + c];
            float dm = dsm[c];
            d -= dm * rintf(d/dm);
            dp[e*4 + c] = d;
        }
        __syncthreads();
        // fused layer-1 epilogue -> swizzled bf16 hi/lo A tiles
        #pragma unroll 4
        for (int q = 0; q < 32; q++){
            int idx = tid + q*256;
            int e = idx >> 6, jp = idx & 63, j = jp*2;
            int nd = ed[e], ns = es[e];
            float2 av = *(const float2*)(g_A + (size_t)nd*HD + j);
            float2 bv = *(const float2*)(g_B + (size_t)ns*HD + j);
            float d0 = dp[e*4], d1 = dp[e*4+1], d2 = dp[e*4+2];
            float p0 = av.x + bv.x + bias[j]   + d0*wp[j]   + d1*wp[128+j]   + d2*wp[256+j];
            float p1 = av.y + bv.y + bias[j+1] + d0*wp[j+1] + d1*wp[128+j+1] + d2*wp[256+j+1];
            p0 = fmaxf(p0, 0.f); p1 = fmaxf(p1, 0.f);
            __nv_bfloat16 h0 = __float2bfloat16(p0);
            __nv_bfloat16 h1 = __float2bfloat16(p1);
            __nv_bfloat16 l0 = __float2bfloat16(p0 - __bfloat162float(h0));
            __nv_bfloat16 l1 = __float2bfloat16(p1 - __bfloat162float(h1));
            uint32_t o = (uint32_t)e*256 + ((((j>>3) ^ (e&7)))<<4) + (j&7)*2;
            *(unsigned*)(Ahi + o) = (unsigned)__bfloat16_as_ushort(h0) | ((unsigned)__bfloat16_as_ushort(h1) << 16);
            *(unsigned*)(Alo + o) = (unsigned)__bfloat16_as_ushort(l0) | ((unsigned)__bfloat16_as_ushort(l1) << 16);
        }
        __syncthreads();

        float d[2][8][4];
        #pragma unroll
        for (int m = 0; m < 2; m++)
            #pragma unroll
            for (int nf = 0; nf < 8; nf++)
                #pragma unroll
                for (int c = 0; c < 4; c++) d[m][nf][c] = 0.f;

        // A lane address (same row&7 for m0 and m0+16 -> +4096 bytes)
        int rowA = m0 + (lane & 7) + ((lane >> 3) & 1)*8;
        int rowB7 = 0; // computed per nf
        #pragma unroll
        for (int ks = 0; ks < 8; ks++){
            int k0 = ks*16;
            int kbA = k0 + (lane >> 4)*8;
            uint32_t offA = (uint32_t)rowA*256 + ((((kbA>>3) ^ (rowA&7)))<<4);
            uint32_t ah0[4], al0[4], ah1[4], al1[4];
            ldsm4(ah0, AhiB + offA);
            ldsm4(al0, AloB + offA);
            ldsm4(ah1, AhiB + offA + 4096);
            ldsm4(al1, AloB + offA + 4096);
            int kbB = k0 + ((lane >> 3) & 1)*8;
            #pragma unroll
            for (int nf = 0; nf < 8; nf++){
                int rowB = nh + nf*8 + (lane & 7);
                rowB7 = rowB & 7;
                uint32_t offB = (uint32_t)rowB*256 + ((((kbB>>3) ^ rowB7))<<4);
                uint32_t bh[2], bl[2];
                ldsm2(bh, BhiB + offB);
                ldsm2(bl, BloB + offB);
                mma16816(d[0][nf], ah0, bh);
                mma16816(d[0][nf], al0, bh);
                mma16816(d[0][nf], ah0, bl);
                mma16816(d[0][nf], al0, bl);
                mma16816(d[1][nf], ah1, bh);
                mma16816(d[1][nf], al1, bh);
                mma16816(d[1][nf], ah1, bl);
                mma16816(d[1][nf], al1, bl);
            }
        }
        __syncthreads();   // all warps done reading A smem; safe to overwrite as outb

        // writeout: relu(d + b2) -> swizzled outb [128][128] f32 (16B-block XOR)
        #pragma unroll
        for (int m = 0; m < 2; m++){
            int e0 = m0 + m*16 + quad;
            int e1 = e0 + 8;
            #pragma unroll
            for (int nf = 0; nf < 8; nf++){
                int n = nh + nf*8 + 2*tq;
                float2 v0 = { fmaxf(d[m][nf][0] + b2[n], 0.f), fmaxf(d[m][nf][1] + b2[n+1], 0.f) };
                float2 v1 = { fmaxf(d[m][nf][2] + b2[n], 0.f), fmaxf(d[m][nf][3] + b2[n+1], 0.f) };
                *(float2*)(outb + (size_t)e0*128 + ((((n>>2) ^ (e0&7)))<<2) + (n&3)) = v0;
                *(float2*)(outb + (size_t)e1*128 + ((((n>>2) ^ (e1&7)))<<2) + (n&3)) = v1;
            }
        }
        __syncthreads();
        // scatter: vector red4, de-swizzling on read
        #pragma unroll
        for (int q = 0; q < 16; q++){
            int idx = tid + q*256;
            int e = idx >> 5, c = idx & 31;
            if (e < nval){
                float4 val = ((const float4*)outb)[e*32 + (c ^ (e&7))];
                red4(&g_agg[(size_t)ed[e]*HD + c*4], val);
            }
        }
        __syncthreads();
    }
}

// ---------------- upd pass b ----------------
__global__ void __launch_bounds__(256,2) k_upd1b(const float* __restrict__ updW1, int l)
{
    extern __shared__ float sm[];
    float* wT   = sm;
    float* bias = wT + 128*KP;
    float* act  = bias + 128;
    float* dinv = act + TIL*128;
    const float* W = updW1 + (size_t)l*268*HD + 128*128;
    int tid = threadIdx.x;
    for (int idx = tid; idx < 128*128; idx += 256){
        int k = idx >> 7, jj = idx & 127;
        wT[jj*KP + k] = W[idx];
    }
    if (tid < 128) bias[tid] = g_bias_upd[l*HD + tid];
    __syncthreads();
    int c0 = tid & 63, c1 = c0 + 64, r0 = (tid >> 6)*16;
    for (int tile = blockIdx.x; tile < NT; tile += gridDim.x){
        int base = tile*TIL;
        if (tid < TIL) dinv[tid] = 1.f / fmaxf(g_deg[base + tid], 1.f);
        __syncthreads();
        for (int idx = tid; idx < TIL*128; idx += 256)
            act[idx] = g_agg[base*HD + idx] * dinv[idx >> 7];
        __syncthreads();
        u64 acc0[16], acc1[16];
        #pragma unroll
        for (int i = 0; i < 16; i++){ acc0[i]=0ull; acc1[i]=0ull; }
        const float* wr0 = &wT[c0*KP];
        const float* wr1 = &wT[c1*KP];
        const float* ab  = &act[r0*128];
        GEMM16(acc0, acc1, ab, wr0, wr1);
        #pragma unroll
        for (int i = 0; i < 16; i++){
            int row = base + r0 + i;
            g_u1[row*HD + c0] = fmaxf(g_u1[row*HD + c0] + hadd2(acc0[i]) + bias[c0], 0.f);
            g_u1[row*HD + c1] = fmaxf(g_u1[row*HD + c1] + hadd2(acc1[i]) + bias[c1], 0.f);
        }
        __syncthreads();
    }
}

// ---------------- upd2 ----------------
__global__ void __launch_bounds__(256,2) k_upd2(const float* __restrict__ updW2,
                                                const float* __restrict__ updb2, int l)
{
    extern __shared__ float sm[];
    float* wT  = sm;
    float* b2  = wT + 128*KP;
    float* mu  = b2 + 128;
    float* is  = mu + 128;
    float* act = is + 128;
    const float* W = updW2 + (size_t)l*HD*HD;
    int tid = threadIdx.x;
    for (int idx = tid; idx < 128*128; idx += 256){
        int k = idx >> 7, jj = idx & 127;
        wT[jj*KP + k] = W[idx];
    }
    if (tid < 128){
        b2[tid] = updb2[l*HD + tid];
        mu[tid] = g_mu[tid]; is[tid] = g_is[tid];
    }
    __syncthreads();
    int c0 = tid & 63, c1 = c0 + 64, r0 = (tid >> 6)*16;
    float s1a = 0.f, s2a = 0.f, s1b = 0.f, s2b = 0.f;
    for (int tile = blockIdx.x; tile < NT; tile += gridDim.x){
        int base = tile*TIL;
        for (int idx = tid; idx < TIL*128; idx += 256) act[idx] = g_u1[base*HD + idx];
        __syncthreads();
        u64 acc0[16], acc1[16];
        #pragma unroll
        for (int i = 0; i < 16; i++){ acc0[i]=0ull; acc1[i]=0ull; }
        const float* wr0 = &wT[c0*KP];
        const float* wr1 = &wT[c1*KP];
        const float* ab  = &act[r0*128];
        GEMM16(acc0, acc1, ab, wr0, wr1);
        #pragma unroll
        for (int i = 0; i < 16; i++){
            int row = base + r0 + i;
            float h0 = (g_h[row*HD + c0] - mu[c0])*is[c0];
            float h1 = (g_h[row*HD + c1] - mu[c1])*is[c1];
            float z0 = h0 + hadd2(acc0[i]) + b2[c0];
            float z1 = h1 + hadd2(acc1[i]) + b2[c1];
            g_h[row*HD + c0] = z0;
            g_h[row*HD + c1] = z1;
            if (row < NND){ s1a += z0; s2a += z0*z0; s1b += z1; s2b += z1*z1; }
        }
        __syncthreads();
    }
    atomicAdd(&g_stats[c0], s1a);
    atomicAdd(&g_stats[HD + c0], s2a);
    atomicAdd(&g_stats[c1], s1b);
    atomicAdd(&g_stats[HD + c1], s2b);
}

__global__ void k_hsum(){
    int j = threadIdx.x;
    float s = 0.f;
    for (int node = blockIdx.x; node < NND; node += gridDim.x)
        s += g_h[node*HD + j];
    atomicAdd(&g_hsum[j], s);
}

// ---------------- output head ----------------
__global__ void __launch_bounds__(256,2) k_out(const float* __restrict__ outW1,
                                               const float* __restrict__ outb1,
                                               const float* __restrict__ outW2,
                                               const float* __restrict__ outb2,
                                               const float* __restrict__ pos,
                                               const float* __restrict__ v,
                                               const float* __restrict__ domn,
                                               float* __restrict__ out)
{
    extern __shared__ float sm[];
    float* w1T = sm;
    float* b1  = w1T + 128*KP;
    float* mu  = b1 + 128;
    float* is  = mu + 128;
    float* w2o = is + 128;
    float* b2o = w2o + 128*12;
    float* dnx = b2o + 16;
    float* hsm = dnx + 4;
    float* o1  = hsm + OTIL*128;
    float* rv9 = o1 + OTIL*128;
    int tid = threadIdx.x;
    for (int idx = tid; idx < 128*128; idx += 256){
        int k = idx >> 7, jj = idx & 127;
        w1T[jj*KP + k] = outW1[idx];
    }
    for (int idx = tid; idx < HD*9; idx += 256){
        int k = idx/9, c = idx%9;
        w2o[k*12 + c] = outW2[idx];
    }
    if (tid < 128){
        b1[tid] = outb1[tid];
        mu[tid] = g_mu[tid]; is[tid] = g_is[tid];
    }
    if (tid < 9) b2o[tid] = outb2[tid];
    if (tid < 3) dnx[tid] = domn[tid];
    __syncthreads();
    int c0 = tid & 63, c1 = c0 + 64, r0 = (tid >> 6)*8;
    for (int tile = blockIdx.x; tile < ONT; tile += gridDim.x){
        int base = tile*OTIL;
        for (int idx = tid; idx < OTIL*128; idx += 256){
            int j = idx & 127;
            hsm[idx] = (g_h[base*HD + idx] - mu[j])*is[j];
        }
        for (int tt = tid; tt < OTIL*9; tt += 256){
            int i = tt/9, c = tt%9; int row = base + i;
            rv9[i*12 + c] = (row < NND) ? ((c < 3) ? pos[row*3 + c] : v[row*6 + c-3]) : 0.f;
        }
        __syncthreads();
        u64 acc0[8], acc1[8];
        #pragma unroll
        for (int i = 0; i < 8; i++){ acc0[i]=0ull; acc1[i]=0ull; }
        const float* wr0 = &w1T[c0*KP];
        const float* wr1 = &w1T[c1*KP];
        const float* ab  = &hsm[r0*128];
        GEMM8(acc0, acc1, ab, wr0, wr1);
        #pragma unroll
        for (int i = 0; i < 8; i++){
            o1[(r0+i)*128 + c0] = fmaxf(hadd2(acc0[i]) + b1[c0], 0.f);
            o1[(r0+i)*128 + c1] = fmaxf(hadd2(acc1[i]) + b1[c1], 0.f);
        }
        __syncthreads();
        for (int tt = tid; tt < OTIL*9; tt += 256){
            int i = tt/9, c = tt%9; int row = base + i;
            if (row < NND){
                float s = b2o[c];
                for (int k = 0; k < HD; k++) s += o1[i*128 + k]*w2o[k*12 + c];
                if (c < 3){
                    float p = 0.001f*s + rv9[i*12 + c];
                    float d = dnx[c];
                    out[row*3 + c] = p - floorf(p/d)*d;
                } else {
                    float sc = (c < 6) ? 0.001f : 0.01f;
                    out[NND*3 + row*6 + (c-3)] = sc*s + rv9[i*12 + c];
                }
            }
        }
        __syncthreads();
    }
}

__global__ void k_macro(const float* __restrict__ W1, const float* __restrict__ b1,
                        const float* __restrict__ W2, const float* __restrict__ b2,
                        float* __restrict__ out)
{
    __shared__ float hm[HD];
    __shared__ float hid[HD];
    int j = threadIdx.x;
    hm[j] = (g_hsum[j]*(1.0f/(float)NND) - g_mu[j])*g_is[j];
    __syncthreads();
    float acc = b1[j];
    for (int k = 0; k < HD; k++) acc += hm[k]*W1[k*HD + j];
    hid[j] = fmaxf(acc, 0.f);
    __syncthreads();
    if (j < 3){
        float s = b2[j];
        for (int k = 0; k < HD; k++) s += hid[k]*W2[k*3 + j];
        out[NND*9 + j] = s;
    }
}

extern "C" void kernel_launch(void* const* d_in, const int* in_sizes, int n_in,
                              void* d_out, int out_size)
{
    const float* v    = (const float*)d_in[0];
    const float* pos  = (const float*)d_in[1];
    const float* r    = (const float*)d_in[2];
    const float* dom  = (const float*)d_in[3];
    const float* t    = (const float*)d_in[4];
    const float* xg   = (const float*)d_in[5];
    const float* domn = (const float*)d_in[6];
    const float* tn   = (const float*)d_in[7];
    const int*   ei   = (const int*)d_in[8];
    const float* embW1=(const float*)d_in[10];
    const float* embb1=(const float*)d_in[11];
    const float* embW2=(const float*)d_in[12];
    const float* embb2=(const float*)d_in[13];
    const float* msgW1=(const float*)d_in[14];
    const float* msgb1=(const float*)d_in[15];
    const float* msgW2=(const float*)d_in[16];
    const float* msgb2=(const float*)d_in[17];
    const float* updW1=(const float*)d_in[18];
    const float* updb1=(const float*)d_in[19];
    const float* updW2=(const float*)d_in[20];
    const float* updb2=(const float*)d_in[21];
    const float* outW1=(const float*)d_in[22];
    const float* outb1=(const float*)d_in[23];
    const float* outW2=(const float*)d_in[24];
    const float* outb2=(const float*)d_in[25];
    const float* macW1=(const float*)d_in[26];
    const float* macb1=(const float*)d_in[27];
    const float* macW2=(const float*)d_in[28];
    const float* macb2=(const float*)d_in[29];
    float* out = (float*)d_out;

    size_t smEmbed = (size_t)(128*KP + 7*128 + 256 + TIL*128 + TIL*8)*4;
    size_t smNode  = (size_t)(128*KP + 6*128 + 3*128 + TIL*128 + TIL*8)*4;
    size_t smEdge  = 131072 + (size_t)(384 + 128 + 128 + 4 + 512)*4 + 1024 + 64;
    size_t smU1b   = (size_t)(128*KP + 128 + TIL*128 + TIL)*4;
    size_t smU2    = (size_t)(128*KP + 3*128 + TIL*128)*4;
    size_t smOut   = (size_t)(128*KP + 3*128 + 128*12 + 16 + 4 + 2*OTIL*128 + OTIL*12)*4;
    cudaFuncSetAttribute(k_embed, cudaFuncAttributeMaxDynamicSharedMemorySize, (int)smEmbed);
    cudaFuncSetAttribute(k_node,  cudaFuncAttributeMaxDynamicSharedMemorySize, (int)smNode);
    cudaFuncSetAttribute(k_edge_tc, cudaFuncAttributeMaxDynamicSharedMemorySize, (int)smEdge);
    cudaFuncSetAttribute(k_upd1b, cudaFuncAttributeMaxDynamicSharedMemorySize, (int)smU1b);
    cudaFuncSetAttribute(k_upd2,  cudaFuncAttributeMaxDynamicSharedMemorySize, (int)smU2);
    cudaFuncSetAttribute(k_out,   cudaFuncAttributeMaxDynamicSharedMemorySize, (int)smOut);

    k_prep<<<1,128>>>(dom, t, xg, domn, tn, embW1, embb1, msgW1, msgb1, updW1, updb1);
    k_zero0<<<64,256>>>();
    k_count<<<256,256>>>(ei);
    k_embed<<<296,256,smEmbed>>>(embW1, embW2, embb2, v, r);
    for (int l = 0; l < NL; l++){
        const float* W1 = msgW1 + (size_t)l*279*HD;
        const float* WU = updW1 + (size_t)l*268*HD;
        k_zeroagg<<<512,256>>>();
        k_node<<<296,256,smNode>>>(W1,            W1, v, r, 0);
        k_node<<<296,256,smNode>>>(W1 + 128*128,  W1, v, r, 1);
        k_edge_tc<<<148,256,smEdge>>>(msgW1, msgW2, msgb2, ei, pos, dom, l);
        k_node<<<296,256,smNode>>>(WU, (const float*)0, v, r, 2);
        k_upd1b<<<296,256,smU1b>>>(updW1, l);
        k_upd2<<<296,256,smU2>>>(updW2, updb2, l);
        k_stats<<<1,128>>>();
    }
    k_hsum<<<296,128>>>();
    k_out<<<296,256,smOut>>>(outW1, outb1, outW2, outb2, pos, v, domn, out);
    k_macro<<<1,128>>>(macW1, macb1, macW2, macb2, out);
}

// round 12
// speedup vs baseline: 2.3303x; 1.3022x over previous
#include <cuda_runtime.h>
#include <cuda_bf16.h>
#include <cstdint>

#define NND 50000
#define NP  50048
#define NED 300000
#define NEP 300032
#define HD 128
#define NL 6
#define KP 132
#define TIL 64
#define NT  (NP/TIL)
#define NTT (NP/128)
#define OTIL 32
#define ONT (NP/OTIL)
#define EMT 128
#define ET2 (NEP/EMT)

__device__ float g_h[NP*HD];
__device__ float g_A[NP*HD];
__device__ float g_B[NP*HD];
__device__ float g_agg[NP*HD];
__device__ float g_u1[NP*HD];
__device__ float g_deg[NP];
__device__ float g_bias_emb[HD];
__device__ float g_bias_msg[NL*HD];
__device__ float g_bias_upd[NL*HD];
__device__ float g_stats[2*HD];
__device__ float g_mu[HD];
__device__ float g_is[HD];
__device__ float g_hsum[HD];

typedef unsigned long long u64;

__device__ __forceinline__ void ffma2(u64 &d, u64 a, u64 b){
    asm("fma.rn.f32x2 %0, %1, %2, %0;" : "+l"(d) : "l"(a), "l"(b));
}
__device__ __forceinline__ float hadd2(u64 a){
    return __uint_as_float((unsigned)a) + __uint_as_float((unsigned)(a>>32));
}
__device__ __forceinline__ void red4(float* p, float4 v){
    asm volatile("red.global.add.v4.f32 [%0], {%1,%2,%3,%4};"
                 :: "l"(p), "f"(v.x), "f"(v.y), "f"(v.z), "f"(v.w) : "memory");
}
__device__ __forceinline__ uint32_t smem_u32(const void* p){
    uint32_t a;
    asm("{ .reg .u64 t; cvta.to.shared.u64 t, %1; cvt.u32.u64 %0, t; }" : "=r"(a) : "l"(p));
    return a;
}
__device__ __forceinline__ void ldsm4(uint32_t* r, uint32_t addr){
    asm volatile("ldmatrix.sync.aligned.m8n8.x4.shared.b16 {%0,%1,%2,%3}, [%4];"
        : "=r"(r[0]),"=r"(r[1]),"=r"(r[2]),"=r"(r[3]) : "r"(addr));
}
__device__ __forceinline__ void ldsm2(uint32_t* r, uint32_t addr){
    asm volatile("ldmatrix.sync.aligned.m8n8.x2.shared.b16 {%0,%1}, [%2];"
        : "=r"(r[0]),"=r"(r[1]) : "r"(addr));
}
__device__ __forceinline__ void mma16816(float* d, const uint32_t* a, const uint32_t* b){
    asm volatile("mma.sync.aligned.m16n8k16.row.col.f32.bf16.bf16.f32 "
        "{%0,%1,%2,%3}, {%4,%5,%6,%7}, {%8,%9}, {%0,%1,%2,%3};"
        : "+f"(d[0]),"+f"(d[1]),"+f"(d[2]),"+f"(d[3])
        : "r"(a[0]),"r"(a[1]),"r"(a[2]),"r"(a[3]), "r"(b[0]),"r"(b[1]));
}
__device__ __forceinline__ void hilo(float p0, float p1, unsigned &hi, unsigned &lo){
    __nv_bfloat16 h0=__float2bfloat16(p0), h1=__float2bfloat16(p1);
    __nv_bfloat16 l0=__float2bfloat16(p0-__bfloat162float(h0));
    __nv_bfloat16 l1=__float2bfloat16(p1-__bfloat162float(h1));
    hi = (unsigned)__bfloat16_as_ushort(h0) | ((unsigned)__bfloat16_as_ushort(h1)<<16);
    lo = (unsigned)__bfloat16_as_ushort(l0) | ((unsigned)__bfloat16_as_ushort(l1)<<16);
}

#define GEMM16(ACC0, ACC1, ACTB, WR0, WR1) \
  _Pragma("unroll 2") \
  for (int kk = 0; kk < 128; kk += 4){ \
    ulonglong2 w0v = *(const ulonglong2*)((WR0) + kk); \
    ulonglong2 w1v = *(const ulonglong2*)((WR1) + kk); \
    _Pragma("unroll") \
    for (int ii = 0; ii < 16; ii++){ \
      ulonglong2 xv = *(const ulonglong2*)((ACTB) + ii*128 + kk); \
      ffma2(ACC0[ii], xv.x, w0v.x); ffma2(ACC0[ii], xv.y, w0v.y); \
      ffma2(ACC1[ii], xv.x, w1v.x); ffma2(ACC1[ii], xv.y, w1v.y); \
    } \
  }
#define GEMM8(ACC0, ACC1, ACTB, WR0, WR1) \
  _Pragma("unroll 2") \
  for (int kk = 0; kk < 128; kk += 4){ \
    ulonglong2 w0v = *(const ulonglong2*)((WR0) + kk); \
    ulonglong2 w1v = *(const ulonglong2*)((WR1) + kk); \
    _Pragma("unroll") \
    for (int ii = 0; ii < 8; ii++){ \
      ulonglong2 xv = *(const ulonglong2*)((ACTB) + ii*128 + kk); \
      ffma2(ACC0[ii], xv.x, w0v.x); ffma2(ACC0[ii], xv.y, w0v.y); \
      ffma2(ACC1[ii], xv.x, w1v.x); ffma2(ACC1[ii], xv.y, w1v.y); \
    } \
  }

// stage a 128x128 weight block W[k][n] -> smem [n][k] hi/lo, 256B rows, XOR swizzle
#define STAGEW(W, WHI, WLO) \
  for (int idx = tid; idx < 128*64; idx += 256){ \
    int n = idx >> 6, kp = idx & 63; \
    uint32_t o = (uint32_t)n*256 + ((((kp>>2) ^ (n&7)))<<4) + (kp&3)*4; \
    unsigned hi, lo; \
    hilo((W)[(2*kp)*128 + n], (W)[(2*kp+1)*128 + n], hi, lo); \
    *(unsigned*)((WHI) + o) = hi; \
    *(unsigned*)((WLO) + o) = lo; \
  }

__global__ void k_prep(const float* __restrict__ dom, const float* __restrict__ t,
                       const float* __restrict__ xg, const float* __restrict__ domn,
                       const float* __restrict__ tn,
                       const float* __restrict__ embW1, const float* __restrict__ embb1,
                       const float* __restrict__ msgW1, const float* __restrict__ msgb1,
                       const float* __restrict__ updW1, const float* __restrict__ updb1)
{
    __shared__ float gf[12];
    int j = threadIdx.x;
    if (j < 12){
        float val;
        if (j < 3) val = dom[j];
        else if (j == 3) val = t[0];
        else if (j < 8) val = xg[j-4];
        else if (j < 11) val = domn[j-8];
        else val = tn[0];
        gf[j] = val;
    }
    __syncthreads();
    float acc = embb1[j];
    #pragma unroll
    for (int g = 0; g < 12; g++) acc += gf[g]*embW1[(7+g)*HD + j];
    g_bias_emb[j] = acc;
    for (int l = 0; l < NL; l++){
        const float* W = msgW1 + (size_t)l*279*HD;
        float a = msgb1[l*HD + j];
        #pragma unroll
        for (int g = 0; g < 12; g++) a += gf[g]*W[(267+g)*HD + j];
        g_bias_msg[l*HD + j] = a;
        const float* U = updW1 + (size_t)l*268*HD;
        float b = updb1[l*HD + j];
        #pragma unroll
        for (int g = 0; g < 12; g++) b += gf[g]*U[(256+g)*HD + j];
        g_bias_upd[l*HD + j] = b;
    }
}

__global__ void k_zero0(){
    int i = blockIdx.x*blockDim.x + threadIdx.x;
    for (int idx = i; idx < NP; idx += gridDim.x*blockDim.x) g_deg[idx] = 0.f;
    if (i < HD){ g_hsum[i] = 0.f; g_mu[i] = 0.f; g_is[i] = 1.f; }
    if (i < 2*HD) g_stats[i] = 0.f;
}

__global__ void k_count(const int* __restrict__ ei){
    for (int e = blockIdx.x*blockDim.x + threadIdx.x; e < NED; e += gridDim.x*blockDim.x)
        atomicAdd(&g_deg[ei[NED + e]], 1.0f);
}

__global__ void k_stats(){
    int j = threadIdx.x;
    const float inv_n = 1.0f/(float)NND;
    float mu = g_stats[j]*inv_n;
    float var = fmaxf(g_stats[HD+j]*inv_n - mu*mu, 0.f);
    g_mu[j] = mu;
    g_is[j] = rsqrtf(var + 1e-5f);
    g_stats[j] = 0.f; g_stats[HD+j] = 0.f;
}

// ---------------- embedding (scalar FFMA2) ----------------
__global__ void __launch_bounds__(256,2) k_embed(const float* __restrict__ embW1,
                                                 const float* __restrict__ embW2,
                                                 const float* __restrict__ embb2,
                                                 const float* __restrict__ v,
                                                 const float* __restrict__ rr)
{
    extern __shared__ float sm[];
    float* w2t = sm;
    float* w1  = w2t + 128*KP;
    float* be  = w1 + 7*128;
    float* b2e = be + 128;
    float* hid = b2e + 128;
    float* rv  = hid + TIL*128;
    int tid = threadIdx.x;
    for (int idx = tid; idx < 128*128; idx += 256){
        int k = idx >> 7, jj = idx & 127;
        w2t[jj*KP + k] = embW2[idx];
    }
    for (int idx = tid; idx < 7*128; idx += 256) w1[idx] = embW1[idx];
    if (tid < 128){ be[tid] = g_bias_emb[tid]; b2e[tid] = embb2[tid]; }
    __syncthreads();
    int c0 = tid & 63, c1 = c0 + 64, r0 = (tid >> 6)*16;
    for (int tile = blockIdx.x; tile < NT; tile += gridDim.x){
        int base = tile*TIL;
        for (int idx = tid; idx < TIL*7; idx += 256){
            int i = idx/7, c = idx%7; int row = base + i;
            rv[i*8+c] = (row < NND) ? ((c==0) ? rr[row] : v[row*6 + c-1]) : 0.f;
        }
        __syncthreads();
        #pragma unroll
        for (int i = 0; i < 16; i++){
            int rr8 = (r0+i)*8;
            float a0 = be[c0] + rv[rr8]*w1[c0];
            float a1 = be[c1] + rv[rr8]*w1[c1];
            #pragma unroll
            for (int c = 0; c < 6; c++){
                float x = rv[rr8+1+c];
                a0 += x*w1[(1+c)*128 + c0];
                a1 += x*w1[(1+c)*128 + c1];
            }
            hid[(r0+i)*128 + c0] = fmaxf(a0, 0.f);
            hid[(r0+i)*128 + c1] = fmaxf(a1, 0.f);
        }
        __syncthreads();
        u64 acc0[16], acc1[16];
        #pragma unroll
        for (int i = 0; i < 16; i++){ acc0[i]=0ull; acc1[i]=0ull; }
        const float* wr0 = &w2t[c0*KP];
        const float* wr1 = &w2t[c1*KP];
        const float* ab  = &hid[r0*128];
        GEMM16(acc0, acc1, ab, wr0, wr1);
        #pragma unroll
        for (int i = 0; i < 16; i++){
            int row = base + r0 + i;
            g_h[row*HD + c0] = fmaxf(hadd2(acc0[i]) + b2e[c0], 0.f);
            g_h[row*HD + c1] = fmaxf(hadd2(acc1[i]) + b2e[c1], 0.f);
        }
        __syncthreads();
    }
}

// ---------------- node A+B fused tensor GEMM + agg zero ----------------
__global__ void __launch_bounds__(256,1) k_nAB(const float* __restrict__ msgW1,
                                               const float* __restrict__ v,
                                               const float* __restrict__ rr, int l)
{
    extern __shared__ char smc[];
    char* WdHi = smc;
    char* WdLo = smc + 32768;
    char* WsHi = smc + 65536;
    char* WsLo = smc + 98304;
    char* AHi  = smc + 131072;
    char* ALo  = smc + 163840;
    float* wv  = (float*)(smc + 196608);
    float* wrA = wv + 768;
    float* wrB = wrA + 128;
    float* mu  = wrB + 128;
    float* is  = mu + 128;
    float* rv  = is + 128;       // 128*8
    const float* W1 = msgW1 + (size_t)l*279*HD;
    int tid = threadIdx.x, wid = tid>>5, lane = tid&31;
    STAGEW(W1, WdHi, WdLo);
    STAGEW(W1 + 128*128, WsHi, WsLo);
    for (int idx = tid; idx < 768; idx += 256) wv[idx] = W1[259*128 + idx];
    if (tid < 128){
        wrA[tid] = W1[265*128+tid]; wrB[tid] = W1[266*128+tid];
        mu[tid] = g_mu[tid]; is[tid] = g_is[tid];
    }
    __syncthreads();
    int m0 = (wid&3)*32, nh = (wid>>2)*64, quad = lane>>2, tq = lane&3;
    uint32_t AHiB = smem_u32(AHi), ALoB = smem_u32(ALo);
    uint32_t WdHiB = smem_u32(WdHi), WdLoB = smem_u32(WdLo);
    uint32_t WsHiB = smem_u32(WsHi), WsLoB = smem_u32(WsLo);
    for (int tile = blockIdx.x; tile < NTT; tile += gridDim.x){
        int base = tile*128;
        float4 z4 = {0.f,0.f,0.f,0.f};
        #pragma unroll
        for (int q = 0; q < 16; q++)
            ((float4*)(g_agg + (size_t)base*128))[tid + q*256] = z4;
        for (int idx = tid; idx < 128*7; idx += 256){
            int i = idx/7, c = idx%7; int row = base+i;
            rv[i*8+c] = (row<NND) ? ((c==0)?rr[row]:v[row*6+c-1]) : 0.f;
        }
        #pragma unroll 4
        for (int q = 0; q < 32; q++){
            int idx = tid + q*256;
            int e = idx>>6, jp = idx&63, j = jp*2;
            float2 hv = *(const float2*)(g_h + (size_t)(base+e)*128 + j);
            float p0 = (hv.x - mu[j])*is[j], p1 = (hv.y - mu[j+1])*is[j+1];
            unsigned hi, lo; hilo(p0, p1, hi, lo);
            uint32_t o = (uint32_t)e*256 + ((((j>>3) ^ (e&7)))<<4) + (j&7)*2;
            *(unsigned*)(AHi + o) = hi;
            *(unsigned*)(ALo + o) = lo;
        }
        __syncthreads();
        float dA[2][8][4], dB[2][8][4];
        #pragma unroll
        for (int m = 0; m < 2; m++)
            #pragma unroll
            for (int nf = 0; nf < 8; nf++)
                #pragma unroll
                for (int c = 0; c < 4; c++){ dA[m][nf][c]=0.f; dB[m][nf][c]=0.f; }
        int rowA = m0 + (lane & 7) + ((lane >> 3) & 1)*8;
        #pragma unroll
        for (int ks = 0; ks < 8; ks++){
            int k0 = ks*16;
            int kbA = k0 + (lane >> 4)*8;
            uint32_t offA = (uint32_t)rowA*256 + ((((kbA>>3) ^ (rowA&7)))<<4);
            uint32_t ah0[4], al0[4], ah1[4], al1[4];
            ldsm4(ah0, AHiB + offA);
            ldsm4(al0, ALoB + offA);
            ldsm4(ah1, AHiB + offA + 4096);
            ldsm4(al1, ALoB + offA + 4096);
            int kbB = k0 + ((lane >> 3) & 1)*8;
            #pragma unroll
            for (int nf = 0; nf < 8; nf++){
                int rowB = nh + nf*8 + (lane & 7);
                uint32_t offB = (uint32_t)rowB*256 + ((((kbB>>3) ^ (rowB&7)))<<4);
                uint32_t dh[2], dl[2], sh[2], sl[2];
                ldsm2(dh, WdHiB + offB);
                ldsm2(dl, WdLoB + offB);
                ldsm2(sh, WsHiB + offB);
                ldsm2(sl, WsLoB + offB);
                mma16816(dA[0][nf], ah0, dh); mma16816(dA[0][nf], al0, dh); mma16816(dA[0][nf], ah0, dl);
                mma16816(dA[1][nf], ah1, dh); mma16816(dA[1][nf], al1, dh); mma16816(dA[1][nf], ah1, dl);
                mma16816(dB[0][nf], ah0, sh); mma16816(dB[0][nf], al0, sh); mma16816(dB[0][nf], ah0, sl);
                mma16816(dB[1][nf], ah1, sh); mma16816(dB[1][nf], al1, sh); mma16816(dB[1][nf], ah1, sl);
            }
        }
        #pragma unroll
        for (int m = 0; m < 2; m++){
            int e0 = m0 + m*16 + quad, e1 = e0 + 8;
            const float* rv0 = &rv[e0*8];
            const float* rv1 = &rv[e1*8];
            #pragma unroll
            for (int nf = 0; nf < 8; nf++){
                int n = nh + nf*8 + 2*tq;
                float va00=0.f, va01=0.f, va10=0.f, va11=0.f;
                #pragma unroll
                for (int c = 0; c < 6; c++){
                    float w0 = wv[c*128+n], w1 = wv[c*128+n+1];
                    va00 += rv0[1+c]*w0; va01 += rv0[1+c]*w1;
                    va10 += rv1[1+c]*w0; va11 += rv1[1+c]*w1;
                }
                float r0 = rv0[0], r1 = rv1[0];
                float2 a0 = { dA[m][nf][0]+va00+r0*wrA[n], dA[m][nf][1]+va01+r0*wrA[n+1] };
                float2 a1 = { dA[m][nf][2]+va10+r1*wrA[n], dA[m][nf][3]+va11+r1*wrA[n+1] };
                float2 b0 = { dB[m][nf][0]-va00+r0*wrB[n], dB[m][nf][1]-va01+r0*wrB[n+1] };
                float2 b1 = { dB[m][nf][2]-va10+r1*wrB[n], dB[m][nf][3]-va11+r1*wrB[n+1] };
                *(float2*)(g_A+(size_t)(base+e0)*128+n) = a0;
                *(float2*)(g_A+(size_t)(base+e1)*128+n) = a1;
                *(float2*)(g_B+(size_t)(base+e0)*128+n) = b0;
                *(float2*)(g_B+(size_t)(base+e1)*128+n) = b1;
            }
        }
        __syncthreads();
    }
}

// ---------------- edge kernel: mma.sync bf16 hi/lo (3-term) ----------------
__global__ void __launch_bounds__(256) k_edge_tc(const float* __restrict__ msgW1,
                                                 const float* __restrict__ msgW2,
                                                 const float* __restrict__ msgb2,
                                                 const int* __restrict__ ei,
                                                 const float* __restrict__ pos,
                                                 const float* __restrict__ dom, int l)
{
    extern __shared__ char smc[];
    char* Bhi = smc;
    char* Blo = smc + 32768;
    char* Ahi = smc + 65536;
    char* Alo = smc + 98304;
    float* outb = (float*)(smc + 65536);
    float* wp   = (float*)(smc + 131072);
    float* bias = wp + 384;
    float* b2   = bias + 128;
    float* dsm  = b2 + 128;
    float* dp   = dsm + 4;
    int* es     = (int*)(dp + 512);
    int* ed     = es + 128;

    const float* W1 = msgW1 + (size_t)l*279*HD;
    const float* W2 = msgW2 + (size_t)l*HD*HD;
    int tid = threadIdx.x;
    int wid = tid >> 5, lane = tid & 31;
    uint32_t AhiB = smem_u32(Ahi), AloB = smem_u32(Alo);
    uint32_t BhiB = smem_u32(Bhi), BloB = smem_u32(Blo);

    STAGEW(W2, Bhi, Blo);
    for (int idx = tid; idx < 3*128; idx += 256) wp[idx] = W1[256*128 + idx];
    if (tid < 128){
        bias[tid] = g_bias_msg[l*HD + tid];
        b2[tid]   = msgb2[l*HD + tid];
    }
    if (tid < 3) dsm[tid] = dom[tid];
    __syncthreads();

    int m0 = (wid & 3)*32;
    int nh = (wid >> 2)*64;
    int quad = lane >> 2, tq = lane & 3;

    for (int tile = blockIdx.x; tile < ET2; tile += gridDim.x){
        int base = tile*EMT;
        int nval = NED - base; if (nval > EMT) nval = EMT;
        if (tid < EMT) es[tid] = (tid < nval) ? ei[base + tid] : 0;
        else { int e = tid - EMT; ed[e] = (e < nval) ? ei[NED + base + e] : 0; }
        __syncthreads();
        for (int idx = tid; idx < EMT*3; idx += 256){
            int e = idx/3, c = idx%3;
            float d = pos[ed[e]*3 + c] - pos[es[e]*3 + c];
            float dm = dsm[c];
            d -= dm * rintf(d/dm);
            dp[e*4 + c] = d;
        }
        __syncthreads();
        #pragma unroll 4
        for (int q = 0; q < 32; q++){
            int idx = tid + q*256;
            int e = idx >> 6, jp = idx & 63, j = jp*2;
            int nd = ed[e], ns = es[e];
            float2 av = *(const float2*)(g_A + (size_t)nd*HD + j);
            float2 bv = *(const float2*)(g_B + (size_t)ns*HD + j);
            float d0 = dp[e*4], d1 = dp[e*4+1], d2 = dp[e*4+2];
            float p0 = av.x + bv.x + bias[j]   + d0*wp[j]   + d1*wp[128+j]   + d2*wp[256+j];
            float p1 = av.y + bv.y + bias[j+1] + d0*wp[j+1] + d1*wp[128+j+1] + d2*wp[256+j+1];
            p0 = fmaxf(p0, 0.f); p1 = fmaxf(p1, 0.f);
            unsigned hi, lo; hilo(p0, p1, hi, lo);
            uint32_t o = (uint32_t)e*256 + ((((j>>3) ^ (e&7)))<<4) + (j&7)*2;
            *(unsigned*)(Ahi + o) = hi;
            *(unsigned*)(Alo + o) = lo;
        }
        __syncthreads();

        float d[2][8][4];
        #pragma unroll
        for (int m = 0; m < 2; m++)
            #pragma unroll
            for (int nf = 0; nf < 8; nf++)
                #pragma unroll
                for (int c = 0; c < 4; c++) d[m][nf][c] = 0.f;

        int rowA = m0 + (lane & 7) + ((lane >> 3) & 1)*8;
        #pragma unroll
        for (int ks = 0; ks < 8; ks++){
            int k0 = ks*16;
            int kbA = k0 + (lane >> 4)*8;
            uint32_t offA = (uint32_t)rowA*256 + ((((kbA>>3) ^ (rowA&7)))<<4);
            uint32_t ah0[4], al0[4], ah1[4], al1[4];
            ldsm4(ah0, AhiB + offA);
            ldsm4(al0, AloB + offA);
            ldsm4(ah1, AhiB + offA + 4096);
            ldsm4(al1, AloB + offA + 4096);
            int kbB = k0 + ((lane >> 3) & 1)*8;
            #pragma unroll
            for (int nf = 0; nf < 8; nf++){
                int rowB = nh + nf*8 + (lane & 7);
                uint32_t offB = (uint32_t)rowB*256 + ((((kbB>>3) ^ (rowB&7)))<<4);
                uint32_t bh[2], bl[2];
                ldsm2(bh, BhiB + offB);
                ldsm2(bl, BloB + offB);
                mma16816(d[0][nf], ah0, bh);
                mma16816(d[0][nf], al0, bh);
                mma16816(d[0][nf], ah0, bl);
                mma16816(d[1][nf], ah1, bh);
                mma16816(d[1][nf], al1, bh);
                mma16816(d[1][nf], ah1, bl);
            }
        }
        __syncthreads();

        #pragma unroll
        for (int m = 0; m < 2; m++){
            int e0 = m0 + m*16 + quad;
            int e1 = e0 + 8;
            #pragma unroll
            for (int nf = 0; nf < 8; nf++){
                int n = nh + nf*8 + 2*tq;
                float2 v0 = { fmaxf(d[m][nf][0] + b2[n], 0.f), fmaxf(d[m][nf][1] + b2[n+1], 0.f) };
                float2 v1 = { fmaxf(d[m][nf][2] + b2[n], 0.f), fmaxf(d[m][nf][3] + b2[n+1], 0.f) };
                *(float2*)(outb + (size_t)e0*128 + ((((n>>2) ^ (e0&7)))<<2) + (n&3)) = v0;
                *(float2*)(outb + (size_t)e1*128 + ((((n>>2) ^ (e1&7)))<<2) + (n&3)) = v1;
            }
        }
        __syncthreads();
        #pragma unroll
        for (int q = 0; q < 16; q++){
            int idx = tid + q*256;
            int e = idx >> 5, c = idx & 31;
            if (e < nval){
                float4 val = ((const float4*)outb)[e*32 + (c ^ (e&7))];
                red4(&g_agg[(size_t)ed[e]*HD + c*4], val);
            }
        }
        __syncthreads();
    }
}

// ---------------- update first linear (two-pass tensor MMA) ----------------
__global__ void __launch_bounds__(256,1) k_upd1t(const float* __restrict__ updW1, int l)
{
    extern __shared__ char smc[];
    char* WhHi = smc;
    char* WhLo = smc + 32768;
    char* WaHi = smc + 65536;
    char* WaLo = smc + 98304;
    char* AHi  = smc + 131072;
    char* ALo  = smc + 163840;
    float* bias = (float*)(smc + 196608);
    float* mu  = bias + 128;
    float* is  = mu + 128;
    float* dsm = is + 128;
    const float* WU = updW1 + (size_t)l*268*HD;
    int tid = threadIdx.x, wid = tid>>5, lane = tid&31;
    STAGEW(WU, WhHi, WhLo);
    STAGEW(WU + 128*128, WaHi, WaLo);
    if (tid < 128){
        bias[tid] = g_bias_upd[l*HD + tid];
        mu[tid] = g_mu[tid]; is[tid] = g_is[tid];
    }
    __syncthreads();
    int m0 = (wid&3)*32, nh = (wid>>2)*64, quad = lane>>2, tq = lane&3;
    uint32_t AHiB = smem_u32(AHi), ALoB = smem_u32(ALo);
    uint32_t WhHiB = smem_u32(WhHi), WhLoB = smem_u32(WhLo);
    uint32_t WaHiB = smem_u32(WaHi), WaLoB = smem_u32(WaLo);
    int rowA = m0 + (lane & 7) + ((lane >> 3) & 1)*8;
    for (int tile = blockIdx.x; tile < NTT; tile += gridDim.x){
        int base = tile*128;
        // pass 1: hn
        #pragma unroll 4
        for (int q = 0; q < 32; q++){
            int idx = tid + q*256;
            int e = idx>>6, jp = idx&63, j = jp*2;
            float2 hv = *(const float2*)(g_h + (size_t)(base+e)*128 + j);
            float p0 = (hv.x - mu[j])*is[j], p1 = (hv.y - mu[j+1])*is[j+1];
            unsigned hi, lo; hilo(p0, p1, hi, lo);
            uint32_t o = (uint32_t)e*256 + ((((j>>3) ^ (e&7)))<<4) + (j&7)*2;
            *(unsigned*)(AHi + o) = hi;
            *(unsigned*)(ALo + o) = lo;
        }
        __syncthreads();
        float d[2][8][4];
        #pragma unroll
        for (int m = 0; m < 2; m++)
            #pragma unroll
            for (int nf = 0; nf < 8; nf++)
                #pragma unroll
                for (int c = 0; c < 4; c++) d[m][nf][c] = 0.f;
        #pragma unroll
        for (int ks = 0; ks < 8; ks++){
            int k0 = ks*16;
            int kbA = k0 + (lane >> 4)*8;
            uint32_t offA = (uint32_t)rowA*256 + ((((kbA>>3) ^ (rowA&7)))<<4);
            uint32_t ah0[4], al0[4], ah1[4], al1[4];
            ldsm4(ah0, AHiB + offA);
            ldsm4(al0, ALoB + offA);
            ldsm4(ah1, AHiB + offA + 4096);
            ldsm4(al1, ALoB + offA + 4096);
            int kbB = k0 + ((lane >> 3) & 1)*8;
            #pragma unroll
            for (int nf = 0; nf < 8; nf++){
                int rowB = nh + nf*8 + (lane & 7);
                uint32_t offB = (uint32_t)rowB*256 + ((((kbB>>3) ^ (rowB&7)))<<4);
                uint32_t bh[2], bl[2];
                ldsm2(bh, WhHiB + offB);
                ldsm2(bl, WhLoB + offB);
                mma16816(d[0][nf], ah0, bh); mma16816(d[0][nf], al0, bh); mma16816(d[0][nf], ah0, bl);
                mma16816(d[1][nf], ah1, bh); mma16816(d[1][nf], al1, bh); mma16816(d[1][nf], ah1, bl);
            }
        }
        if (tid < 128) dsm[tid] = 1.f / fmaxf(g_deg[base + tid], 1.f);
        __syncthreads();
        // pass 2: aggn
        #pragma unroll 4
        for (int q = 0; q < 32; q++){
            int idx = tid + q*256;
            int e = idx>>6, jp = idx&63, j = jp*2;
            float di = dsm[e];
            float2 av = *(const float2*)(g_agg + (size_t)(base+e)*128 + j);
            unsigned hi, lo; hilo(av.x*di, av.y*di, hi, lo);
            uint32_t o = (uint32_t)e*256 + ((((j>>3) ^ (e&7)))<<4) + (j&7)*2;
            *(unsigned*)(AHi + o) = hi;
            *(unsigned*)(ALo + o) = lo;
        }
        __syncthreads();
        #pragma unroll
        for (int ks = 0; ks < 8; ks++){
            int k0 = ks*16;
            int kbA = k0 + (lane >> 4)*8;
            uint32_t offA = (uint32_t)rowA*256 + ((((kbA>>3) ^ (rowA&7)))<<4);
            uint32_t ah0[4], al0[4], ah1[4], al1[4];
            ldsm4(ah0, AHiB + offA);
            ldsm4(al0, ALoB + offA);
            ldsm4(ah1, AHiB + offA + 4096);
            ldsm4(al1, ALoB + offA + 4096);
            int kbB = k0 + ((lane >> 3) & 1)*8;
            #pragma unroll
            for (int nf = 0; nf < 8; nf++){
                int rowB = nh + nf*8 + (lane & 7);
                uint32_t offB = (uint32_t)rowB*256 + ((((kbB>>3) ^ (rowB&7)))<<4);
                uint32_t bh[2], bl[2];
                ldsm2(bh, WaHiB + offB);
                ldsm2(bl, WaLoB + offB);
                mma16816(d[0][nf], ah0, bh); mma16816(d[0][nf], al0, bh); mma16816(d[0][nf], ah0, bl);
                mma16816(d[1][nf], ah1, bh); mma16816(d[1][nf], al1, bh); mma16816(d[1][nf], ah1, bl);
            }
        }
        __syncthreads();
        #pragma unroll
        for (int m = 0; m < 2; m++){
            int e0 = m0 + m*16 + quad, e1 = e0 + 8;
            #pragma unroll
            for (int nf = 0; nf < 8; nf++){
                int n = nh + nf*8 + 2*tq;
                float2 u0 = { fmaxf(d[m][nf][0]+bias[n], 0.f), fmaxf(d[m][nf][1]+bias[n+1], 0.f) };
                float2 u1v = { fmaxf(d[m][nf][2]+bias[n], 0.f), fmaxf(d[m][nf][3]+bias[n+1], 0.f) };
                *(float2*)(g_u1+(size_t)(base+e0)*128+n) = u0;
                *(float2*)(g_u1+(size_t)(base+e1)*128+n) = u1v;
            }
        }
    }
}

// ---------------- update second linear (tensor MMA) + residual + stats ----------------
__global__ void __launch_bounds__(256,1) k_upd2t(const float* __restrict__ updW2,
                                                 const float* __restrict__ updb2, int l)
{
    extern __shared__ char smc[];
    char* WHi = smc;
    char* WLo = smc + 32768;
    char* AHi = smc + 65536;
    char* ALo = smc + 98304;
    float* b2  = (float*)(smc + 131072);
    float* mu  = b2 + 128;
    float* is  = mu + 128;
    float* sstat = is + 128;   // 256
    const float* W = updW2 + (size_t)l*HD*HD;
    int tid = threadIdx.x, wid = tid>>5, lane = tid&31;
    STAGEW(W, WHi, WLo);
    if (tid < 128){
        b2[tid] = updb2[l*HD + tid];
        mu[tid] = g_mu[tid]; is[tid] = g_is[tid];
    }
    if (tid < 256) sstat[tid] = 0.f;
    __syncthreads();
    int m0 = (wid&3)*32, nh = (wid>>2)*64, quad = lane>>2, tq = lane&3;
    uint32_t AHiB = smem_u32(AHi), ALoB = smem_u32(ALo);
    uint32_t WHiB = smem_u32(WHi), WLoB = smem_u32(WLo);
    int rowA = m0 + (lane & 7) + ((lane >> 3) & 1)*8;
    float ls1[16], ls2[16];
    #pragma unroll
    for (int i = 0; i < 16; i++){ ls1[i]=0.f; ls2[i]=0.f; }
    for (int tile = blockIdx.x; tile < NTT; tile += gridDim.x){
        int base = tile*128;
        #pragma unroll 4
        for (int q = 0; q < 32; q++){
            int idx = tid + q*256;
            int e = idx>>6, jp = idx&63, j = jp*2;
            float2 uv = *(const float2*)(g_u1 + (size_t)(base+e)*128 + j);
            unsigned hi, lo; hilo(uv.x, uv.y, hi, lo);
            uint32_t o = (uint32_t)e*256 + ((((j>>3) ^ (e&7)))<<4) + (j&7)*2;
            *(unsigned*)(AHi + o) = hi;
            *(unsigned*)(ALo + o) = lo;
        }
        __syncthreads();
        float d[2][8][4];
        #pragma unroll
        for (int m = 0; m < 2; m++)
            #pragma unroll
            for (int nf = 0; nf < 8; nf++)
                #pragma unroll
                for (int c = 0; c < 4; c++) d[m][nf][c] = 0.f;
        #pragma unroll
        for (int ks = 0; ks < 8; ks++){
            int k0 = ks*16;
            int kbA = k0 + (lane >> 4)*8;
            uint32_t offA = (uint32_t)rowA*256 + ((((kbA>>3) ^ (rowA&7)))<<4);
            uint32_t ah0[4], al0[4], ah1[4], al1[4];
            ldsm4(ah0, AHiB + offA);
            ldsm4(al0, ALoB + offA);
            ldsm4(ah1, AHiB + offA + 4096);
            ldsm4(al1, ALoB + offA + 4096);
            int kbB = k0 + ((lane >> 3) & 1)*8;
            #pragma unroll
            for (int nf = 0; nf < 8; nf++){
                int rowB = nh + nf*8 + (lane & 7);
                uint32_t offB = (uint32_t)rowB*256 + ((((kbB>>3) ^ (rowB&7)))<<4);
                uint32_t bh[2], bl[2];
                ldsm2(bh, WHiB + offB);
                ldsm2(bl, WLoB + offB);
                mma16816(d[0][nf], ah0, bh); mma16816(d[0][nf], al0, bh); mma16816(d[0][nf], ah0, bl);
                mma16816(d[1][nf], ah1, bh); mma16816(d[1][nf], al1, bh); mma16816(d[1][nf], ah1, bl);
            }
        }
        __syncthreads();
        #pragma unroll
        for (int m = 0; m < 2; m++){
            int e0 = m0 + m*16 + quad, e1 = e0 + 8;
            int row0 = base + e0, row1 = base + e1;
            #pragma unroll
            for (int nf = 0; nf < 8; nf++){
                int n = nh + nf*8 + 2*tq;
                float2 h0 = *(float2*)(g_h+(size_t)row0*128+n);
                float2 h1 = *(float2*)(g_h+(size_t)row1*128+n);
                float z00 = (h0.x-mu[n])*is[n] + d[m][nf][0] + b2[n];
                float z01 = (h0.y-mu[n+1])*is[n+1] + d[m][nf][1] + b2[n+1];
                float z10 = (h1.x-mu[n])*is[n] + d[m][nf][2] + b2[n];
                float z11 = (h1.y-mu[n+1])*is[n+1] + d[m][nf][3] + b2[n+1];
                *(float2*)(g_h+(size_t)row0*128+n) = make_float2(z00, z01);
                *(float2*)(g_h+(size_t)row1*128+n) = make_float2(z10, z11);
                if (row0 < NND){ ls1[nf*2]+=z00; ls1[nf*2+1]+=z01; ls2[nf*2]+=z00*z00; ls2[nf*2+1]+=z01*z01; }
                if (row1 < NND){ ls1[nf*2]+=z10; ls1[nf*2+1]+=z11; ls2[nf*2]+=z10*z10; ls2[nf*2+1]+=z11*z11; }
            }
        }
    }
    __syncthreads();
    #pragma unroll
    for (int nf = 0; nf < 8; nf++){
        int n = nh + nf*8 + 2*tq;
        atomicAdd(&sstat[n],   ls1[nf*2]);
        atomicAdd(&sstat[n+1], ls1[nf*2+1]);
        atomicAdd(&sstat[128+n],   ls2[nf*2]);
        atomicAdd(&sstat[128+n+1], ls2[nf*2+1]);
    }
    __syncthreads();
    if (tid < 256) atomicAdd(&g_stats[tid], sstat[tid]);
}

__global__ void k_hsum(){
    int j = threadIdx.x;
    float s = 0.f;
    for (int node = blockIdx.x; node < NND; node += gridDim.x)
        s += g_h[node*HD + j];
    atomicAdd(&g_hsum[j], s);
}

// ---------------- output head ----------------
__global__ void __launch_bounds__(256,2) k_out(const float* __restrict__ outW1,
                                               const float* __restrict__ outb1,
                                               const float* __restrict__ outW2,
                                               const float* __restrict__ outb2,
                                               const float* __restrict__ pos,
                                               const float* __restrict__ v,
                                               const float* __restrict__ domn,
                                               float* __restrict__ out)
{
    extern __shared__ float sm[];
    float* w1T = sm;
    float* b1  = w1T + 128*KP;
    float* mu  = b1 + 128;
    float* is  = mu + 128;
    float* w2o = is + 128;
    float* b2o = w2o + 128*12;
    float* dnx = b2o + 16;
    float* hsm = dnx + 4;
    float* o1  = hsm + OTIL*128;
    float* rv9 = o1 + OTIL*128;
    int tid = threadIdx.x;
    for (int idx = tid; idx < 128*128; idx += 256){
        int k = idx >> 7, jj = idx & 127;
        w1T[jj*KP + k] = outW1[idx];
    }
    for (int idx = tid; idx < HD*9; idx += 256){
        int k = idx/9, c = idx%9;
        w2o[k*12 + c] = outW2[idx];
    }
    if (tid < 128){
        b1[tid] = outb1[tid];
        mu[tid] = g_mu[tid]; is[tid] = g_is[tid];
    }
    if (tid < 9) b2o[tid] = outb2[tid];
    if (tid < 3) dnx[tid] = domn[tid];
    __syncthreads();
    int c0 = tid & 63, c1 = c0 + 64, r0 = (tid >> 6)*8;
    for (int tile = blockIdx.x; tile < ONT; tile += gridDim.x){
        int base = tile*OTIL;
        for (int idx = tid; idx < OTIL*128; idx += 256){
            int j = idx & 127;
            hsm[idx] = (g_h[base*HD + idx] - mu[j])*is[j];
        }
        for (int tt = tid; tt < OTIL*9; tt += 256){
            int i = tt/9, c = tt%9; int row = base + i;
            rv9[i*12 + c] = (row < NND) ? ((c < 3) ? pos[row*3 + c] : v[row*6 + c-3]) : 0.f;
        }
        __syncthreads();
        u64 acc0[8], acc1[8];
        #pragma unroll
        for (int i = 0; i < 8; i++){ acc0[i]=0ull; acc1[i]=0ull; }
        const float* wr0 = &w1T[c0*KP];
        const float* wr1 = &w1T[c1*KP];
        const float* ab  = &hsm[r0*128];
        GEMM8(acc0, acc1, ab, wr0, wr1);
        #pragma unroll
        for (int i = 0; i < 8; i++){
            o1[(r0+i)*128 + c0] = fmaxf(hadd2(acc0[i]) + b1[c0], 0.f);
            o1[(r0+i)*128 + c1] = fmaxf(hadd2(acc1[i]) + b1[c1], 0.f);
        }
        __syncthreads();
        for (int tt = tid; tt < OTIL*9; tt += 256){
            int i = tt/9, c = tt%9; int row = base + i;
            if (row < NND){
                float s = b2o[c];
                for (int k = 0; k < HD; k++) s += o1[i*128 + k]*w2o[k*12 + c];
                if (c < 3){
                    float p = 0.001f*s + rv9[i*12 + c];
                    float d = dnx[c];
                    out[row*3 + c] = p - floorf(p/d)*d;
                } else {
                    float sc = (c < 6) ? 0.001f : 0.01f;
                    out[NND*3 + row*6 + (c-3)] = sc*s + rv9[i*12 + c];
                }
            }
        }
        __syncthreads();
    }
}

__global__ void k_macro(const float* __restrict__ W1, const float* __restrict__ b1,
                        const float* __restrict__ W2, const float* __restrict__ b2,
                        float* __restrict__ out)
{
    __shared__ float hm[HD];
    __shared__ float hid[HD];
    int j = threadIdx.x;
    hm[j] = (g_hsum[j]*(1.0f/(float)NND) - g_mu[j])*g_is[j];
    __syncthreads();
    float acc = b1[j];
    for (int k = 0; k < HD; k++) acc += hm[k]*W1[k*HD + j];
    hid[j] = fmaxf(acc, 0.f);
    __syncthreads();
    if (j < 3){
        float s = b2[j];
        for (int k = 0; k < HD; k++) s += hid[k]*W2[k*3 + j];
        out[NND*9 + j] = s;
    }
}

extern "C" void kernel_launch(void* const* d_in, const int* in_sizes, int n_in,
                              void* d_out, int out_size)
{
    const float* v    = (const float*)d_in[0];
    const float* pos  = (const float*)d_in[1];
    const float* r    = (const float*)d_in[2];
    const float* dom  = (const float*)d_in[3];
    const float* t    = (const float*)d_in[4];
    const float* xg   = (const float*)d_in[5];
    const float* domn = (const float*)d_in[6];
    const float* tn   = (const float*)d_in[7];
    const int*   ei   = (const int*)d_in[8];
    const float* embW1=(const float*)d_in[10];
    const float* embb1=(const float*)d_in[11];
    const float* embW2=(const float*)d_in[12];
    const float* embb2=(const float*)d_in[13];
    const float* msgW1=(const float*)d_in[14];
    const float* msgb1=(const float*)d_in[15];
    const float* msgW2=(const float*)d_in[16];
    const float* msgb2=(const float*)d_in[17];
    const float* updW1=(const float*)d_in[18];
    const float* updb1=(const float*)d_in[19];
    const float* updW2=(const float*)d_in[20];
    const float* updb2=(const float*)d_in[21];
    const float* outW1=(const float*)d_in[22];
    const float* outb1=(const float*)d_in[23];
    const float* outW2=(const float*)d_in[24];
    const float* outb2=(const float*)d_in[25];
    const float* macW1=(const float*)d_in[26];
    const float* macb1=(const float*)d_in[27];
    const float* macW2=(const float*)d_in[28];
    const float* macb2=(const float*)d_in[29];
    float* out = (float*)d_out;

    size_t smEmbed = (size_t)(128*KP + 7*128 + 256 + TIL*128 + TIL*8)*4;
    size_t smNAB   = 196608 + (size_t)(768 + 4*128 + 128*8)*4;
    size_t smEdge  = 131072 + (size_t)(384 + 128 + 128 + 4 + 512)*4 + 1024 + 64;
    size_t smU1    = 196608 + (size_t)(4*128)*4;
    size_t smU2    = 131072 + (size_t)(3*128 + 256)*4;
    size_t smOut   = (size_t)(128*KP + 3*128 + 128*12 + 16 + 4 + 2*OTIL*128 + OTIL*12)*4;
    cudaFuncSetAttribute(k_embed, cudaFuncAttributeMaxDynamicSharedMemorySize, (int)smEmbed);
    cudaFuncSetAttribute(k_nAB,   cudaFuncAttributeMaxDynamicSharedMemorySize, (int)smNAB);
    cudaFuncSetAttribute(k_edge_tc, cudaFuncAttributeMaxDynamicSharedMemorySize, (int)smEdge);
    cudaFuncSetAttribute(k_upd1t, cudaFuncAttributeMaxDynamicSharedMemorySize, (int)smU1);
    cudaFuncSetAttribute(k_upd2t, cudaFuncAttributeMaxDynamicSharedMemorySize, (int)smU2);
    cudaFuncSetAttribute(k_out,   cudaFuncAttributeMaxDynamicSharedMemorySize, (int)smOut);

    k_prep<<<1,128>>>(dom, t, xg, domn, tn, embW1, embb1, msgW1, msgb1, updW1, updb1);
    k_zero0<<<64,256>>>();
    k_count<<<256,256>>>(ei);
    k_embed<<<296,256,smEmbed>>>(embW1, embW2, embb2, v, r);
    for (int l = 0; l < NL; l++){
        k_nAB<<<148,256,smNAB>>>(msgW1, v, r, l);
        k_edge_tc<<<148,256,smEdge>>>(msgW1, msgW2, msgb2, ei, pos, dom, l);
        k_upd1t<<<148,256,smU1>>>(updW1, l);
        k_upd2t<<<148,256,smU2>>>(updW2, updb2, l);
        k_stats<<<1,128>>>();
    }
    k_hsum<<<296,128>>>();
    k_out<<<296,256,smOut>>>(outW1, outb1, outW2, outb2, pos, v, domn, out);
    k_macro<<<1,128>>>(macW1, macb1, macW2, macb2, out);
}

// round 13
// speedup vs baseline: 2.7529x; 1.1813x over previous
#include <cuda_runtime.h>
#include <cuda_bf16.h>
#include <cstdint>

#define NND 50000
#define NP  50048
#define NED 300000
#define NEP 300032
#define HD 128
#define NL 6
#define KP 132
#define TIL 64
#define NT  (NP/TIL)
#define NTT (NP/128)
#define OTIL 32
#define ONT (NP/OTIL)
#define EMT 128
#define ET2 (NEP/EMT)

__device__ float g_h[NP*HD];
__device__ float g_A[NP*HD];
__device__ float g_B[NP*HD];
__device__ float g_agg[NP*HD];
__device__ float g_deg[NP];
__device__ float g_bias_emb[HD];
__device__ float g_bias_msg[NL*HD];
__device__ float g_bias_upd[NL*HD];
__device__ float g_stats[2*HD];
__device__ float g_mu[HD];
__device__ float g_is[HD];
__device__ float g_hsum[HD];
__device__ unsigned g_tick;

typedef unsigned long long u64;

__device__ __forceinline__ void ffma2(u64 &d, u64 a, u64 b){
    asm("fma.rn.f32x2 %0, %1, %2, %0;" : "+l"(d) : "l"(a), "l"(b));
}
__device__ __forceinline__ float hadd2(u64 a){
    return __uint_as_float((unsigned)a) + __uint_as_float((unsigned)(a>>32));
}
__device__ __forceinline__ void red4(float* p, float4 v){
    asm volatile("red.global.add.v4.f32 [%0], {%1,%2,%3,%4};"
                 :: "l"(p), "f"(v.x), "f"(v.y), "f"(v.z), "f"(v.w) : "memory");
}
__device__ __forceinline__ uint32_t smem_u32(const void* p){
    uint32_t a;
    asm("{ .reg .u64 t; cvta.to.shared.u64 t, %1; cvt.u32.u64 %0, t; }" : "=r"(a) : "l"(p));
    return a;
}
__device__ __forceinline__ void ldsm4(uint32_t* r, uint32_t addr){
    asm volatile("ldmatrix.sync.aligned.m8n8.x4.shared.b16 {%0,%1,%2,%3}, [%4];"
        : "=r"(r[0]),"=r"(r[1]),"=r"(r[2]),"=r"(r[3]) : "r"(addr));
}
__device__ __forceinline__ void ldsm2(uint32_t* r, uint32_t addr){
    asm volatile("ldmatrix.sync.aligned.m8n8.x2.shared.b16 {%0,%1}, [%2];"
        : "=r"(r[0]),"=r"(r[1]) : "r"(addr));
}
__device__ __forceinline__ void mma16816(float* d, const uint32_t* a, const uint32_t* b){
    asm volatile("mma.sync.aligned.m16n8k16.row.col.f32.bf16.bf16.f32 "
        "{%0,%1,%2,%3}, {%4,%5,%6,%7}, {%8,%9}, {%0,%1,%2,%3};"
        : "+f"(d[0]),"+f"(d[1]),"+f"(d[2]),"+f"(d[3])
        : "r"(a[0]),"r"(a[1]),"r"(a[2]),"r"(a[3]), "r"(b[0]),"r"(b[1]));
}
__device__ __forceinline__ void hilo(float p0, float p1, unsigned &hi, unsigned &lo){
    __nv_bfloat16 h0=__float2bfloat16(p0), h1=__float2bfloat16(p1);
    __nv_bfloat16 l0=__float2bfloat16(p0-__bfloat162float(h0));
    __nv_bfloat16 l1=__float2bfloat16(p1-__bfloat162float(h1));
    hi = (unsigned)__bfloat16_as_ushort(h0) | ((unsigned)__bfloat16_as_ushort(h1)<<16);
    lo = (unsigned)__bfloat16_as_ushort(l0) | ((unsigned)__bfloat16_as_ushort(l1)<<16);
}

#define GEMM16(ACC0, ACC1, ACTB, WR0, WR1) \
  _Pragma("unroll 2") \
  for (int kk = 0; kk < 128; kk += 4){ \
    ulonglong2 w0v = *(const ulonglong2*)((WR0) + kk); \
    ulonglong2 w1v = *(const ulonglong2*)((WR1) + kk); \
    _Pragma("unroll") \
    for (int ii = 0; ii < 16; ii++){ \
      ulonglong2 xv = *(const ulonglong2*)((ACTB) + ii*128 + kk); \
      ffma2(ACC0[ii], xv.x, w0v.x); ffma2(ACC0[ii], xv.y, w0v.y); \
      ffma2(ACC1[ii], xv.x, w1v.x); ffma2(ACC1[ii], xv.y, w1v.y); \
    } \
  }
#define GEMM8(ACC0, ACC1, ACTB, WR0, WR1) \
  _Pragma("unroll 2") \
  for (int kk = 0; kk < 128; kk += 4){ \
    ulonglong2 w0v = *(const ulonglong2*)((WR0) + kk); \
    ulonglong2 w1v = *(const ulonglong2*)((WR1) + kk); \
    _Pragma("unroll") \
    for (int ii = 0; ii < 8; ii++){ \
      ulonglong2 xv = *(const ulonglong2*)((ACTB) + ii*128 + kk); \
      ffma2(ACC0[ii], xv.x, w0v.x); ffma2(ACC0[ii], xv.y, w0v.y); \
      ffma2(ACC1[ii], xv.x, w1v.x); ffma2(ACC1[ii], xv.y, w1v.y); \
    } \
  }

#define STAGEW(W, WHI, WLO) \
  for (int idx = tid; idx < 128*64; idx += 256){ \
    int n = idx >> 6, kp = idx & 63; \
    uint32_t o = (uint32_t)n*256 + ((((kp>>2) ^ (n&7)))<<4) + (kp&3)*4; \
    unsigned hi, lo; \
    hilo((W)[(2*kp)*128 + n], (W)[(2*kp+1)*128 + n], hi, lo); \
    *(unsigned*)((WHI) + o) = hi; \
    *(unsigned*)((WLO) + o) = lo; \
  }

__global__ void k_prep(const float* __restrict__ dom, const float* __restrict__ t,
                       const float* __restrict__ xg, const float* __restrict__ domn,
                       const float* __restrict__ tn,
                       const float* __restrict__ embW1, const float* __restrict__ embb1,
                       const float* __restrict__ msgW1, const float* __restrict__ msgb1,
                       const float* __restrict__ updW1, const float* __restrict__ updb1)
{
    __shared__ float gf[12];
    int j = threadIdx.x;
    if (j < 12){
        float val;
        if (j < 3) val = dom[j];
        else if (j == 3) val = t[0];
        else if (j < 8) val = xg[j-4];
        else if (j < 11) val = domn[j-8];
        else val = tn[0];
        gf[j] = val;
    }
    __syncthreads();
    float acc = embb1[j];
    #pragma unroll
    for (int g = 0; g < 12; g++) acc += gf[g]*embW1[(7+g)*HD + j];
    g_bias_emb[j] = acc;
    for (int l = 0; l < NL; l++){
        const float* W = msgW1 + (size_t)l*279*HD;
        float a = msgb1[l*HD + j];
        #pragma unroll
        for (int g = 0; g < 12; g++) a += gf[g]*W[(267+g)*HD + j];
        g_bias_msg[l*HD + j] = a;
        const float* U = updW1 + (size_t)l*268*HD;
        float b = updb1[l*HD + j];
        #pragma unroll
        for (int g = 0; g < 12; g++) b += gf[g]*U[(256+g)*HD + j];
        g_bias_upd[l*HD + j] = b;
    }
}

__global__ void k_zero0(){
    int i = blockIdx.x*blockDim.x + threadIdx.x;
    for (int idx = i; idx < NP; idx += gridDim.x*blockDim.x) g_deg[idx] = 0.f;
    if (i < HD){ g_hsum[i] = 0.f; g_mu[i] = 0.f; g_is[i] = 1.f; }
    if (i < 2*HD) g_stats[i] = 0.f;
    if (i == 0) g_tick = 0u;
}

__global__ void k_count(const int* __restrict__ ei){
    for (int e = blockIdx.x*blockDim.x + threadIdx.x; e < NED; e += gridDim.x*blockDim.x)
        atomicAdd(&g_deg[ei[NED + e]], 1.0f);
}

// ---------------- embedding (scalar FFMA2) ----------------
__global__ void __launch_bounds__(256,2) k_embed(const float* __restrict__ embW1,
                                                 const float* __restrict__ embW2,
                                                 const float* __restrict__ embb2,
                                                 const float* __restrict__ v,
                                                 const float* __restrict__ rr)
{
    extern __shared__ float sm[];
    float* w2t = sm;
    float* w1  = w2t + 128*KP;
    float* be  = w1 + 7*128;
    float* b2e = be + 128;
    float* hid = b2e + 128;
    float* rv  = hid + TIL*128;
    int tid = threadIdx.x;
    for (int idx = tid; idx < 128*128; idx += 256){
        int k = idx >> 7, jj = idx & 127;
        w2t[jj*KP + k] = embW2[idx];
    }
    for (int idx = tid; idx < 7*128; idx += 256) w1[idx] = embW1[idx];
    if (tid < 128){ be[tid] = g_bias_emb[tid]; b2e[tid] = embb2[tid]; }
    __syncthreads();
    int c0 = tid & 63, c1 = c0 + 64, r0 = (tid >> 6)*16;
    for (int tile = blockIdx.x; tile < NT; tile += gridDim.x){
        int base = tile*TIL;
        for (int idx = tid; idx < TIL*7; idx += 256){
            int i = idx/7, c = idx%7; int row = base + i;
            rv[i*8+c] = (row < NND) ? ((c==0) ? rr[row] : v[row*6 + c-1]) : 0.f;
        }
        __syncthreads();
        #pragma unroll
        for (int i = 0; i < 16; i++){
            int rr8 = (r0+i)*8;
            float a0 = be[c0] + rv[rr8]*w1[c0];
            float a1 = be[c1] + rv[rr8]*w1[c1];
            #pragma unroll
            for (int c = 0; c < 6; c++){
                float x = rv[rr8+1+c];
                a0 += x*w1[(1+c)*128 + c0];
                a1 += x*w1[(1+c)*128 + c1];
            }
            hid[(r0+i)*128 + c0] = fmaxf(a0, 0.f);
            hid[(r0+i)*128 + c1] = fmaxf(a1, 0.f);
        }
        __syncthreads();
        u64 acc0[16], acc1[16];
        #pragma unroll
        for (int i = 0; i < 16; i++){ acc0[i]=0ull; acc1[i]=0ull; }
        const float* wr0 = &w2t[c0*KP];
        const float* wr1 = &w2t[c1*KP];
        const float* ab  = &hid[r0*128];
        GEMM16(acc0, acc1, ab, wr0, wr1);
        #pragma unroll
        for (int i = 0; i < 16; i++){
            int row = base + r0 + i;
            g_h[row*HD + c0] = fmaxf(hadd2(acc0[i]) + b2e[c0], 0.f);
            g_h[row*HD + c1] = fmaxf(hadd2(acc1[i]) + b2e[c1], 0.f);
        }
        __syncthreads();
    }
}

// ---------------- node A+B fused tensor GEMM + agg zero ----------------
__global__ void __launch_bounds__(256,1) k_nAB(const float* __restrict__ msgW1,
                                               const float* __restrict__ v,
                                               const float* __restrict__ rr, int l)
{
    extern __shared__ char smc[];
    char* WdHi = smc;
    char* WdLo = smc + 32768;
    char* WsHi = smc + 65536;
    char* WsLo = smc + 98304;
    char* AHi  = smc + 131072;
    char* ALo  = smc + 163840;
    float* wv  = (float*)(smc + 196608);
    float* wrA = wv + 768;
    float* wrB = wrA + 128;
    float* mu  = wrB + 128;
    float* is  = mu + 128;
    float* rv  = is + 128;       // 128*8
    const float* W1 = msgW1 + (size_t)l*279*HD;
    int tid = threadIdx.x, wid = tid>>5, lane = tid&31;
    STAGEW(W1, WdHi, WdLo);
    STAGEW(W1 + 128*128, WsHi, WsLo);
    for (int idx = tid; idx < 768; idx += 256) wv[idx] = W1[259*128 + idx];
    if (tid < 128){
        wrA[tid] = W1[265*128+tid]; wrB[tid] = W1[266*128+tid];
        mu[tid] = g_mu[tid]; is[tid] = g_is[tid];
    }
    __syncthreads();
    int m0 = (wid&3)*32, nh = (wid>>2)*64, quad = lane>>2, tq = lane&3;
    uint32_t AHiB = smem_u32(AHi), ALoB = smem_u32(ALo);
    uint32_t WdHiB = smem_u32(WdHi), WdLoB = smem_u32(WdLo);
    uint32_t WsHiB = smem_u32(WsHi), WsLoB = smem_u32(WsLo);
    for (int tile = blockIdx.x; tile < NTT; tile += gridDim.x){
        int base = tile*128;
        float4 z4 = {0.f,0.f,0.f,0.f};
        #pragma unroll
        for (int q = 0; q < 16; q++)
            ((float4*)(g_agg + (size_t)base*128))[tid + q*256] = z4;
        for (int idx = tid; idx < 128*7; idx += 256){
            int i = idx/7, c = idx%7; int row = base+i;
            rv[i*8+c] = (row<NND) ? ((c==0)?rr[row]:v[row*6+c-1]) : 0.f;
        }
        #pragma unroll 4
        for (int q = 0; q < 16; q++){
            int idx = tid + q*256;
            int e = idx>>5, jp = idx&31, j = jp*4;
            float4 hv = *(const float4*)(g_h + (size_t)(base+e)*128 + j);
            float p0=(hv.x-mu[j])*is[j],   p1=(hv.y-mu[j+1])*is[j+1];
            float p2=(hv.z-mu[j+2])*is[j+2], p3=(hv.w-mu[j+3])*is[j+3];
            unsigned h0,l0,h1,l1; hilo(p0,p1,h0,l0); hilo(p2,p3,h1,l1);
            uint32_t o = (uint32_t)e*256 + ((((j>>3) ^ (e&7)))<<4) + (j&7)*2;
            *(uint2*)(AHi + o) = make_uint2(h0,h1);
            *(uint2*)(ALo + o) = make_uint2(l0,l1);
        }
        __syncthreads();
        float dA[2][8][4], dB[2][8][4];
        #pragma unroll
        for (int m = 0; m < 2; m++)
            #pragma unroll
            for (int nf = 0; nf < 8; nf++)
                #pragma unroll
                for (int c = 0; c < 4; c++){ dA[m][nf][c]=0.f; dB[m][nf][c]=0.f; }
        int rowA = m0 + (lane & 7) + ((lane >> 3) & 1)*8;
        #pragma unroll
        for (int ks = 0; ks < 8; ks++){
            int k0 = ks*16;
            int kbA = k0 + (lane >> 4)*8;
            uint32_t offA = (uint32_t)rowA*256 + ((((kbA>>3) ^ (rowA&7)))<<4);
            uint32_t ah0[4], al0[4], ah1[4], al1[4];
            ldsm4(ah0, AHiB + offA);
            ldsm4(al0, ALoB + offA);
            ldsm4(ah1, AHiB + offA + 4096);
            ldsm4(al1, ALoB + offA + 4096);
            int kbB = k0 + ((lane >> 3) & 1)*8;
            #pragma unroll
            for (int nf = 0; nf < 8; nf++){
                int rowB = nh + nf*8 + (lane & 7);
                uint32_t offB = (uint32_t)rowB*256 + ((((kbB>>3) ^ (rowB&7)))<<4);
                uint32_t dh[2], dl[2], sh[2], sl[2];
                ldsm2(dh, WdHiB + offB);
                ldsm2(dl, WdLoB + offB);
                ldsm2(sh, WsHiB + offB);
                ldsm2(sl, WsLoB + offB);
                mma16816(dA[0][nf], ah0, dh); mma16816(dA[0][nf], al0, dh); mma16816(dA[0][nf], ah0, dl);
                mma16816(dA[1][nf], ah1, dh); mma16816(dA[1][nf], al1, dh); mma16816(dA[1][nf], ah1, dl);
                mma16816(dB[0][nf], ah0, sh); mma16816(dB[0][nf], al0, sh); mma16816(dB[0][nf], ah0, sl);
                mma16816(dB[1][nf], ah1, sh); mma16816(dB[1][nf], al1, sh); mma16816(dB[1][nf], ah1, sl);
            }
        }
        #pragma unroll
        for (int m = 0; m < 2; m++){
            int e0 = m0 + m*16 + quad, e1 = e0 + 8;
            const float* rv0 = &rv[e0*8];
            const float* rv1 = &rv[e1*8];
            #pragma unroll
            for (int nf = 0; nf < 8; nf++){
                int n = nh + nf*8 + 2*tq;
                float va00=0.f, va01=0.f, va10=0.f, va11=0.f;
                #pragma unroll
                for (int c = 0; c < 6; c++){
                    float w0 = wv[c*128+n], w1 = wv[c*128+n+1];
                    va00 += rv0[1+c]*w0; va01 += rv0[1+c]*w1;
                    va10 += rv1[1+c]*w0; va11 += rv1[1+c]*w1;
                }
                float r0 = rv0[0], r1 = rv1[0];
                float2 a0 = { dA[m][nf][0]+va00+r0*wrA[n], dA[m][nf][1]+va01+r0*wrA[n+1] };
                float2 a1 = { dA[m][nf][2]+va10+r1*wrA[n], dA[m][nf][3]+va11+r1*wrA[n+1] };
                float2 b0 = { dB[m][nf][0]-va00+r0*wrB[n], dB[m][nf][1]-va01+r0*wrB[n+1] };
                float2 b1 = { dB[m][nf][2]-va10+r1*wrB[n], dB[m][nf][3]-va11+r1*wrB[n+1] };
                *(float2*)(g_A+(size_t)(base+e0)*128+n) = a0;
                *(float2*)(g_A+(size_t)(base+e1)*128+n) = a1;
                *(float2*)(g_B+(size_t)(base+e0)*128+n) = b0;
                *(float2*)(g_B+(size_t)(base+e1)*128+n) = b1;
            }
        }
        __syncthreads();
    }
}

// ---------------- edge kernel: mma.sync bf16 hi/lo (3-term) ----------------
__global__ void __launch_bounds__(256) k_edge_tc(const float* __restrict__ msgW1,
                                                 const float* __restrict__ msgW2,
                                                 const float* __restrict__ msgb2,
                                                 const int* __restrict__ ei,
                                                 const float* __restrict__ pos,
                                                 const float* __restrict__ dom, int l)
{
    extern __shared__ char smc[];
    char* Bhi = smc;
    char* Blo = smc + 32768;
    char* Ahi = smc + 65536;
    char* Alo = smc + 98304;
    float* outb = (float*)(smc + 65536);
    float* wp   = (float*)(smc + 131072);
    float* bias = wp + 384;
    float* b2   = bias + 128;
    float* dsm  = b2 + 128;
    float* dp   = dsm + 4;
    int* es     = (int*)(dp + 512);
    int* ed     = es + 128;

    const float* W1 = msgW1 + (size_t)l*279*HD;
    const float* W2 = msgW2 + (size_t)l*HD*HD;
    int tid = threadIdx.x;
    int wid = tid >> 5, lane = tid & 31;
    uint32_t AhiB = smem_u32(Ahi), AloB = smem_u32(Alo);
    uint32_t BhiB = smem_u32(Bhi), BloB = smem_u32(Blo);

    STAGEW(W2, Bhi, Blo);
    for (int idx = tid; idx < 3*128; idx += 256) wp[idx] = W1[256*128 + idx];
    if (tid < 128){
        bias[tid] = g_bias_msg[l*HD + tid];
        b2[tid]   = msgb2[l*HD + tid];
    }
    if (tid < 3) dsm[tid] = dom[tid];
    __syncthreads();

    int m0 = (wid & 3)*32;
    int nh = (wid >> 2)*64;
    int quad = lane >> 2, tq = lane & 3;

    for (int tile = blockIdx.x; tile < ET2; tile += gridDim.x){
        int base = tile*EMT;
        int nval = NED - base; if (nval > EMT) nval = EMT;
        if (tid < EMT) es[tid] = (tid < nval) ? ei[base + tid] : 0;
        else { int e = tid - EMT; ed[e] = (e < nval) ? ei[NED + base + e] : 0; }
        __syncthreads();
        for (int idx = tid; idx < EMT*3; idx += 256){
            int e = idx/3, c = idx%3;
            float d = pos[ed[e]*3 + c] - pos[es[e]*3 + c];
            float dm = dsm[c];
            d -= dm * rintf(d/dm);
            dp[e*4 + c] = d;
        }
        __syncthreads();
        #pragma unroll 4
        for (int q = 0; q < 16; q++){
            int idx = tid + q*256;
            int e = idx >> 5, jp = idx & 31, j = jp*4;
            int nd = ed[e], ns = es[e];
            float4 av = *(const float4*)(g_A + (size_t)nd*HD + j);
            float4 bv = *(const float4*)(g_B + (size_t)ns*HD + j);
            float d0 = dp[e*4], d1 = dp[e*4+1], d2v = dp[e*4+2];
            float p0 = av.x + bv.x + bias[j]   + d0*wp[j]   + d1*wp[128+j]   + d2v*wp[256+j];
            float p1 = av.y + bv.y + bias[j+1] + d0*wp[j+1] + d1*wp[128+j+1] + d2v*wp[256+j+1];
            float p2 = av.z + bv.z + bias[j+2] + d0*wp[j+2] + d1*wp[128+j+2] + d2v*wp[256+j+2];
            float p3 = av.w + bv.w + bias[j+3] + d0*wp[j+3] + d1*wp[128+j+3] + d2v*wp[256+j+3];
            p0 = fmaxf(p0, 0.f); p1 = fmaxf(p1, 0.f);
            p2 = fmaxf(p2, 0.f); p3 = fmaxf(p3, 0.f);
            unsigned h0,l0,h1,l1; hilo(p0,p1,h0,l0); hilo(p2,p3,h1,l1);
            uint32_t o = (uint32_t)e*256 + ((((j>>3) ^ (e&7)))<<4) + (j&7)*2;
            *(uint2*)(Ahi + o) = make_uint2(h0,h1);
            *(uint2*)(Alo + o) = make_uint2(l0,l1);
        }
        __syncthreads();

        float d[2][8][4];
        #pragma unroll
        for (int m = 0; m < 2; m++)
            #pragma unroll
            for (int nf = 0; nf < 8; nf++)
                #pragma unroll
                for (int c = 0; c < 4; c++) d[m][nf][c] = 0.f;

        int rowA = m0 + (lane & 7) + ((lane >> 3) & 1)*8;
        #pragma unroll
        for (int ks = 0; ks < 8; ks++){
            int k0 = ks*16;
            int kbA = k0 + (lane >> 4)*8;
            uint32_t offA = (uint32_t)rowA*256 + ((((kbA>>3) ^ (rowA&7)))<<4);
            uint32_t ah0[4], al0[4], ah1[4], al1[4];
            ldsm4(ah0, AhiB + offA);
            ldsm4(al0, AloB + offA);
            ldsm4(ah1, AhiB + offA + 4096);
            ldsm4(al1, AloB + offA + 4096);
            int kbB = k0 + ((lane >> 3) & 1)*8;
            #pragma unroll
            for (int nf = 0; nf < 8; nf++){
                int rowB = nh + nf*8 + (lane & 7);
                uint32_t offB = (uint32_t)rowB*256 + ((((kbB>>3) ^ (rowB&7)))<<4);
                uint32_t bh[2], bl[2];
                ldsm2(bh, BhiB + offB);
                ldsm2(bl, BloB + offB);
                mma16816(d[0][nf], ah0, bh);
                mma16816(d[0][nf], al0, bh);
                mma16816(d[0][nf], ah0, bl);
                mma16816(d[1][nf], ah1, bh);
                mma16816(d[1][nf], al1, bh);
                mma16816(d[1][nf], ah1, bl);
            }
        }
        __syncthreads();

        #pragma unroll
        for (int m = 0; m < 2; m++){
            int e0 = m0 + m*16 + quad;
            int e1 = e0 + 8;
            #pragma unroll
            for (int nf = 0; nf < 8; nf++){
                int n = nh + nf*8 + 2*tq;
                float2 v0 = { fmaxf(d[m][nf][0] + b2[n], 0.f), fmaxf(d[m][nf][1] + b2[n+1], 0.f) };
                float2 v1 = { fmaxf(d[m][nf][2] + b2[n], 0.f), fmaxf(d[m][nf][3] + b2[n+1], 0.f) };
                *(float2*)(outb + (size_t)e0*128 + ((((n>>2) ^ (e0&7)))<<2) + (n&3)) = v0;
                *(float2*)(outb + (size_t)e1*128 + ((((n>>2) ^ (e1&7)))<<2) + (n&3)) = v1;
            }
        }
        __syncthreads();
        #pragma unroll
        for (int q = 0; q < 16; q++){
            int idx = tid + q*256;
            int e = idx >> 5, c = idx & 31;
            if (e < nval){
                float4 val = ((const float4*)outb)[e*32 + (c ^ (e&7))];
                red4(&g_agg[(size_t)ed[e]*HD + c*4], val);
            }
        }
        __syncthreads();
    }
}

// ---------------- fused update: u1 = relu(hn@Wh + aggn@Wa + bias); z = hn + u1@W2 + b2 ----------------
__global__ void __launch_bounds__(256,1) k_updF(const float* __restrict__ updW1,
                                                const float* __restrict__ updW2,
                                                const float* __restrict__ updb2, int l)
{
    extern __shared__ char smc[];
    char* WhHi = smc;
    char* WhLo = smc + 32768;
    char* WaHi = smc + 65536;
    char* WaLo = smc + 98304;
    char* W2Hi = smc + 131072;
    char* W2Lo = smc + 163840;
    char* PHi  = smc + 196608;           // 128 rows x 80B
    char* PLo  = smc + 206848;
    float* bias = (float*)(smc + 217088);
    float* b2   = bias + 128;
    float* mu   = b2 + 128;
    float* is   = mu + 128;
    float* dsm  = is + 128;
    float* sstat= dsm + 128;             // 256
    int*   sflag= (int*)(sstat + 256);
    const float* Wh = updW1 + (size_t)l*268*HD;
    const float* Wa = Wh + 128*128;
    const float* W2 = updW2 + (size_t)l*HD*HD;
    int tid = threadIdx.x, wid = tid>>5, lane = tid&31;
    STAGEW(Wh, WhHi, WhLo);
    STAGEW(Wa, WaHi, WaLo);
    STAGEW(W2, W2Hi, W2Lo);
    if (tid < 128){
        bias[tid] = g_bias_upd[l*HD + tid];
        b2[tid]   = updb2[l*HD + tid];
        mu[tid] = g_mu[tid]; is[tid] = g_is[tid];
    }
    if (tid < 256) sstat[tid] = 0.f;
    __syncthreads();
    int m0 = (wid&3)*32, nh = (wid>>2)*64, quad = lane>>2, tq = lane&3;
    uint32_t PHiB = smem_u32(PHi), PLoB = smem_u32(PLo);
    uint32_t WhHiB = smem_u32(WhHi), WhLoB = smem_u32(WhLo);
    uint32_t WaHiB = smem_u32(WaHi), WaLoB = smem_u32(WaLo);
    uint32_t W2HiB = smem_u32(W2Hi), W2LoB = smem_u32(W2Lo);
    int rowA = m0 + (lane & 7) + ((lane >> 3) & 1)*8;
    uint32_t laneABase = (uint32_t)rowA*80 + (uint32_t)((lane>>4)*16);
    float ls1[16], ls2[16];
    #pragma unroll
    for (int i = 0; i < 16; i++){ ls1[i]=0.f; ls2[i]=0.f; }

    for (int tile = blockIdx.x; tile < NTT; tile += gridDim.x){
        int base = tile*128;
        float d[2][8][4];
        #pragma unroll
        for (int m = 0; m < 2; m++)
            #pragma unroll
            for (int nf = 0; nf < 8; nf++)
                #pragma unroll
                for (int c = 0; c < 4; c++) d[m][nf][c] = 0.f;
        if (tid < 128) dsm[tid] = 1.f/fmaxf(g_deg[base+tid], 1.f);

        // pass 0: hn @ Wh ; pass 1: (agg*dinv) @ Wa — accumulate into d
        for (int pass = 0; pass < 2; pass++){
            uint32_t BHiB = pass ? WaHiB : WhHiB;
            uint32_t BLoB = pass ? WaLoB : WhLoB;
            for (int p = 0; p < 4; p++){
                __syncthreads();
                #pragma unroll
                for (int q = 0; q < 4; q++){
                    int idx = tid + q*256;
                    int e = idx>>3, c = idx&7; int j = p*32 + c*4;
                    float4 xv;
                    if (pass == 0){
                        xv = *(const float4*)(g_h + (size_t)(base+e)*128 + j);
                        xv.x = (xv.x - mu[j])*is[j];
                        xv.y = (xv.y - mu[j+1])*is[j+1];
                        xv.z = (xv.z - mu[j+2])*is[j+2];
                        xv.w = (xv.w - mu[j+3])*is[j+3];
                    } else {
                        xv = *(const float4*)(g_agg + (size_t)(base+e)*128 + j);
                        float di = dsm[e];
                        xv.x *= di; xv.y *= di; xv.z *= di; xv.w *= di;
                    }
                    unsigned h0,l0,h1,l1; hilo(xv.x,xv.y,h0,l0); hilo(xv.z,xv.w,h1,l1);
                    *(uint2*)(PHi + (uint32_t)e*80 + c*8) = make_uint2(h0,h1);
                    *(uint2*)(PLo + (uint32_t)e*80 + c*8) = make_uint2(l0,l1);
                }
                __syncthreads();
                #pragma unroll
                for (int ksl = 0; ksl < 2; ksl++){
                    uint32_t offA = laneABase + ksl*32;
                    uint32_t ah0[4], al0[4], ah1[4], al1[4];
                    ldsm4(ah0, PHiB + offA);
                    ldsm4(al0, PLoB + offA);
                    ldsm4(ah1, PHiB + offA + 16*80);
                    ldsm4(al1, PLoB + offA + 16*80);
                    int kglob = p*32 + ksl*16 + ((lane>>3)&1)*8;
                    #pragma unroll
                    for (int nf = 0; nf < 8; nf++){
                        int rowB = nh + nf*8 + (lane&7);
                        uint32_t offB = (uint32_t)rowB*256 + ((((kglob>>3) ^ (rowB&7)))<<4);
                        uint32_t bh[2], bl[2];
                        ldsm2(bh, BHiB + offB);
                        ldsm2(bl, BLoB + offB);
                        mma16816(d[0][nf], ah0, bh); mma16816(d[0][nf], al0, bh); mma16816(d[0][nf], ah0, bl);
                        mma16816(d[1][nf], ah1, bh); mma16816(d[1][nf], al1, bh); mma16816(d[1][nf], ah1, bl);
                    }
                }
            }
        }
        // u1 = relu(d + bias)
        #pragma unroll
        for (int m = 0; m < 2; m++)
            #pragma unroll
            for (int nf = 0; nf < 8; nf++){
                int n = nh + nf*8 + 2*tq;
                d[m][nf][0] = fmaxf(d[m][nf][0] + bias[n],   0.f);
                d[m][nf][1] = fmaxf(d[m][nf][1] + bias[n+1], 0.f);
                d[m][nf][2] = fmaxf(d[m][nf][2] + bias[n],   0.f);
                d[m][nf][3] = fmaxf(d[m][nf][3] + bias[n+1], 0.f);
            }
        // pass 2: u1 @ W2
        float d2[2][8][4];
        #pragma unroll
        for (int m = 0; m < 2; m++)
            #pragma unroll
            for (int nf = 0; nf < 8; nf++)
                #pragma unroll
                for (int c = 0; c < 4; c++) d2[m][nf][c] = 0.f;
        for (int p = 0; p < 4; p++){
            __syncthreads();
            if ((wid>>2) == (p>>1)){
                #pragma unroll
                for (int m = 0; m < 2; m++){
                    int e0 = m0 + m*16 + quad, e1 = e0 + 8;
                    #pragma unroll
                    for (int nfl = 0; nfl < 4; nfl++){
                        int nf = 4*(p&1) + nfl;
                        int n = nh + nf*8 + 2*tq;
                        int kl = n - 32*p;
                        unsigned hi, lo;
                        hilo(d[m][nf][0], d[m][nf][1], hi, lo);
                        *(unsigned*)(PHi + (uint32_t)e0*80 + kl*2) = hi;
                        *(unsigned*)(PLo + (uint32_t)e0*80 + kl*2) = lo;
                        hilo(d[m][nf][2], d[m][nf][3], hi, lo);
                        *(unsigned*)(PHi + (uint32_t)e1*80 + kl*2) = hi;
                        *(unsigned*)(PLo + (uint32_t)e1*80 + kl*2) = lo;
                    }
                }
            }
            __syncthreads();
            #pragma unroll
            for (int ksl = 0; ksl < 2; ksl++){
                uint32_t offA = laneABase + ksl*32;
                uint32_t ah0[4], al0[4], ah1[4], al1[4];
                ldsm4(ah0, PHiB + offA);
                ldsm4(al0, PLoB + offA);
                ldsm4(ah1, PHiB + offA + 16*80);
                ldsm4(al1, PLoB + offA + 16*80);
                int kglob = p*32 + ksl*16 + ((lane>>3)&1)*8;
                #pragma unroll
                for (int nf = 0; nf < 8; nf++){
                    int rowB = nh + nf*8 + (lane&7);
                    uint32_t offB = (uint32_t)rowB*256 + ((((kglob>>3) ^ (rowB&7)))<<4);
                    uint32_t bh[2], bl[2];
                    ldsm2(bh, W2HiB + offB);
                    ldsm2(bl, W2LoB + offB);
                    mma16816(d2[0][nf], ah0, bh); mma16816(d2[0][nf], al0, bh); mma16816(d2[0][nf], ah0, bl);
                    mma16816(d2[1][nf], ah1, bh); mma16816(d2[1][nf], al1, bh); mma16816(d2[1][nf], ah1, bl);
                }
            }
        }
        // epilogue: z = hn + d2 + b2 ; write pre-norm h ; stats
        #pragma unroll
        for (int m = 0; m < 2; m++){
            int e0 = m0 + m*16 + quad, e1 = e0 + 8;
            int row0 = base + e0, row1 = base + e1;
            #pragma unroll
            for (int nf = 0; nf < 8; nf++){
                int n = nh + nf*8 + 2*tq;
                float2 h0 = *(float2*)(g_h + (size_t)row0*128 + n);
                float2 h1 = *(float2*)(g_h + (size_t)row1*128 + n);
                float z00 = (h0.x-mu[n])*is[n]     + d2[m][nf][0] + b2[n];
                float z01 = (h0.y-mu[n+1])*is[n+1] + d2[m][nf][1] + b2[n+1];
                float z10 = (h1.x-mu[n])*is[n]     + d2[m][nf][2] + b2[n];
                float z11 = (h1.y-mu[n+1])*is[n+1] + d2[m][nf][3] + b2[n+1];
                *(float2*)(g_h + (size_t)row0*128 + n) = make_float2(z00, z01);
                *(float2*)(g_h + (size_t)row1*128 + n) = make_float2(z10, z11);
                if (row0 < NND){ ls1[nf*2]+=z00; ls1[nf*2+1]+=z01; ls2[nf*2]+=z00*z00; ls2[nf*2+1]+=z01*z01; }
                if (row1 < NND){ ls1[nf*2]+=z10; ls1[nf*2+1]+=z11; ls2[nf*2]+=z10*z10; ls2[nf*2+1]+=z11*z11; }
            }
        }
    }
    __syncthreads();
    #pragma unroll
    for (int nf = 0; nf < 8; nf++){
        int n = nh + nf*8 + 2*tq;
        atomicAdd(&sstat[n],       ls1[nf*2]);
        atomicAdd(&sstat[n+1],     ls1[nf*2+1]);
        atomicAdd(&sstat[128+n],   ls2[nf*2]);
        atomicAdd(&sstat[128+n+1], ls2[nf*2+1]);
    }
    __syncthreads();
    if (tid < 256) atomicAdd(&g_stats[tid], sstat[tid]);
    __threadfence();
    if (tid == 0){
        unsigned tk = atomicAdd(&g_tick, 1u);
        *sflag = (tk == (unsigned)gridDim.x - 1u) ? 1 : 0;
    }
    __syncthreads();
    if (*sflag){
        if (tid < 128){
            const float inv_n = 1.0f/(float)NND;
            float m_ = g_stats[tid]*inv_n;
            float var = fmaxf(g_stats[128+tid]*inv_n - m_*m_, 0.f);
            g_mu[tid] = m_;
            g_is[tid] = rsqrtf(var + 1e-5f);
            g_stats[tid] = 0.f; g_stats[128+tid] = 0.f;
        }
        if (tid == 0) g_tick = 0u;
    }
}

__global__ void k_hsum(){
    int j = threadIdx.x;
    float s = 0.f;
    for (int node = blockIdx.x; node < NND; node += gridDim.x)
        s += g_h[node*HD + j];
    atomicAdd(&g_hsum[j], s);
}

// ---------------- output head ----------------
__global__ void __launch_bounds__(256,2) k_out(const float* __restrict__ outW1,
                                               const float* __restrict__ outb1,
                                               const float* __restrict__ outW2,
                                               const float* __restrict__ outb2,
                                               const float* __restrict__ pos,
                                               const float* __restrict__ v,
                                               const float* __restrict__ domn,
                                               float* __restrict__ out)
{
    extern __shared__ float sm[];
    float* w1T = sm;
    float* b1  = w1T + 128*KP;
    float* mu  = b1 + 128;
    float* is  = mu + 128;
    float* w2o = is + 128;
    float* b2o = w2o + 128*12;
    float* dnx = b2o + 16;
    float* hsm = dnx + 4;
    float* o1  = hsm + OTIL*128;
    float* rv9 = o1 + OTIL*128;
    int tid = threadIdx.x;
    for (int idx = tid; idx < 128*128; idx += 256){
        int k = idx >> 7, jj = idx & 127;
        w1T[jj*KP + k] = outW1[idx];
    }
    for (int idx = tid; idx < HD*9; idx += 256){
        int k = idx/9, c = idx%9;
        w2o[k*12 + c] = outW2[idx];
    }
    if (tid < 128){
        b1[tid] = outb1[tid];
        mu[tid] = g_mu[tid]; is[tid] = g_is[tid];
    }
    if (tid < 9) b2o[tid] = outb2[tid];
    if (tid < 3) dnx[tid] = domn[tid];
    __syncthreads();
    int c0 = tid & 63, c1 = c0 + 64, r0 = (tid >> 6)*8;
    for (int tile = blockIdx.x; tile < ONT; tile += gridDim.x){
        int base = tile*OTIL;
        for (int idx = tid; idx < OTIL*128; idx += 256){
            int j = idx & 127;
            hsm[idx] = (g_h[base*HD + idx] - mu[j])*is[j];
        }
        for (int tt = tid; tt < OTIL*9; tt += 256){
            int i = tt/9, c = tt%9; int row = base + i;
            rv9[i*12 + c] = (row < NND) ? ((c < 3) ? pos[row*3 + c] : v[row*6 + c-3]) : 0.f;
        }
        __syncthreads();
        u64 acc0[8], acc1[8];
        #pragma unroll
        for (int i = 0; i < 8; i++){ acc0[i]=0ull; acc1[i]=0ull; }
        const float* wr0 = &w1T[c0*KP];
        const float* wr1 = &w1T[c1*KP];
        const float* ab  = &hsm[r0*128];
        GEMM8(acc0, acc1, ab, wr0, wr1);
        #pragma unroll
        for (int i = 0; i < 8; i++){
            o1[(r0+i)*128 + c0] = fmaxf(hadd2(acc0[i]) + b1[c0], 0.f);
            o1[(r0+i)*128 + c1] = fmaxf(hadd2(acc1[i]) + b1[c1], 0.f);
        }
        __syncthreads();
        for (int tt = tid; tt < OTIL*9; tt += 256){
            int i = tt/9, c = tt%9; int row = base + i;
            if (row < NND){
                float s = b2o[c];
                for (int k = 0; k < HD; k++) s += o1[i*128 + k]*w2o[k*12 + c];
                if (c < 3){
                    float p = 0.001f*s + rv9[i*12 + c];
                    float d = dnx[c];
                    out[row*3 + c] = p - floorf(p/d)*d;
                } else {
                    float sc = (c < 6) ? 0.001f : 0.01f;
                    out[NND*3 + row*6 + (c-3)] = sc*s + rv9[i*12 + c];
                }
            }
        }
        __syncthreads();
    }
}

__global__ void k_macro(const float* __restrict__ W1, const float* __restrict__ b1,
                        const float* __restrict__ W2, const float* __restrict__ b2,
                        float* __restrict__ out)
{
    __shared__ float hm[HD];
    __shared__ float hid[HD];
    int j = threadIdx.x;
    hm[j] = (g_hsum[j]*(1.0f/(float)NND) - g_mu[j])*g_is[j];
    __syncthreads();
    float acc = b1[j];
    for (int k = 0; k < HD; k++) acc += hm[k]*W1[k*HD + j];
    hid[j] = fmaxf(acc, 0.f);
    __syncthreads();
    if (j < 3){
        float s = b2[j];
        for (int k = 0; k < HD; k++) s += hid[k]*W2[k*3 + j];
        out[NND*9 + j] = s;
    }
}

extern "C" void kernel_launch(void* const* d_in, const int* in_sizes, int n_in,
                              void* d_out, int out_size)
{
    const float* v    = (const float*)d_in[0];
    const float* pos  = (const float*)d_in[1];
    const float* r    = (const float*)d_in[2];
    const float* dom  = (const float*)d_in[3];
    const float* t    = (const float*)d_in[4];
    const float* xg   = (const float*)d_in[5];
    const float* domn = (const float*)d_in[6];
    const float* tn   = (const float*)d_in[7];
    const int*   ei   = (const int*)d_in[8];
    const float* embW1=(const float*)d_in[10];
    const float* embb1=(const float*)d_in[11];
    const float* embW2=(const float*)d_in[12];
    const float* embb2=(const float*)d_in[13];
    const float* msgW1=(const float*)d_in[14];
    const float* msgb1=(const float*)d_in[15];
    const float* msgW2=(const float*)d_in[16];
    const float* msgb2=(const float*)d_in[17];
    const float* updW1=(const float*)d_in[18];
    const float* updb1=(const float*)d_in[19];
    const float* updW2=(const float*)d_in[20];
    const float* updb2=(const float*)d_in[21];
    const float* outW1=(const float*)d_in[22];
    const float* outb1=(const float*)d_in[23];
    const float* outW2=(const float*)d_in[24];
    const float* outb2=(const float*)d_in[25];
    const float* macW1=(const float*)d_in[26];
    const float* macb1=(const float*)d_in[27];
    const float* macW2=(const float*)d_in[28];
    const float* macb2=(const float*)d_in[29];
    float* out = (float*)d_out;

    size_t smEmbed = (size_t)(128*KP + 7*128 + 256 + TIL*128 + TIL*8)*4;
    size_t smNAB   = 196608 + (size_t)(768 + 4*128 + 128*8)*4;
    size_t smEdge  = 131072 + (size_t)(384 + 128 + 128 + 4 + 512)*4 + 1024 + 64;
    size_t smUpdF  = 217088 + (size_t)(5*128 + 256 + 4)*4 + 64;
    size_t smOut   = (size_t)(128*KP + 3*128 + 128*12 + 16 + 4 + 2*OTIL*128 + OTIL*12)*4;
    cudaFuncSetAttribute(k_embed, cudaFuncAttributeMaxDynamicSharedMemorySize, (int)smEmbed);
    cudaFuncSetAttribute(k_nAB,   cudaFuncAttributeMaxDynamicSharedMemorySize, (int)smNAB);
    cudaFuncSetAttribute(k_edge_tc, cudaFuncAttributeMaxDynamicSharedMemorySize, (int)smEdge);
    cudaFuncSetAttribute(k_updF,  cudaFuncAttributeMaxDynamicSharedMemorySize, (int)smUpdF);
    cudaFuncSetAttribute(k_out,   cudaFuncAttributeMaxDynamicSharedMemorySize, (int)smOut);

    k_prep<<<1,128>>>(dom, t, xg, domn, tn, embW1, embb1, msgW1, msgb1, updW1, updb1);
    k_zero0<<<64,256>>>();
    k_count<<<256,256>>>(ei);
    k_embed<<<296,256,smEmbed>>>(embW1, embW2, embb2, v, r);
    for (int l = 0; l < NL; l++){
        k_nAB<<<148,256,smNAB>>>(msgW1, v, r, l);
        k_edge_tc<<<148,256,smEdge>>>(msgW1, msgW2, msgb2, ei, pos, dom, l);
        k_updF<<<148,256,smUpdF>>>(updW1, updW2, updb2, l);
    }
    k_hsum<<<296,128>>>();
    k_out<<<296,256,smOut>>>(outW1, outb1, outW2, outb2, pos, v, domn, out);
    k_macro<<<1,128>>>(macW1, macb1, macW2, macb2, out);
}

// round 16
// speedup vs baseline: 2.8359x; 1.0301x over previous
#include <cuda_runtime.h>
#include <cuda_bf16.h>
#include <cstdint>

#define NND 50000
#define NP  50048
#define NED 300000
#define HD 128
#define NL 6
#define NTT (NP/128)
#define EMT 128
#define ET2 ((NED + EMT - 1)/EMT)

__device__ float g_h[NP*HD];
__device__ float g_A[NP*HD];
__device__ float g_B[NP*HD];
__device__ float g_agg[NP*HD];
__device__ float g_deg[NP];
__device__ float g_bias_emb[HD];
__device__ float g_bias_msg[NL*HD];
__device__ float g_bias_upd[NL*HD];
__device__ float g_stats[2*HD];
__device__ float g_mu[HD];
__device__ float g_is[HD];
__device__ unsigned g_tick;

typedef unsigned long long u64;

__device__ __forceinline__ void red4(float* p, float4 v){
    asm volatile("red.global.add.v4.f32 [%0], {%1,%2,%3,%4};"
                 :: "l"(p), "f"(v.x), "f"(v.y), "f"(v.z), "f"(v.w) : "memory");
}
__device__ __forceinline__ uint32_t smem_u32(const void* p){
    uint32_t a;
    asm("{ .reg .u64 t; cvta.to.shared.u64 t, %1; cvt.u32.u64 %0, t; }" : "=r"(a) : "l"(p));
    return a;
}
__device__ __forceinline__ void ldsm4(uint32_t* r, uint32_t addr){
    asm volatile("ldmatrix.sync.aligned.m8n8.x4.shared.b16 {%0,%1,%2,%3}, [%4];"
        : "=r"(r[0]),"=r"(r[1]),"=r"(r[2]),"=r"(r[3]) : "r"(addr));
}
__device__ __forceinline__ void ldsm2(uint32_t* r, uint32_t addr){
    asm volatile("ldmatrix.sync.aligned.m8n8.x2.shared.b16 {%0,%1}, [%2];"
        : "=r"(r[0]),"=r"(r[1]) : "r"(addr));
}
__device__ __forceinline__ void mma16816(float* d, const uint32_t* a, const uint32_t* b){
    asm volatile("mma.sync.aligned.m16n8k16.row.col.f32.bf16.bf16.f32 "
        "{%0,%1,%2,%3}, {%4,%5,%6,%7}, {%8,%9}, {%0,%1,%2,%3};"
        : "+f"(d[0]),"+f"(d[1]),"+f"(d[2]),"+f"(d[3])
        : "r"(a[0]),"r"(a[1]),"r"(a[2]),"r"(a[3]), "r"(b[0]),"r"(b[1]));
}
__device__ __forceinline__ void hilo(float p0, float p1, unsigned &hi, unsigned &lo){
    __nv_bfloat16 h0=__float2bfloat16(p0), h1=__float2bfloat16(p1);
    __nv_bfloat16 l0=__float2bfloat16(p0-__bfloat162float(h0));
    __nv_bfloat16 l1=__float2bfloat16(p1-__bfloat162float(h1));
    hi = (unsigned)__bfloat16_as_ushort(h0) | ((unsigned)__bfloat16_as_ushort(h1)<<16);
    lo = (unsigned)__bfloat16_as_ushort(l0) | ((unsigned)__bfloat16_as_ushort(l1)<<16);
}

#define STAGEW(W, WHI, WLO) \
  for (int idx = tid; idx < 128*64; idx += 256){ \
    int n = idx >> 6, kp = idx & 63; \
    uint32_t o = (uint32_t)n*256 + ((((kp>>2) ^ (n&7)))<<4) + (kp&3)*4; \
    unsigned hi, lo; \
    hilo((W)[(2*kp)*128 + n], (W)[(2*kp+1)*128 + n], hi, lo); \
    *(unsigned*)((WHI) + o) = hi; \
    *(unsigned*)((WLO) + o) = lo; \
  }

__global__ void k_prep(const float* __restrict__ dom, const float* __restrict__ t,
                       const float* __restrict__ xg, const float* __restrict__ domn,
                       const float* __restrict__ tn,
                       const float* __restrict__ embW1, const float* __restrict__ embb1,
                       const float* __restrict__ msgW1, const float* __restrict__ msgb1,
                       const float* __restrict__ updW1, const float* __restrict__ updb1)
{
    __shared__ float gf[12];
    int j = threadIdx.x;
    if (j < 12){
        float val;
        if (j < 3) val = dom[j];
        else if (j == 3) val = t[0];
        else if (j < 8) val = xg[j-4];
        else if (j < 11) val = domn[j-8];
        else val = tn[0];
        gf[j] = val;
    }
    __syncthreads();
    float acc = embb1[j];
    #pragma unroll
    for (int g = 0; g < 12; g++) acc += gf[g]*embW1[(7+g)*HD + j];
    g_bias_emb[j] = acc;
    for (int l = 0; l < NL; l++){
        const float* W = msgW1 + (size_t)l*279*HD;
        float a = msgb1[l*HD + j];
        #pragma unroll
        for (int g = 0; g < 12; g++) a += gf[g]*W[(267+g)*HD + j];
        g_bias_msg[l*HD + j] = a;
        const float* U = updW1 + (size_t)l*268*HD;
        float b = updb1[l*HD + j];
        #pragma unroll
        for (int g = 0; g < 12; g++) b += gf[g]*U[(256+g)*HD + j];
        g_bias_upd[l*HD + j] = b;
    }
}

__global__ void k_zero0(){
    int i = blockIdx.x*blockDim.x + threadIdx.x;
    for (int idx = i; idx < NP; idx += gridDim.x*blockDim.x) g_deg[idx] = 0.f;
    if (i < HD){ g_mu[i] = 0.f; g_is[i] = 1.f; }
    if (i < 2*HD) g_stats[i] = 0.f;
    if (i == 0) g_tick = 0u;
}

__global__ void k_count(const int* __restrict__ ei){
    for (int e = blockIdx.x*blockDim.x + threadIdx.x; e < NED; e += gridDim.x*blockDim.x)
        atomicAdd(&g_deg[ei[NED + e]], 1.0f);
}

// ---------------- embedding: layer1 inline, layer2 tensor MMA ----------------
__global__ void __launch_bounds__(256,1) k_embedT(const float* __restrict__ embW1,
                                                  const float* __restrict__ embW2,
                                                  const float* __restrict__ embb2,
                                                  const float* __restrict__ v,
                                                  const float* __restrict__ rr)
{
    extern __shared__ char smc[];
    char* WHi = smc;
    char* WLo = smc + 32768;
    char* AHi = smc + 65536;
    char* ALo = smc + 98304;
    float* w1  = (float*)(smc + 131072);  // 7*128
    float* be  = w1 + 896;                // 128
    float* b2e = be + 128;                // 128
    float* rv  = b2e + 128;               // 128*8
    int tid = threadIdx.x, wid = tid>>5, lane = tid&31;
    STAGEW(embW2, WHi, WLo);
    for (int idx = tid; idx < 7*128; idx += 256) w1[idx] = embW1[idx];
    if (tid < 128){ be[tid] = g_bias_emb[tid]; b2e[tid] = embb2[tid]; }
    __syncthreads();
    int m0 = (wid&3)*32, nh = (wid>>2)*64, quad = lane>>2, tq = lane&3;
    uint32_t AHiB = smem_u32(AHi), ALoB = smem_u32(ALo);
    uint32_t WHiB = smem_u32(WHi), WLoB = smem_u32(WLo);
    int rowA = m0 + (lane & 7) + ((lane >> 3) & 1)*8;
    for (int tile = blockIdx.x; tile < NTT; tile += gridDim.x){
        int base = tile*128;
        for (int idx = tid; idx < 128*7; idx += 256){
            int i = idx/7, c = idx%7; int row = base+i;
            rv[i*8+c] = (row<NND) ? ((c==0)?rr[row]:v[row*6+c-1]) : 0.f;
        }
        __syncthreads();
        #pragma unroll 2
        for (int q = 0; q < 16; q++){
            int idx = tid + q*256;
            int e = idx>>5, jp = idx&31, j = jp*4;
            const float* rve = &rv[e*8];
            float p[4];
            #pragma unroll
            for (int c = 0; c < 4; c++){
                int jc = j + c;
                float a = be[jc] + rve[0]*w1[jc];
                #pragma unroll
                for (int c2 = 0; c2 < 6; c2++) a += rve[1+c2]*w1[(1+c2)*128 + jc];
                p[c] = fmaxf(a, 0.f);
            }
            unsigned h0,l0,h1,l1; hilo(p[0],p[1],h0,l0); hilo(p[2],p[3],h1,l1);
            uint32_t o = (uint32_t)e*256 + ((((j>>3) ^ (e&7)))<<4) + (j&7)*2;
            *(uint2*)(AHi + o) = make_uint2(h0,h1);
            *(uint2*)(ALo + o) = make_uint2(l0,l1);
        }
        __syncthreads();
        float d[2][8][4];
        #pragma unroll
        for (int m = 0; m < 2; m++)
            #pragma unroll
            for (int nf = 0; nf < 8; nf++)
                #pragma unroll
                for (int c = 0; c < 4; c++) d[m][nf][c] = 0.f;
        #pragma unroll
        for (int ks = 0; ks < 8; ks++){
            int k0 = ks*16;
            int kbA = k0 + (lane >> 4)*8;
            uint32_t offA = (uint32_t)rowA*256 + ((((kbA>>3) ^ (rowA&7)))<<4);
            uint32_t ah0[4], al0[4], ah1[4], al1[4];
            ldsm4(ah0, AHiB + offA);
            ldsm4(al0, ALoB + offA);
            ldsm4(ah1, AHiB + offA + 4096);
            ldsm4(al1, ALoB + offA + 4096);
            int kbB = k0 + ((lane >> 3) & 1)*8;
            #pragma unroll
            for (int nf = 0; nf < 8; nf++){
                int rowB = nh + nf*8 + (lane & 7);
                uint32_t offB = (uint32_t)rowB*256 + ((((kbB>>3) ^ (rowB&7)))<<4);
                uint32_t bh[2], bl[2];
                ldsm2(bh, WHiB + offB);
                ldsm2(bl, WLoB + offB);
                mma16816(d[0][nf], ah0, bh); mma16816(d[0][nf], al0, bh); mma16816(d[0][nf], ah0, bl);
                mma16816(d[1][nf], ah1, bh); mma16816(d[1][nf], al1, bh); mma16816(d[1][nf], ah1, bl);
            }
        }
        #pragma unroll
        for (int m = 0; m < 2; m++){
            int e0 = m0 + m*16 + quad, e1 = e0 + 8;
            #pragma unroll
            for (int nf = 0; nf < 8; nf++){
                int n = nh + nf*8 + 2*tq;
                float2 o0 = { fmaxf(d[m][nf][0]+b2e[n],0.f), fmaxf(d[m][nf][1]+b2e[n+1],0.f) };
                float2 o1v = { fmaxf(d[m][nf][2]+b2e[n],0.f), fmaxf(d[m][nf][3]+b2e[n+1],0.f) };
                *(float2*)(g_h+(size_t)(base+e0)*128+n) = o0;
                *(float2*)(g_h+(size_t)(base+e1)*128+n) = o1v;
            }
        }
        __syncthreads();
    }
}

// ---------------- node A+B fused tensor GEMM + agg zero ----------------
__global__ void __launch_bounds__(256,1) k_nAB(const float* __restrict__ msgW1,
                                               const float* __restrict__ v,
                                               const float* __restrict__ rr, int l)
{
    extern __shared__ char smc[];
    char* WdHi = smc;
    char* WdLo = smc + 32768;
    char* WsHi = smc + 65536;
    char* WsLo = smc + 98304;
    char* AHi  = smc + 131072;
    char* ALo  = smc + 163840;
    float* wv  = (float*)(smc + 196608);
    float* wrA = wv + 768;
    float* wrB = wrA + 128;
    float* mu  = wrB + 128;
    float* is  = mu + 128;
    float* rv  = is + 128;       // 128*8
    const float* W1 = msgW1 + (size_t)l*279*HD;
    int tid = threadIdx.x, wid = tid>>5, lane = tid&31;
    STAGEW(W1, WdHi, WdLo);
    STAGEW(W1 + 128*128, WsHi, WsLo);
    for (int idx = tid; idx < 768; idx += 256) wv[idx] = W1[259*128 + idx];
    if (tid < 128){
        wrA[tid] = W1[265*128+tid]; wrB[tid] = W1[266*128+tid];
        mu[tid] = g_mu[tid]; is[tid] = g_is[tid];
    }
    __syncthreads();
    int m0 = (wid&3)*32, nh = (wid>>2)*64, quad = lane>>2, tq = lane&3;
    uint32_t AHiB = smem_u32(AHi), ALoB = smem_u32(ALo);
    uint32_t WdHiB = smem_u32(WdHi), WdLoB = smem_u32(WdLo);
    uint32_t WsHiB = smem_u32(WsHi), WsLoB = smem_u32(WsLo);
    for (int tile = blockIdx.x; tile < NTT; tile += gridDim.x){
        int base = tile*128;
        float4 z4 = {0.f,0.f,0.f,0.f};
        #pragma unroll
        for (int q = 0; q < 16; q++)
            ((float4*)(g_agg + (size_t)base*128))[tid + q*256] = z4;
        for (int idx = tid; idx < 128*7; idx += 256){
            int i = idx/7, c = idx%7; int row = base+i;
            rv[i*8+c] = (row<NND) ? ((c==0)?rr[row]:v[row*6+c-1]) : 0.f;
        }
        #pragma unroll 4
        for (int q = 0; q < 16; q++){
            int idx = tid + q*256;
            int e = idx>>5, jp = idx&31, j = jp*4;
            float4 hv = *(const float4*)(g_h + (size_t)(base+e)*128 + j);
            float p0=(hv.x-mu[j])*is[j],   p1=(hv.y-mu[j+1])*is[j+1];
            float p2=(hv.z-mu[j+2])*is[j+2], p3=(hv.w-mu[j+3])*is[j+3];
            unsigned h0,l0,h1,l1; hilo(p0,p1,h0,l0); hilo(p2,p3,h1,l1);
            uint32_t o = (uint32_t)e*256 + ((((j>>3) ^ (e&7)))<<4) + (j&7)*2;
            *(uint2*)(AHi + o) = make_uint2(h0,h1);
            *(uint2*)(ALo + o) = make_uint2(l0,l1);
        }
        __syncthreads();
        float dA[2][8][4], dB[2][8][4];
        #pragma unroll
        for (int m = 0; m < 2; m++)
            #pragma unroll
            for (int nf = 0; nf < 8; nf++)
                #pragma unroll
                for (int c = 0; c < 4; c++){ dA[m][nf][c]=0.f; dB[m][nf][c]=0.f; }
        int rowA = m0 + (lane & 7) + ((lane >> 3) & 1)*8;
        #pragma unroll
        for (int ks = 0; ks < 8; ks++){
            int k0 = ks*16;
            int kbA = k0 + (lane >> 4)*8;
            uint32_t offA = (uint32_t)rowA*256 + ((((kbA>>3) ^ (rowA&7)))<<4);
            uint32_t ah0[4], al0[4], ah1[4], al1[4];
            ldsm4(ah0, AHiB + offA);
            ldsm4(al0, ALoB + offA);
            ldsm4(ah1, AHiB + offA + 4096);
            ldsm4(al1, ALoB + offA + 4096);
            int kbB = k0 + ((lane >> 3) & 1)*8;
            #pragma unroll
            for (int nf = 0; nf < 8; nf++){
                int rowB = nh + nf*8 + (lane & 7);
                uint32_t offB = (uint32_t)rowB*256 + ((((kbB>>3) ^ (rowB&7)))<<4);
                uint32_t dh[2], dl[2], sh[2], sl[2];
                ldsm2(dh, WdHiB + offB);
                ldsm2(dl, WdLoB + offB);
                ldsm2(sh, WsHiB + offB);
                ldsm2(sl, WsLoB + offB);
                mma16816(dA[0][nf], ah0, dh); mma16816(dA[0][nf], al0, dh); mma16816(dA[0][nf], ah0, dl);
                mma16816(dA[1][nf], ah1, dh); mma16816(dA[1][nf], al1, dh); mma16816(dA[1][nf], ah1, dl);
                mma16816(dB[0][nf], ah0, sh); mma16816(dB[0][nf], al0, sh); mma16816(dB[0][nf], ah0, sl);
                mma16816(dB[1][nf], ah1, sh); mma16816(dB[1][nf], al1, sh); mma16816(dB[1][nf], ah1, sl);
            }
        }
        #pragma unroll
        for (int m = 0; m < 2; m++){
            int e0 = m0 + m*16 + quad, e1 = e0 + 8;
            const float* rv0 = &rv[e0*8];
            const float* rv1 = &rv[e1*8];
            #pragma unroll
            for (int nf = 0; nf < 8; nf++){
                int n = nh + nf*8 + 2*tq;
                float va00=0.f, va01=0.f, va10=0.f, va11=0.f;
                #pragma unroll
                for (int c = 0; c < 6; c++){
                    float w0 = wv[c*128+n], w1 = wv[c*128+n+1];
                    va00 += rv0[1+c]*w0; va01 += rv0[1+c]*w1;
                    va10 += rv1[1+c]*w0; va11 += rv1[1+c]*w1;
                }
                float r0 = rv0[0], r1 = rv1[0];
                float2 a0 = { dA[m][nf][0]+va00+r0*wrA[n], dA[m][nf][1]+va01+r0*wrA[n+1] };
                float2 a1 = { dA[m][nf][2]+va10+r1*wrA[n], dA[m][nf][3]+va11+r1*wrA[n+1] };
                float2 b0 = { dB[m][nf][0]-va00+r0*wrB[n], dB[m][nf][1]-va01+r0*wrB[n+1] };
                float2 b1 = { dB[m][nf][2]-va10+r1*wrB[n], dB[m][nf][3]-va11+r1*wrB[n+1] };
                *(float2*)(g_A+(size_t)(base+e0)*128+n) = a0;
                *(float2*)(g_A+(size_t)(base+e1)*128+n) = a1;
                *(float2*)(g_B+(size_t)(base+e0)*128+n) = b0;
                *(float2*)(g_B+(size_t)(base+e1)*128+n) = b1;
            }
        }
        __syncthreads();
    }
}

// ---------------- edge kernel: mma.sync bf16 hi/lo (3-term) ----------------
__global__ void __launch_bounds__(256) k_edge_tc(const float* __restrict__ msgW1,
                                                 const float* __restrict__ msgW2,
                                                 const float* __restrict__ msgb2,
                                                 const int* __restrict__ ei,
                                                 const float* __restrict__ pos,
                                                 const float* __restrict__ dom, int l)
{
    extern __shared__ char smc[];
    char* Bhi = smc;
    char* Blo = smc + 32768;
    char* Ahi = smc + 65536;
    char* Alo = smc + 98304;
    float* outb = (float*)(smc + 65536);
    float* wp   = (float*)(smc + 131072);
    float* bias = wp + 384;
    float* b2   = bias + 128;
    float* dsm  = b2 + 128;
    float* dp   = dsm + 4;
    int* es     = (int*)(dp + 512);
    int* ed     = es + 128;

    const float* W1 = msgW1 + (size_t)l*279*HD;
    const float* W2 = msgW2 + (size_t)l*HD*HD;
    int tid = threadIdx.x;
    int wid = tid >> 5, lane = tid & 31;
    uint32_t AhiB = smem_u32(Ahi), AloB = smem_u32(Alo);
    uint32_t BhiB = smem_u32(Bhi), BloB = smem_u32(Blo);

    STAGEW(W2, Bhi, Blo);
    for (int idx = tid; idx < 3*128; idx += 256) wp[idx] = W1[256*128 + idx];
    if (tid < 128){
        bias[tid] = g_bias_msg[l*HD + tid];
        b2[tid]   = msgb2[l*HD + tid];
    }
    if (tid < 3) dsm[tid] = dom[tid];
    __syncthreads();

    int m0 = (wid & 3)*32;
    int nh = (wid >> 2)*64;
    int quad = lane >> 2, tq = lane & 3;

    for (int tile = blockIdx.x; tile < ET2; tile += gridDim.x){
        int base = tile*EMT;
        int nval = NED - base; if (nval > EMT) nval = EMT;
        if (tid < EMT) es[tid] = (tid < nval) ? ei[base + tid] : 0;
        else { int e = tid - EMT; ed[e] = (e < nval) ? ei[NED + base + e] : 0; }
        __syncthreads();
        for (int idx = tid; idx < EMT*3; idx += 256){
            int e = idx/3, c = idx%3;
            float d = pos[ed[e]*3 + c] - pos[es[e]*3 + c];
            float dm = dsm[c];
            d -= dm * rintf(d/dm);
            dp[e*4 + c] = d;
        }
        __syncthreads();
        #pragma unroll 4
        for (int q = 0; q < 16; q++){
            int idx = tid + q*256;
            int e = idx >> 5, jp = idx & 31, j = jp*4;
            int nd = ed[e], ns = es[e];
            float4 av = *(const float4*)(g_A + (size_t)nd*HD + j);
            float4 bv = *(const float4*)(g_B + (size_t)ns*HD + j);
            float d0 = dp[e*4], d1 = dp[e*4+1], d2v = dp[e*4+2];
            float p0 = av.x + bv.x + bias[j]   + d0*wp[j]   + d1*wp[128+j]   + d2v*wp[256+j];
            float p1 = av.y + bv.y + bias[j+1] + d0*wp[j+1] + d1*wp[128+j+1] + d2v*wp[256+j+1];
            float p2 = av.z + bv.z + bias[j+2] + d0*wp[j+2] + d1*wp[128+j+2] + d2v*wp[256+j+2];
            float p3 = av.w + bv.w + bias[j+3] + d0*wp[j+3] + d1*wp[128+j+3] + d2v*wp[256+j+3];
            p0 = fmaxf(p0, 0.f); p1 = fmaxf(p1, 0.f);
            p2 = fmaxf(p2, 0.f); p3 = fmaxf(p3, 0.f);
            unsigned h0,l0,h1,l1; hilo(p0,p1,h0,l0); hilo(p2,p3,h1,l1);
            uint32_t o = (uint32_t)e*256 + ((((j>>3) ^ (e&7)))<<4) + (j&7)*2;
            *(uint2*)(Ahi + o) = make_uint2(h0,h1);
            *(uint2*)(Alo + o) = make_uint2(l0,l1);
        }
        __syncthreads();

        float d[2][8][4];
        #pragma unroll
        for (int m = 0; m < 2; m++)
            #pragma unroll
            for (int nf = 0; nf < 8; nf++)
                #pragma unroll
                for (int c = 0; c < 4; c++) d[m][nf][c] = 0.f;

        int rowA = m0 + (lane & 7) + ((lane >> 3) & 1)*8;
        #pragma unroll
        for (int ks = 0; ks < 8; ks++){
            int k0 = ks*16;
            int kbA = k0 + (lane >> 4)*8;
            uint32_t offA = (uint32_t)rowA*256 + ((((kbA>>3) ^ (rowA&7)))<<4);
            uint32_t ah0[4], al0[4], ah1[4], al1[4];
            ldsm4(ah0, AhiB + offA);
            ldsm4(al0, AloB + offA);
            ldsm4(ah1, AhiB + offA + 4096);
            ldsm4(al1, AloB + offA + 4096);
            int kbB = k0 + ((lane >> 3) & 1)*8;
            #pragma unroll
            for (int nf = 0; nf < 8; nf++){
                int rowB = nh + nf*8 + (lane & 7);
                uint32_t offB = (uint32_t)rowB*256 + ((((kbB>>3) ^ (rowB&7)))<<4);
                uint32_t bh[2], bl[2];
                ldsm2(bh, BhiB + offB);
                ldsm2(bl, BloB + offB);
                mma16816(d[0][nf], ah0, bh);
                mma16816(d[0][nf], al0, bh);
                mma16816(d[0][nf], ah0, bl);
                mma16816(d[1][nf], ah1, bh);
                mma16816(d[1][nf], al1, bh);
                mma16816(d[1][nf], ah1, bl);
            }
        }
        __syncthreads();

        #pragma unroll
        for (int m = 0; m < 2; m++){
            int e0 = m0 + m*16 + quad;
            int e1 = e0 + 8;
            #pragma unroll
            for (int nf = 0; nf < 8; nf++){
                int n = nh + nf*8 + 2*tq;
                float2 v0 = { fmaxf(d[m][nf][0] + b2[n], 0.f), fmaxf(d[m][nf][1] + b2[n+1], 0.f) };
                float2 v1 = { fmaxf(d[m][nf][2] + b2[n], 0.f), fmaxf(d[m][nf][3] + b2[n+1], 0.f) };
                *(float2*)(outb + (size_t)e0*128 + ((((n>>2) ^ (e0&7)))<<2) + (n&3)) = v0;
                *(float2*)(outb + (size_t)e1*128 + ((((n>>2) ^ (e1&7)))<<2) + (n&3)) = v1;
            }
        }
        __syncthreads();
        #pragma unroll
        for (int q = 0; q < 16; q++){
            int idx = tid + q*256;
            int e = idx >> 5, c = idx & 31;
            if (e < nval){
                float4 val = ((const float4*)outb)[e*32 + (c ^ (e&7))];
                red4(&g_agg[(size_t)ed[e]*HD + c*4], val);
            }
        }
        __syncthreads();
    }
}

// ---------------- fused update ----------------
__global__ void __launch_bounds__(256,1) k_updF(const float* __restrict__ updW1,
                                                const float* __restrict__ updW2,
                                                const float* __restrict__ updb2, int l)
{
    extern __shared__ char smc[];
    char* WhHi = smc;
    char* WhLo = smc + 32768;
    char* WaHi = smc + 65536;
    char* WaLo = smc + 98304;
    char* W2Hi = smc + 131072;
    char* W2Lo = smc + 163840;
    char* PHi  = smc + 196608;           // 128 rows x 80B
    char* PLo  = smc + 206848;
    float* bias = (float*)(smc + 217088);
    float* b2   = bias + 128;
    float* mu   = b2 + 128;
    float* is   = mu + 128;
    float* dsm  = is + 128;
    float* sstat= dsm + 128;             // 256
    int*   sflag= (int*)(sstat + 256);
    const float* Wh = updW1 + (size_t)l*268*HD;
    const float* Wa = Wh + 128*128;
    const float* W2 = updW2 + (size_t)l*HD*HD;
    int tid = threadIdx.x, wid = tid>>5, lane = tid&31;
    STAGEW(Wh, WhHi, WhLo);
    STAGEW(Wa, WaHi, WaLo);
    STAGEW(W2, W2Hi, W2Lo);
    if (tid < 128){
        bias[tid] = g_bias_upd[l*HD + tid];
        b2[tid]   = updb2[l*HD + tid];
        mu[tid] = g_mu[tid]; is[tid] = g_is[tid];
    }
    if (tid < 256) sstat[tid] = 0.f;
    __syncthreads();
    int m0 = (wid&3)*32, nh = (wid>>2)*64, quad = lane>>2, tq = lane&3;
    uint32_t PHiB = smem_u32(PHi), PLoB = smem_u32(PLo);
    uint32_t WhHiB = smem_u32(WhHi), WhLoB = smem_u32(WhLo);
    uint32_t WaHiB = smem_u32(WaHi), WaLoB = smem_u32(WaLo);
    uint32_t W2HiB = smem_u32(W2Hi), W2LoB = smem_u32(W2Lo);
    int rowA = m0 + (lane & 7) + ((lane >> 3) & 1)*8;
    uint32_t laneABase = (uint32_t)rowA*80 + (uint32_t)((lane>>4)*16);
    float ls1[16], ls2[16];
    #pragma unroll
    for (int i = 0; i < 16; i++){ ls1[i]=0.f; ls2[i]=0.f; }

    for (int tile = blockIdx.x; tile < NTT; tile += gridDim.x){
        int base = tile*128;
        float d[2][8][4];
        #pragma unroll
        for (int m = 0; m < 2; m++)
            #pragma unroll
            for (int nf = 0; nf < 8; nf++)
                #pragma unroll
                for (int c = 0; c < 4; c++) d[m][nf][c] = 0.f;
        if (tid < 128) dsm[tid] = 1.f/fmaxf(g_deg[base+tid], 1.f);

        for (int pass = 0; pass < 2; pass++){
            uint32_t BHiB = pass ? WaHiB : WhHiB;
            uint32_t BLoB = pass ? WaLoB : WhLoB;
            for (int p = 0; p < 4; p++){
                __syncthreads();
                #pragma unroll
                for (int q = 0; q < 4; q++){
                    int idx = tid + q*256;
                    int e = idx>>3, c = idx&7; int j = p*32 + c*4;
                    float4 xv;
                    if (pass == 0){
                        xv = *(const float4*)(g_h + (size_t)(base+e)*128 + j);
                        xv.x = (xv.x - mu[j])*is[j];
                        xv.y = (xv.y - mu[j+1])*is[j+1];
                        xv.z = (xv.z - mu[j+2])*is[j+2];
                        xv.w = (xv.w - mu[j+3])*is[j+3];
                    } else {
                        xv = *(const float4*)(g_agg + (size_t)(base+e)*128 + j);
                        float di = dsm[e];
                        xv.x *= di; xv.y *= di; xv.z *= di; xv.w *= di;
                    }
                    unsigned h0,l0,h1,l1; hilo(xv.x,xv.y,h0,l0); hilo(xv.z,xv.w,h1,l1);
                    *(uint2*)(PHi + (uint32_t)e*80 + c*8) = make_uint2(h0,h1);
                    *(uint2*)(PLo + (uint32_t)e*80 + c*8) = make_uint2(l0,l1);
                }
                __syncthreads();
                #pragma unroll
                for (int ksl = 0; ksl < 2; ksl++){
                    uint32_t offA = laneABase + ksl*32;
                    uint32_t ah0[4], al0[4], ah1[4], al1[4];
                    ldsm4(ah0, PHiB + offA);
                    ldsm4(al0, PLoB + offA);
                    ldsm4(ah1, PHiB + offA + 16*80);
                    ldsm4(al1, PLoB + offA + 16*80);
                    int kglob = p*32 + ksl*16 + ((lane>>3)&1)*8;
                    #pragma unroll
                    for (int nf = 0; nf < 8; nf++){
                        int rowB = nh + nf*8 + (lane&7);
                        uint32_t offB = (uint32_t)rowB*256 + ((((kglob>>3) ^ (rowB&7)))<<4);
                        uint32_t bh[2], bl[2];
                        ldsm2(bh, BHiB + offB);
                        ldsm2(bl, BLoB + offB);
                        mma16816(d[0][nf], ah0, bh); mma16816(d[0][nf], al0, bh); mma16816(d[0][nf], ah0, bl);
                        mma16816(d[1][nf], ah1, bh); mma16816(d[1][nf], al1, bh); mma16816(d[1][nf], ah1, bl);
                    }
                }
            }
        }
        #pragma unroll
        for (int m = 0; m < 2; m++)
            #pragma unroll
            for (int nf = 0; nf < 8; nf++){
                int n = nh + nf*8 + 2*tq;
                d[m][nf][0] = fmaxf(d[m][nf][0] + bias[n],   0.f);
                d[m][nf][1] = fmaxf(d[m][nf][1] + bias[n+1], 0.f);
                d[m][nf][2] = fmaxf(d[m][nf][2] + bias[n],   0.f);
                d[m][nf][3] = fmaxf(d[m][nf][3] + bias[n+1], 0.f);
            }
        float d2[2][8][4];
        #pragma unroll
        for (int m = 0; m < 2; m++)
            #pragma unroll
            for (int nf = 0; nf < 8; nf++)
                #pragma unroll
                for (int c = 0; c < 4; c++) d2[m][nf][c] = 0.f;
        for (int p = 0; p < 4; p++){
            __syncthreads();
            if ((wid>>2) == (p>>1)){
                #pragma unroll
                for (int m = 0; m < 2; m++){
                    int e0 = m0 + m*16 + quad, e1 = e0 + 8;
                    #pragma unroll
                    for (int nfl = 0; nfl < 4; nfl++){
                        int nf = 4*(p&1) + nfl;
                        int n = nh + nf*8 + 2*tq;
                        int kl = n - 32*p;
                        unsigned hi, lo;
                        hilo(d[m][nf][0], d[m][nf][1], hi, lo);
                        *(unsigned*)(PHi + (uint32_t)e0*80 + kl*2) = hi;
                        *(unsigned*)(PLo + (uint32_t)e0*80 + kl*2) = lo;
                        hilo(d[m][nf][2], d[m][nf][3], hi, lo);
                        *(unsigned*)(PHi + (uint32_t)e1*80 + kl*2) = hi;
                        *(unsigned*)(PLo + (uint32_t)e1*80 + kl*2) = lo;
                    }
                }
            }
            __syncthreads();
            #pragma unroll
            for (int ksl = 0; ksl < 2; ksl++){
                uint32_t offA = laneABase + ksl*32;
                uint32_t ah0[4], al0[4], ah1[4], al1[4];
                ldsm4(ah0, PHiB + offA);
                ldsm4(al0, PLoB + offA);
                ldsm4(ah1, PHiB + offA + 16*80);
                ldsm4(al1, PLoB + offA + 16*80);
                int kglob = p*32 + ksl*16 + ((lane>>3)&1)*8;
                #pragma unroll
                for (int nf = 0; nf < 8; nf++){
                    int rowB = nh + nf*8 + (lane&7);
                    uint32_t offB = (uint32_t)rowB*256 + ((((kglob>>3) ^ (rowB&7)))<<4);
                    uint32_t bh[2], bl[2];
                    ldsm2(bh, W2HiB + offB);
                    ldsm2(bl, W2LoB + offB);
                    mma16816(d2[0][nf], ah0, bh); mma16816(d2[0][nf], al0, bh); mma16816(d2[0][nf], ah0, bl);
                    mma16816(d2[1][nf], ah1, bh); mma16816(d2[1][nf], al1, bh); mma16816(d2[1][nf], ah1, bl);
                }
            }
        }
        #pragma unroll
        for (int m = 0; m < 2; m++){
            int e0 = m0 + m*16 + quad, e1 = e0 + 8;
            int row0 = base + e0, row1 = base + e1;
            #pragma unroll
            for (int nf = 0; nf < 8; nf++){
                int n = nh + nf*8 + 2*tq;
                float2 h0 = *(float2*)(g_h + (size_t)row0*128 + n);
                float2 h1 = *(float2*)(g_h + (size_t)row1*128 + n);
                float z00 = (h0.x-mu[n])*is[n]     + d2[m][nf][0] + b2[n];
                float z01 = (h0.y-mu[n+1])*is[n+1] + d2[m][nf][1] + b2[n+1];
                float z10 = (h1.x-mu[n])*is[n]     + d2[m][nf][2] + b2[n];
                float z11 = (h1.y-mu[n+1])*is[n+1] + d2[m][nf][3] + b2[n+1];
                *(float2*)(g_h + (size_t)row0*128 + n) = make_float2(z00, z01);
                *(float2*)(g_h + (size_t)row1*128 + n) = make_float2(z10, z11);
                if (row0 < NND){ ls1[nf*2]+=z00; ls1[nf*2+1]+=z01; ls2[nf*2]+=z00*z00; ls2[nf*2+1]+=z01*z01; }
                if (row1 < NND){ ls1[nf*2]+=z10; ls1[nf*2+1]+=z11; ls2[nf*2]+=z10*z10; ls2[nf*2+1]+=z11*z11; }
            }
        }
    }
    __syncthreads();
    #pragma unroll
    for (int nf = 0; nf < 8; nf++){
        int n = nh + nf*8 + 2*tq;
        atomicAdd(&sstat[n],       ls1[nf*2]);
        atomicAdd(&sstat[n+1],     ls1[nf*2+1]);
        atomicAdd(&sstat[128+n],   ls2[nf*2]);
        atomicAdd(&sstat[128+n+1], ls2[nf*2+1]);
    }
    __syncthreads();
    if (tid < 256) atomicAdd(&g_stats[tid], sstat[tid]);
    __threadfence();
    if (tid == 0){
        unsigned tk = atomicAdd(&g_tick, 1u);
        *sflag = (tk == (unsigned)gridDim.x - 1u) ? 1 : 0;
    }
    __syncthreads();
    if (*sflag){
        if (tid < 128){
            const float inv_n = 1.0f/(float)NND;
            float m_ = g_stats[tid]*inv_n;
            float var = fmaxf(g_stats[128+tid]*inv_n - m_*m_, 0.f);
            g_mu[tid] = m_;
            g_is[tid] = rsqrtf(var + 1e-5f);
            g_stats[tid] = 0.f; g_stats[128+tid] = 0.f;
        }
        if (tid == 0) g_tick = 0u;
    }
}

// ---------------- output head: layer1 tensor MMA, layer2 scalar ----------------
__global__ void __launch_bounds__(256,1) k_outT(const float* __restrict__ outW1,
                                                const float* __restrict__ outb1,
                                                const float* __restrict__ outW2,
                                                const float* __restrict__ outb2,
                                                const float* __restrict__ pos,
                                                const float* __restrict__ v,
                                                const float* __restrict__ domn,
                                                float* __restrict__ out)
{
    extern __shared__ char smc[];
    char* WHi = smc;
    char* WLo = smc + 32768;
    char* PHi = smc + 65536;
    char* PLo = smc + 98304;
    float* o1T = (float*)(smc + 131072);   // 132*128 floats
    float* aux = (float*)(smc + 131072 + 132*128*4);
    float* b1  = aux;            // 128
    float* mu  = b1 + 128;       // 128
    float* is  = mu + 128;       // 128
    float* w2o = is + 128;       // 128*12
    float* b2o = w2o + 1536;     // 16
    float* dnx = b2o + 16;       // 4
    float* rv9 = dnx + 4;        // 128*12
    int tid = threadIdx.x, wid = tid>>5, lane = tid&31;
    STAGEW(outW1, WHi, WLo);
    for (int idx = tid; idx < HD*9; idx += 256){
        int k = idx/9, c = idx%9;
        w2o[k*12 + c] = outW2[idx];
    }
    if (tid < 128){
        b1[tid] = outb1[tid];
        mu[tid] = g_mu[tid]; is[tid] = g_is[tid];
    }
    if (tid < 9) b2o[tid] = outb2[tid];
    if (tid < 3) dnx[tid] = domn[tid];
    __syncthreads();
    int m0 = (wid&3)*32, nh = (wid>>2)*64, quad = lane>>2, tq = lane&3;
    uint32_t PHiB = smem_u32(PHi), PLoB = smem_u32(PLo);
    uint32_t WHiB = smem_u32(WHi), WLoB = smem_u32(WLo);
    int rowA = m0 + (lane & 7) + ((lane >> 3) & 1)*8;
    for (int tile = blockIdx.x; tile < NTT; tile += gridDim.x){
        int base = tile*128;
        for (int tt = tid; tt < 128*9; tt += 256){
            int i = tt/9, c = tt%9; int row = base + i;
            rv9[i*12 + c] = (row < NND) ? ((c < 3) ? pos[row*3 + c] : v[row*6 + c-3]) : 0.f;
        }
        #pragma unroll 4
        for (int q = 0; q < 16; q++){
            int idx = tid + q*256;
            int e = idx>>5, jp = idx&31, j = jp*4;
            float4 hv = *(const float4*)(g_h + (size_t)(base+e)*128 + j);
            float p0=(hv.x-mu[j])*is[j],   p1=(hv.y-mu[j+1])*is[j+1];
            float p2=(hv.z-mu[j+2])*is[j+2], p3=(hv.w-mu[j+3])*is[j+3];
            unsigned h0,l0,h1,l1; hilo(p0,p1,h0,l0); hilo(p2,p3,h1,l1);
            uint32_t o = (uint32_t)e*256 + ((((j>>3) ^ (e&7)))<<4) + (j&7)*2;
            *(uint2*)(PHi + o) = make_uint2(h0,h1);
            *(uint2*)(PLo + o) = make_uint2(l0,l1);
        }
        __syncthreads();
        float d[2][8][4];
        #pragma unroll
        for (int m = 0; m < 2; m++)
            #pragma unroll
            for (int nf = 0; nf < 8; nf++)
                #pragma unroll
                for (int c = 0; c < 4; c++) d[m][nf][c] = 0.f;
        #pragma unroll
        for (int ks = 0; ks < 8; ks++){
            int k0 = ks*16;
            int kbA = k0 + (lane >> 4)*8;
            uint32_t offA = (uint32_t)rowA*256 + ((((kbA>>3) ^ (rowA&7)))<<4);
            uint32_t ah0[4], al0[4], ah1[4], al1[4];
            ldsm4(ah0, PHiB + offA);
            ldsm4(al0, PLoB + offA);
            ldsm4(ah1, PHiB + offA + 4096);
            ldsm4(al1, PLoB + offA + 4096);
            int kbB = k0 + ((lane >> 3) & 1)*8;
            #pragma unroll
            for (int nf = 0; nf < 8; nf++){
                int rowB = nh + nf*8 + (lane & 7);
                uint32_t offB = (uint32_t)rowB*256 + ((((kbB>>3) ^ (rowB&7)))<<4);
                uint32_t bh[2], bl[2];
                ldsm2(bh, WHiB + offB);
                ldsm2(bl, WLoB + offB);
                mma16816(d[0][nf], ah0, bh); mma16816(d[0][nf], al0, bh); mma16816(d[0][nf], ah0, bl);
                mma16816(d[1][nf], ah1, bh); mma16816(d[1][nf], al1, bh); mma16816(d[1][nf], ah1, bl);
            }
        }
        // write o1 transposed [k][i] stride 132
        #pragma unroll
        for (int m = 0; m < 2; m++){
            int e0 = m0 + m*16 + quad, e1 = e0 + 8;
            #pragma unroll
            for (int nf = 0; nf < 8; nf++){
                int n = nh + nf*8 + 2*tq;
                o1T[n*132 + e0]     = fmaxf(d[m][nf][0] + b1[n],   0.f);
                o1T[(n+1)*132 + e0] = fmaxf(d[m][nf][1] + b1[n+1], 0.f);
                o1T[n*132 + e1]     = fmaxf(d[m][nf][2] + b1[n],   0.f);
                o1T[(n+1)*132 + e1] = fmaxf(d[m][nf][3] + b1[n+1], 0.f);
            }
        }
        __syncthreads();
        for (int tt = tid; tt < 128*9; tt += 256){
            int i = tt/9, c = tt%9; int row = base + i;
            if (row < NND){
                float s = b2o[c];
                #pragma unroll 4
                for (int k = 0; k < HD; k++) s += o1T[k*132 + i]*w2o[k*12 + c];
                if (c < 3){
                    float p = 0.001f*s + rv9[i*12 + c];
                    float dmn = dnx[c];
                    out[row*3 + c] = p - floorf(p/dmn)*dmn;
                } else {
                    float sc = (c < 6) ? 0.001f : 0.01f;
                    out[NND*3 + row*6 + (c-3)] = sc*s + rv9[i*12 + c];
                }
            }
        }
        __syncthreads();
    }
}

__global__ void k_macro(const float* __restrict__ b1, const float* __restrict__ W2,
                        const float* __restrict__ b2, float* __restrict__ out)
{
    __shared__ float hid[HD];
    int j = threadIdx.x;
    hid[j] = fmaxf(b1[j], 0.f);
    __syncthreads();
    if (j < 3){
        float s = b2[j];
        for (int k = 0; k < HD; k++) s += hid[k]*W2[k*3 + j];
        out[NND*9 + j] = s;
    }
}

extern "C" void kernel_launch(void* const* d_in, const int* in_sizes, int n_in,
                              void* d_out, int out_size)
{
    const float* v    = (const float*)d_in[0];
    const float* pos  = (const float*)d_in[1];
    const float* r    = (const float*)d_in[2];
    const float* dom  = (const float*)d_in[3];
    const float* t    = (const float*)d_in[4];
    const float* xg   = (const float*)d_in[5];
    const float* domn = (const float*)d_in[6];
    const float* tn   = (const float*)d_in[7];
    const int*   ei   = (const int*)d_in[8];
    const float* embW1=(const float*)d_in[10];
    const float* embb1=(const float*)d_in[11];
    const float* embW2=(const float*)d_in[12];
    const float* embb2=(const float*)d_in[13];
    const float* msgW1=(const float*)d_in[14];
    const float* msgb1=(const float*)d_in[15];
    const float* msgW2=(const float*)d_in[16];
    const float* msgb2=(const float*)d_in[17];
    const float* updW1=(const float*)d_in[18];
    const float* updb1=(const float*)d_in[19];
    const float* updW2=(const float*)d_in[20];
    const float* updb2=(const float*)d_in[21];
    const float* outW1=(const float*)d_in[22];
    const float* outb1=(const float*)d_in[23];
    const float* outW2=(const float*)d_in[24];
    const float* outb2=(const float*)d_in[25];
    const float* macb1=(const float*)d_in[27];
    const float* macW2=(const float*)d_in[28];
    const float* macb2=(const float*)d_in[29];
    float* out = (float*)d_out;

    size_t smEmbT  = 131072 + (size_t)(896 + 256 + 1024)*4;
    size_t smNAB   = 196608 + (size_t)(768 + 4*128 + 128*8)*4;
    size_t smEdge  = 131072 + (size_t)(384 + 128 + 128 + 4 + 512)*4 + 1024 + 64;
    size_t smUpdF  = 217088 + (size_t)(5*128 + 256 + 4)*4 + 64;
    size_t smOutT  = 131072 + (size_t)(132*128)*4 + (size_t)(3*128 + 1536 + 16 + 4 + 128*12)*4;
    cudaFuncSetAttribute(k_embedT, cudaFuncAttributeMaxDynamicSharedMemorySize, (int)smEmbT);
    cudaFuncSetAttribute(k_nAB,   cudaFuncAttributeMaxDynamicSharedMemorySize, (int)smNAB);
    cudaFuncSetAttribute(k_edge_tc, cudaFuncAttributeMaxDynamicSharedMemorySize, (int)smEdge);
    cudaFuncSetAttribute(k_updF,  cudaFuncAttributeMaxDynamicSharedMemorySize, (int)smUpdF);
    cudaFuncSetAttribute(k_outT,  cudaFuncAttributeMaxDynamicSharedMemorySize, (int)smOutT);

    k_prep<<<1,128>>>(dom, t, xg, domn, tn, embW1, embb1, msgW1, msgb1, updW1, updb1);
    k_zero0<<<64,256>>>();
    k_count<<<256,256>>>(ei);
    k_embedT<<<148,256,smEmbT>>>(embW1, embW2, embb2, v, r);
    for (int l = 0; l < NL; l++){
        k_nAB<<<148,256,smNAB>>>(msgW1, v, r, l);
        k_edge_tc<<<148,256,smEdge>>>(msgW1, msgW2, msgb2, ei, pos, dom, l);
        k_updF<<<148,256,smUpdF>>>(updW1, updW2, updb2, l);
    }
    k_outT<<<148,256,smOutT>>>(outW1, outb1, outW2, outb2, pos, v, domn, out);
    k_macro<<<1,128>>>(macb1, macW2, macb2, out);
}